// round 9
// baseline (speedup 1.0000x reference)
#include <cuda_runtime.h>
#include <cuda_bf16.h>
#include <math.h>
#include <stdint.h>

// ---------------- problem constants ----------------
#define NN     8191
#define NINT   4095
#define SNPX   5000
#define DD     1600
#define IDDIM  32
#define KIN    1632        // DD + IDDIM (mult of 32)
#define FD     3232        // 2*DD + IDDIM (mult of 32)
#define YW     192         // 3 * 64 fc0 pieces
#define NIOU   4800        // 3 * DD
#define SFC0   4
#define BK     32          // K per pipeline chunk
#define LDS    40          // smem row stride (bf16), 32 data + 8 pad
#define BSM    (2 * 4 * 128 * LDS * 2)   // dynamic smem for bmma2 (80KB)
#define XT_IOU 38          // ceil(4800/128)
#define XT_F   13          // ceil(1600/128)

// ---------------- scratch ----------------
__device__ float g_h[(size_t)NN * DD];           // only leaves consumed
__device__ float g_c[(size_t)NN * DD];
__device__ float g_pre_iou[(size_t)4096 * NIOU]; // S*m <= 4096 partial rows
__device__ float g_pre_f[(size_t)8192 * DD];     // S*2m <= 8192 partial rows
__device__ float g_y[(size_t)SFC0 * NN * YW];

__device__ __nv_bfloat16 g_fb_h[(size_t)NN * FD];
__device__ __nv_bfloat16 g_fb_l[(size_t)NN * FD];
__device__ __nv_bfloat16 g_xiou_h[(size_t)2048 * KIN];
__device__ __nv_bfloat16 g_xiou_l[(size_t)2048 * KIN];
__device__ __nv_bfloat16 g_xf_h[(size_t)4096 * KIN];
__device__ __nv_bfloat16 g_xf_l[(size_t)4096 * KIN];
__device__ __nv_bfloat16 g_wiou_h[(size_t)NIOU * KIN];
__device__ __nv_bfloat16 g_wiou_l[(size_t)NIOU * KIN];
__device__ __nv_bfloat16 g_wf_h[(size_t)DD * KIN];
__device__ __nv_bfloat16 g_wf_l[(size_t)DD * KIN];
__device__ __nv_bfloat16 g_w012h[(size_t)YW * FD];
__device__ __nv_bfloat16 g_w012l[(size_t)YW * FD];

struct Job {
    const __nv_bfloat16 *Ah, *Al, *Bh, *Bl;
    float* C;
    int lda, ldb, ldc;
    size_t strideCz;
    int M, N, xt;
};

__device__ __forceinline__ float sigmoidf(float x) { return 1.0f / (1.0f + expf(-x)); }

__device__ __forceinline__ void split2(float v, __nv_bfloat16* hi, __nv_bfloat16* lo)
{
    __nv_bfloat16 h = __float2bfloat16(v);
    *hi = h;
    *lo = __float2bfloat16(v - __bfloat162float(h));
}

__device__ __forceinline__ uint32_t smem_u32(const void* p)
{
    uint32_t a;
    asm("{ .reg .u64 t; cvta.to.shared.u64 t, %1; cvt.u32.u64 %0, t; }"
        : "=r"(a) : "l"(p));
    return a;
}

__device__ __forceinline__ void cp16(uint32_t dst, const void* src, bool v)
{
    int sz = v ? 16 : 0;   // zfill when guard fails
    asm volatile("cp.async.cg.shared.global [%0], [%1], 16, %2;"
                 :: "r"(dst), "l"(src), "r"(sz) : "memory");
}

__device__ __forceinline__ void ldm_x4a(uint32_t& r0, uint32_t& r1, uint32_t& r2, uint32_t& r3,
                                        uint32_t addr)
{
    asm volatile("ldmatrix.sync.aligned.m8n8.x4.shared.b16 {%0,%1,%2,%3}, [%4];"
                 : "=r"(r0), "=r"(r1), "=r"(r2), "=r"(r3) : "r"(addr));
}

__device__ __forceinline__ void mma_bf16(float* c, const uint32_t* a, const uint32_t* b)
{
    asm volatile("mma.sync.aligned.m16n8k16.row.col.f32.bf16.bf16.f32 "
                 "{%0,%1,%2,%3}, {%4,%5,%6,%7}, {%8,%9}, {%0,%1,%2,%3};"
                 : "+f"(c[0]), "+f"(c[1]), "+f"(c[2]), "+f"(c[3])
                 : "r"(a[0]), "r"(a[1]), "r"(a[2]), "r"(a[3]), "r"(b[0]), "r"(b[1]));
}

// ---------------- dual-job pipelined tensor GEMM ----------------------------
// Cz[M,N] = A[M,Kz] @ B[N,Kz]^T per job; bf16 3-term split, fp32 acc,
// 128x128 tile, BK=32, 256 threads (2x4 warps, 64x32 warp tile),
// double-buffered cp.async with ONE __syncthreads per chunk,
// B fragments via ldmatrix.
// blockIdx.x selects job (x < j0.xt -> j0 else j1); rowBase >= M blocks exit.
__global__ void __launch_bounds__(256, 2)
bmma2(Job j0, Job j1, int K)
{
    extern __shared__ __align__(16) __nv_bfloat16 sm[];  // [2][4][128][LDS]
    const uint32_t smbase = smem_u32(sm);
    const int bx = blockIdx.x;
    const bool is0 = bx < j0.xt;
    const Job j = is0 ? j0 : j1;
    const int rowBase = blockIdx.y * 128;
    if (rowBase >= j.M) return;
    const int colBase = (is0 ? bx : bx - j0.xt) * 128;

    const int tid = threadIdx.x;
    const int warp = tid >> 5, lane = tid & 31;
    const int wm = (warp & 1) * 64;
    const int wn = (warp >> 1) * 32;

    const int ktiles = K / BK;
    const int S = gridDim.z;
    const int kt0 = (int)(((long long)blockIdx.z * ktiles) / S);
    const int kt1 = (int)(((long long)(blockIdx.z + 1) * ktiles) / S);
    const int nch = kt1 - kt0;

    auto load_chunk = [&](int buf, int kt) {
        const int k0 = kt * BK;
        #pragma unroll
        for (int it2 = 0; it2 < 8; it2++) {
            const int plane = it2 >> 1;
            const int rem = (it2 & 1) ? (256 + tid) : tid;   // 0..511
            const int row = rem >> 2;
            const int kp = rem & 3;
            const __nv_bfloat16* g = (plane == 0) ? j.Ah : (plane == 1) ? j.Al
                                    : (plane == 2) ? j.Bh : j.Bl;
            const int ld  = (plane < 2) ? j.lda : j.ldb;
            const int rb  = (plane < 2) ? rowBase : colBase;
            const int lim = (plane < 2) ? j.M : j.N;
            const int grow = rb + row;
            const bool v = grow < lim;
            const char* src = (const char*)(g + (size_t)(v ? grow : 0) * ld + k0)
                              + kp * 16;
            uint32_t dst = smbase +
                (uint32_t)((((buf * 4 + plane) * 128 + row) * LDS + kp * 8) * 2);
            cp16(dst, src, v);
        }
        asm volatile("cp.async.commit_group;" ::: "memory");
    };

    float acc[4][4][4];
    #pragma unroll
    for (int a = 0; a < 4; a++)
        #pragma unroll
        for (int b = 0; b < 4; b++)
            #pragma unroll
            for (int d = 0; d < 4; d++) acc[a][b][d] = 0.0f;

    // B-fragment ldmatrix address lanes
    const int bg = lane >> 3;          // tile group 0..3
    const int br = lane & 7;           // row within tile
    const int b_nt_off = (bg >> 1);    // 0 or 1
    const int b_kh = (bg & 1) * 8;     // 0 or 8

    if (nch > 0) load_chunk(0, kt0);

    for (int i = 0; i < nch; i++) {
        const int buf = i & 1;
        // only pending group is the one for this buf: wait it, then one sync
        asm volatile("cp.async.wait_group 0;" ::: "memory");
        __syncthreads();
        // issue next chunk's loads into the other buffer (safe: all warps
        // finished reading it during iteration i-1 before this sync)
        if (i + 1 < nch) load_chunk(buf ^ 1, kt0 + i + 1);

        #pragma unroll
        for (int ks = 0; ks < 2; ks++) {
            // B fragments via ldmatrix.x4: 2 calls per plane
            uint32_t bfh[4][2], bfl[4][2];
            #pragma unroll
            for (int np = 0; np < 2; np++) {       // nt pairs (0,1) and (2,3)
                const int nr = wn + (np * 2 + b_nt_off) * 8 + br;
                const int kc = ks * 16 + b_kh;
                uint32_t ah = smbase +
                    (uint32_t)((((buf * 4 + 2) * 128 + nr) * LDS + kc) * 2);
                ldm_x4a(bfh[np*2][0], bfh[np*2][1], bfh[np*2+1][0], bfh[np*2+1][1], ah);
                uint32_t al = smbase +
                    (uint32_t)((((buf * 4 + 3) * 128 + nr) * LDS + kc) * 2);
                ldm_x4a(bfl[np*2][0], bfl[np*2][1], bfl[np*2+1][0], bfl[np*2+1][1], al);
            }
            // A fragments loaded per-mt, hi then lo reusing registers
            #pragma unroll
            for (int mt = 0; mt < 4; mt++) {
                const int r = wm + mt * 16 + (lane & 15);
                const int c = ks * 16 + (lane >> 4) * 8;
                uint32_t af[4];
                uint32_t ah = smbase +
                    (uint32_t)((((buf * 4 + 0) * 128 + r) * LDS + c) * 2);
                ldm_x4a(af[0], af[1], af[2], af[3], ah);
                #pragma unroll
                for (int nt = 0; nt < 4; nt++) {
                    mma_bf16(acc[mt][nt], af, bfh[nt]);
                    mma_bf16(acc[mt][nt], af, bfl[nt]);
                }
                uint32_t al = smbase +
                    (uint32_t)((((buf * 4 + 1) * 128 + r) * LDS + c) * 2);
                ldm_x4a(af[0], af[1], af[2], af[3], al);
                #pragma unroll
                for (int nt = 0; nt < 4; nt++)
                    mma_bf16(acc[mt][nt], af, bfh[nt]);
            }
        }
    }

    float* Cz = j.C + (size_t)blockIdx.z * j.strideCz;
    #pragma unroll
    for (int mt = 0; mt < 4; mt++) {
        int r0 = rowBase + wm + mt * 16 + (lane >> 2);
        #pragma unroll
        for (int nt = 0; nt < 4; nt++) {
            int c = colBase + wn + nt * 8 + (lane & 3) * 2;
            if (c < j.N) {
                if (r0 < j.M) {
                    Cz[(size_t)r0 * j.ldc + c]     = acc[mt][nt][0];
                    Cz[(size_t)r0 * j.ldc + c + 1] = acc[mt][nt][1];
                }
                if (r0 + 8 < j.M) {
                    Cz[(size_t)(r0 + 8) * j.ldc + c]     = acc[mt][nt][2];
                    Cz[(size_t)(r0 + 8) * j.ldc + c + 1] = acc[mt][nt][3];
                }
            }
        }
    }
}

// ---------------- conv front-end -------------------------------------------
__global__ void conv_kernel(const float* __restrict__ x,
                            const float* __restrict__ idd,
                            const float* __restrict__ cw, const float* __restrict__ cb,
                            const float* __restrict__ lw, const float* __restrict__ lb)
{
    __shared__ float xs[SNPX];
    __shared__ float pwi[200];
    __shared__ float pwl[200];
    const int n = blockIdx.x;
    const float* xr = x + (size_t)n * SNPX;
    for (int i = threadIdx.x; i < SNPX / 4; i += blockDim.x)
        ((float4*)xs)[i] = ((const float4*)xr)[i];
    if (threadIdx.x < 200) {
        int co = threadIdx.x / 25, off = threadIdx.x % 25;
        int widx = co * 25 + (off % 5) * 5 + (off / 5);
        pwi[threadIdx.x] = cw[widx];
        pwl[threadIdx.x] = lw[widx];
    }
    if (threadIdx.x >= 224) {
        int j = threadIdx.x - 224;
        split2(idd[(size_t)n * IDDIM + j],
               &g_fb_h[(size_t)n * FD + 3200 + j], &g_fb_l[(size_t)n * FD + 3200 + j]);
    }
    __syncthreads();

    const bool leaf = (n >= NINT);
    const int t = threadIdx.x;
    if (t < 200) {
        const float* xp = &xs[25 * t];
        #pragma unroll
        for (int co = 0; co < 8; co++) {
            float acc = cb[co];
            #pragma unroll
            for (int off = 0; off < 25; off++) acc += xp[off] * pwi[co * 25 + off];
            acc = fmaxf(acc, 0.0f);
            size_t o = (size_t)n * FD + co * 200 + t;
            split2(acc, &g_fb_h[o], &g_fb_l[o]);
        }
        if (leaf) {
            #pragma unroll
            for (int co = 0; co < 8; co++) {
                float acc = lb[co];
                #pragma unroll
                for (int off = 0; off < 25; off++) acc += xp[off] * pwl[co * 25 + off];
                acc = fmaxf(acc, 0.0f);
                g_h[(size_t)n * DD + co * 200 + t] = acc;
                size_t o = (size_t)n * FD + DD + co * 200 + t;
                split2(acc, &g_fb_h[o], &g_fb_l[o]);
            }
        }
    }
    if (leaf) {
        for (int j = threadIdx.x; j < DD; j += blockDim.x)
            g_c[(size_t)n * DD + j] = 0.0f;
    }
}

// ---------------- all LSTM weight splits in one kernel ---------------------
__global__ void split_weights(const float* __restrict__ Wi, const float* __restrict__ Wo,
                              const float* __restrict__ Wu, const float* __restrict__ Wf)
{
    const int WN = DD * KIN;
    int i = blockIdx.x * blockDim.x + threadIdx.x;
    if (i >= 4 * WN) return;
    int which = i / WN, r = i % WN;
    const float* src = (which == 0) ? Wi : (which == 1) ? Wo : (which == 2) ? Wu : Wf;
    float v = src[r];
    if (which < 3) split2(v, &g_wiou_h[(size_t)which * WN + r], &g_wiou_l[(size_t)which * WN + r]);
    else           split2(v, &g_wf_h[r], &g_wf_l[r]);
}

// ---------------- pack + split fc0 weight [192,3232] -----------------------
__global__ void pack_w012(const float* __restrict__ fc0_w)
{
    int idx = blockIdx.x * blockDim.x + threadIdx.x;
    if (idx >= YW * FD) return;
    int r = idx / FD, k = idx % FD;
    float v = fc0_w[(size_t)(r & 63) * (3 * FD) + (size_t)(r >> 6) * FD + k];
    split2(v, &g_w012h[idx], &g_w012l[idx]);
}

// ---------------- initial build (depth-11 parents, reads leaf h) -----------
__global__ void build_xin(int start, const float* __restrict__ idd)
{
    const int t = blockIdx.x;
    const int p = start + t;
    const int l = 2 * p + 1, r = 2 * p + 2;
    const float* hl = &g_h[(size_t)l * DD];
    const float* hr = &g_h[(size_t)r * DD];
    const size_t oiou = (size_t)t * KIN;
    const size_t ofl  = (size_t)(2 * t) * KIN;
    const size_t ofr  = (size_t)(2 * t + 1) * KIN;
    for (int j = threadIdx.x; j < IDDIM; j += blockDim.x) {
        float v = idd[(size_t)p * IDDIM + j];
        __nv_bfloat16 h, lo2;
        split2(v, &h, &lo2);
        g_xiou_h[oiou + j] = h; g_xiou_l[oiou + j] = lo2;
        g_xf_h[ofl + j] = h;    g_xf_l[ofl + j] = lo2;
        g_xf_h[ofr + j] = h;    g_xf_l[ofr + j] = lo2;
    }
    for (int j = threadIdx.x; j < DD; j += blockDim.x) {
        float a = hl[j], b = hr[j];
        split2(a + b, &g_xiou_h[oiou + IDDIM + j], &g_xiou_l[oiou + IDDIM + j]);
        split2(a, &g_xf_h[ofl + IDDIM + j], &g_xf_l[ofl + IDDIM + j]);
        split2(b, &g_xf_h[ofr + IDDIM + j], &g_xf_l[ofr + IDDIM + j]);
    }
}

// ---------------- fused combine: sibling pair + writes parent xin ----------
__global__ void lstm_combine2(int start, int m, int S, int writeNext,
                              const float* __restrict__ bi, const float* __restrict__ bf,
                              const float* __restrict__ bu, const float* __restrict__ bo,
                              const float* __restrict__ idd)
{
    const int t = blockIdx.x;
    const int two = (m >= 2);
    const int p0 = start + 2 * t;
    const int p1 = p0 + 1;
    const int q  = (p0 - 1) >> 1;                 // parent node
    const size_t oiou = (size_t)t * KIN;          // parent-local rows
    const size_t ofl  = (size_t)(2 * t) * KIN;
    const size_t ofr  = (size_t)(2 * t + 1) * KIN;

    if (writeNext) {
        for (int j = threadIdx.x; j < IDDIM; j += blockDim.x) {
            float v = idd[(size_t)q * IDDIM + j];
            __nv_bfloat16 h, lo2;
            split2(v, &h, &lo2);
            g_xiou_h[oiou + j] = h; g_xiou_l[oiou + j] = lo2;
            g_xf_h[ofl + j] = h;    g_xf_l[ofl + j] = lo2;
            g_xf_h[ofr + j] = h;    g_xf_l[ofr + j] = lo2;
        }
    }

    for (int j = threadIdx.x; j < DD; j += blockDim.x) {
        float h01[2];
        #pragma unroll
        for (int s = 0; s < 2; s++) {
            if (s == 1 && !two) { h01[1] = 0.f; break; }
            const int p = (s == 0) ? p0 : p1;
            const int loc = 2 * t + s;
            float si = 0.f, so = 0.f, su = 0.f, sfl = 0.f, sfr = 0.f;
            for (int z = 0; z < S; z++) {
                const float* piou = &g_pre_iou[((size_t)z * m + loc) * NIOU];
                si += piou[j];
                so += piou[DD + j];
                su += piou[2 * DD + j];
                const float* pf = &g_pre_f[(size_t)z * 2 * m * DD];
                sfl += pf[(size_t)(2 * loc) * DD + j];
                sfr += pf[(size_t)(2 * loc + 1) * DD + j];
            }
            const int l = 2 * p + 1, r = 2 * p + 2;
            float vi = sigmoidf(si + bi[j]);
            float vo = sigmoidf(so + bo[j]);
            float vu = tanhf  (su + bu[j]);
            float fl = sigmoidf(sfl + bf[j]);
            float fr = sigmoidf(sfr + bf[j]);
            float cn = vi * vu + fl * g_c[(size_t)l * DD + j] + fr * g_c[(size_t)r * DD + j];
            float hn = vo * tanhf(cn);
            g_c[(size_t)p * DD + j] = cn;
            size_t o = (size_t)p * FD + DD + j;
            split2(hn, &g_fb_h[o], &g_fb_l[o]);
            h01[s] = hn;
        }
        if (writeNext) {
            split2(h01[0] + h01[1], &g_xiou_h[oiou + IDDIM + j], &g_xiou_l[oiou + IDDIM + j]);
            split2(h01[0], &g_xf_h[ofl + IDDIM + j], &g_xf_l[ofl + IDDIM + j]);
            split2(h01[1], &g_xf_h[ofr + IDDIM + j], &g_xf_l[ofr + IDDIM + j]);
        }
    }
}

// ---------------- head: fusion combine + fc1 + fc2 -------------------------
__device__ __forceinline__ float ysum(int node, int col)
{
    float s = 0.f;
    #pragma unroll
    for (int z = 0; z < SFC0; z++)
        s += g_y[((size_t)z * NN + node) * YW + col];
    return s;
}

__global__ void head_kernel(const float* __restrict__ fc0_b,
                            const float* __restrict__ fc1_w, const float* __restrict__ fc1_b,
                            const float* __restrict__ fc2_w, const float* __restrict__ fc2_b,
                            float* __restrict__ out)
{
    __shared__ float z[64];
    __shared__ float z1[64];
    __shared__ float partial[2];
    const int n = blockIdx.x;
    const int j = threadIdx.x;

    float acc = fc0_b[j] + ysum(n, j);
    if (n > 0) acc += ysum((n - 1) >> 1, 64 + j);
    if (n < NINT)
        acc += 0.5f * (ysum(2 * n + 1, 128 + j) + ysum(2 * n + 2, 128 + j));
    z[j] = fmaxf(acc, 0.0f);
    __syncthreads();

    float a1 = fc1_b[j];
    #pragma unroll 8
    for (int k = 0; k < 64; k++) a1 += fc1_w[j * 64 + k] * z[k];
    z1[j] = fmaxf(a1, 0.0f);
    __syncthreads();

    float v = fc2_w[j] * z1[j];
    #pragma unroll
    for (int off = 16; off > 0; off >>= 1) v += __shfl_down_sync(0xffffffffu, v, off);
    if ((j & 31) == 0) partial[j >> 5] = v;
    __syncthreads();
    if (j == 0) out[n] = partial[0] + partial[1] + fc2_b[0];
}

// ---------------- launch ----------------------------------------------------
extern "C" void kernel_launch(void* const* d_in, const int* in_sizes, int n_in,
                              void* d_out, int out_size)
{
    const float* x      = (const float*)d_in[0];
    const float* idd    = (const float*)d_in[1];
    const float* conv_w  = (const float*)d_in[4];
    const float* conv_b  = (const float*)d_in[5];
    const float* convl_w = (const float*)d_in[6];
    const float* convl_b = (const float*)d_in[7];
    const float* Wi = (const float*)d_in[8];   const float* bi = (const float*)d_in[9];
    const float* Wf = (const float*)d_in[10];  const float* bf = (const float*)d_in[11];
    const float* Wu = (const float*)d_in[12];  const float* bu = (const float*)d_in[13];
    const float* Wo = (const float*)d_in[14];  const float* bo = (const float*)d_in[15];
    const float* fc0_w = (const float*)d_in[16]; const float* fc0_b = (const float*)d_in[17];
    const float* fc1_w = (const float*)d_in[18]; const float* fc1_b = (const float*)d_in[19];
    const float* fc2_w = (const float*)d_in[20]; const float* fc2_b = (const float*)d_in[21];
    float* out = (float*)d_out;

    float *p_pre_iou, *p_pre_f, *p_y;
    __nv_bfloat16 *p_xiou_h, *p_xiou_l, *p_xf_h, *p_xf_l;
    __nv_bfloat16 *p_wiou_h, *p_wiou_l, *p_wf_h, *p_wf_l;
    __nv_bfloat16 *p_fb_h, *p_fb_l, *p_w012h, *p_w012l;
    cudaGetSymbolAddress((void**)&p_pre_iou, g_pre_iou);
    cudaGetSymbolAddress((void**)&p_pre_f,   g_pre_f);
    cudaGetSymbolAddress((void**)&p_y,       g_y);
    cudaGetSymbolAddress((void**)&p_xiou_h,  g_xiou_h);
    cudaGetSymbolAddress((void**)&p_xiou_l,  g_xiou_l);
    cudaGetSymbolAddress((void**)&p_xf_h,    g_xf_h);
    cudaGetSymbolAddress((void**)&p_xf_l,    g_xf_l);
    cudaGetSymbolAddress((void**)&p_wiou_h,  g_wiou_h);
    cudaGetSymbolAddress((void**)&p_wiou_l,  g_wiou_l);
    cudaGetSymbolAddress((void**)&p_wf_h,    g_wf_h);
    cudaGetSymbolAddress((void**)&p_wf_l,    g_wf_l);
    cudaGetSymbolAddress((void**)&p_fb_h,    g_fb_h);
    cudaGetSymbolAddress((void**)&p_fb_l,    g_fb_l);
    cudaGetSymbolAddress((void**)&p_w012h,   g_w012h);
    cudaGetSymbolAddress((void**)&p_w012l,   g_w012l);

    cudaFuncSetAttribute(bmma2, cudaFuncAttributeMaxDynamicSharedMemorySize, BSM);

    // 0) split weights into bf16 hi/lo planes
    split_weights<<<(4 * DD * KIN + 255) / 256, 256>>>(Wi, Wo, Wu, Wf);
    pack_w012<<<(YW * FD + 255) / 256, 256>>>(fc0_w);

    // 1) conv front-end
    conv_kernel<<<NN, 256>>>(x, idd, conv_w, conv_b, convl_w, convl_b);

    // 2) initial xin build for depth-11 parents (reads leaf h)
    build_xin<<<2048, 256>>>(2047, idd);

    // 3) bottom-up tree LSTM: ONE dual-job GEMM launch + fused combine / level
    for (int depth = 11; depth >= 0; depth--) {
        int m = 1 << depth;
        int start = m - 1;
        // split-K tuned for ~whole-number waves at 296 resident CTAs
        int S = (m >= 2048) ? 2 : (m == 1024) ? 4 : (m == 512) ? 8 : 16;
        Job jiou = { p_xiou_h, p_xiou_l, p_wiou_h, p_wiou_l, p_pre_iou,
                     KIN, KIN, NIOU, (size_t)m * NIOU, m, NIOU, XT_IOU };
        Job jf   = { p_xf_h, p_xf_l, p_wf_h, p_wf_l, p_pre_f,
                     KIN, KIN, DD, (size_t)2 * m * DD, 2 * m, DD, XT_F };
        dim3 g(XT_IOU + XT_F, (2 * m + 127) / 128, S);
        bmma2<<<g, 256, BSM>>>(jiou, jf, KIN);
        int blocks = (m >= 2) ? m / 2 : 1;
        lstm_combine2<<<blocks, 256>>>(start, m, S, depth > 0 ? 1 : 0,
                                       bi, bf, bu, bo, idd);
    }

    // 4) fused fc0 with split-K: Y = feat @ [W0a;W0b;W0c]^T
    Job jfc0 = { p_fb_h, p_fb_l, p_w012h, p_w012l, p_y,
                 FD, FD, YW, (size_t)NN * YW, NN, YW, 2 };
    Job jnull = jfc0; jnull.xt = 0;
    dim3 g3(2, (NN + 127) / 128, SFC0);
    bmma2<<<g3, 256, BSM>>>(jfc0, jnull, FD);

    // 5) fusion combine + fc1 + fc2
    head_kernel<<<NN, 64>>>(fc0_b, fc1_w, fc1_b, fc2_w, fc2_b, out);
}

// round 10
// speedup vs baseline: 1.0619x; 1.0619x over previous
#include <cuda_runtime.h>
#include <cuda_bf16.h>
#include <math.h>
#include <stdint.h>

// ---------------- problem constants ----------------
#define NN     8191
#define NINT   4095
#define SNPX   5000
#define DD     1600
#define IDDIM  32
#define KIN    1632        // DD + IDDIM (mult of 32)
#define FD     3232        // 2*DD + IDDIM (mult of 32)
#define YW     192         // 3 * 64 fc0 pieces
#define NIOU   4800        // 3 * DD
#define SFC0   4
#define BK     32          // K per pipeline chunk
#define LDS    40          // smem row stride (bf16), 32 data + 8 pad
#define BSM    (2 * 4 * 128 * LDS * 2)   // dynamic smem for bmma2 (80KB)
#define XT_IOU 38          // ceil(4800/128)
#define XT_F   13          // ceil(1600/128)

// ---------------- scratch ----------------
__device__ float g_h[(size_t)NN * DD];           // only leaves consumed
__device__ float g_c[(size_t)NN * DD];
__device__ float g_pre_iou[(size_t)2048 * NIOU]; // S*m <= 2048 partial rows
__device__ float g_pre_f[(size_t)4096 * DD];     // S*2m <= 4096 partial rows
__device__ float g_y[(size_t)SFC0 * NN * YW];

__device__ __nv_bfloat16 g_fb_h[(size_t)NN * FD];
__device__ __nv_bfloat16 g_fb_l[(size_t)NN * FD];
__device__ __nv_bfloat16 g_xiou_h[(size_t)2048 * KIN];
__device__ __nv_bfloat16 g_xiou_l[(size_t)2048 * KIN];
__device__ __nv_bfloat16 g_xf_h[(size_t)4096 * KIN];
__device__ __nv_bfloat16 g_xf_l[(size_t)4096 * KIN];
__device__ __nv_bfloat16 g_wiou_h[(size_t)NIOU * KIN];
__device__ __nv_bfloat16 g_wiou_l[(size_t)NIOU * KIN];
__device__ __nv_bfloat16 g_wf_h[(size_t)DD * KIN];
__device__ __nv_bfloat16 g_wf_l[(size_t)DD * KIN];
__device__ __nv_bfloat16 g_w012h[(size_t)YW * FD];
__device__ __nv_bfloat16 g_w012l[(size_t)YW * FD];

struct Job {
    const __nv_bfloat16 *Ah, *Al, *Bh, *Bl;
    float* C;
    int lda, ldb, ldc;
    size_t strideCz;
    int M, N, xt;
};

__device__ __forceinline__ float sigmoidf(float x) { return 1.0f / (1.0f + expf(-x)); }

__device__ __forceinline__ void split2(float v, __nv_bfloat16* hi, __nv_bfloat16* lo)
{
    __nv_bfloat16 h = __float2bfloat16(v);
    *hi = h;
    *lo = __float2bfloat16(v - __bfloat162float(h));
}

__device__ __forceinline__ uint32_t smem_u32(const void* p)
{
    uint32_t a;
    asm("{ .reg .u64 t; cvta.to.shared.u64 t, %1; cvt.u32.u64 %0, t; }"
        : "=r"(a) : "l"(p));
    return a;
}

__device__ __forceinline__ void cp16(uint32_t dst, const void* src, bool v)
{
    int sz = v ? 16 : 0;   // zfill when guard fails
    asm volatile("cp.async.cg.shared.global [%0], [%1], 16, %2;"
                 :: "r"(dst), "l"(src), "r"(sz) : "memory");
}

__device__ __forceinline__ void ldm_x4a(uint32_t& r0, uint32_t& r1, uint32_t& r2, uint32_t& r3,
                                        uint32_t addr)
{
    asm volatile("ldmatrix.sync.aligned.m8n8.x4.shared.b16 {%0,%1,%2,%3}, [%4];"
                 : "=r"(r0), "=r"(r1), "=r"(r2), "=r"(r3) : "r"(addr));
}

__device__ __forceinline__ void mma_bf16(float* c, const uint32_t* a, const uint32_t* b)
{
    asm volatile("mma.sync.aligned.m16n8k16.row.col.f32.bf16.bf16.f32 "
                 "{%0,%1,%2,%3}, {%4,%5,%6,%7}, {%8,%9}, {%0,%1,%2,%3};"
                 : "+f"(c[0]), "+f"(c[1]), "+f"(c[2]), "+f"(c[3])
                 : "r"(a[0]), "r"(a[1]), "r"(a[2]), "r"(a[3]), "r"(b[0]), "r"(b[1]));
}

// ---------------- dual-job pipelined tensor GEMM ----------------------------
// Cz[M,N] = A[M,Kz] @ B[N,Kz]^T per job; bf16 3-term split, fp32 acc,
// 128x128 tile, BK=32, 256 threads (2x4 warps, 64x32 warp tile),
// double-buffered cp.async with ONE __syncthreads per chunk,
// B fragments via ldmatrix.
// blockIdx.x selects job (x < j0.xt -> j0 else j1); rowBase >= M blocks exit.
__global__ void __launch_bounds__(256, 2)
bmma2(Job j0, Job j1, int K)
{
    extern __shared__ __align__(16) __nv_bfloat16 sm[];  // [2][4][128][LDS]
    const uint32_t smbase = smem_u32(sm);
    const int bx = blockIdx.x;
    const bool is0 = bx < j0.xt;
    const Job j = is0 ? j0 : j1;
    const int rowBase = blockIdx.y * 128;
    if (rowBase >= j.M) return;
    const int colBase = (is0 ? bx : bx - j0.xt) * 128;

    const int tid = threadIdx.x;
    const int warp = tid >> 5, lane = tid & 31;
    const int wm = (warp & 1) * 64;
    const int wn = (warp >> 2) * 0 + (warp >> 1) * 32;  // (warp>>1)*32

    const int ktiles = K / BK;
    const int S = gridDim.z;
    const int kt0 = (int)(((long long)blockIdx.z * ktiles) / S);
    const int kt1 = (int)(((long long)(blockIdx.z + 1) * ktiles) / S);
    const int nch = kt1 - kt0;

    auto load_chunk = [&](int buf, int kt) {
        const int k0 = kt * BK;
        #pragma unroll
        for (int it2 = 0; it2 < 8; it2++) {
            const int plane = it2 >> 1;
            const int rem = (it2 & 1) ? (256 + tid) : tid;   // 0..511
            const int row = rem >> 2;
            const int kp = rem & 3;
            const __nv_bfloat16* g = (plane == 0) ? j.Ah : (plane == 1) ? j.Al
                                    : (plane == 2) ? j.Bh : j.Bl;
            const int ld  = (plane < 2) ? j.lda : j.ldb;
            const int rb  = (plane < 2) ? rowBase : colBase;
            const int lim = (plane < 2) ? j.M : j.N;
            const int grow = rb + row;
            const bool v = grow < lim;
            const char* src = (const char*)(g + (size_t)(v ? grow : 0) * ld + k0)
                              + kp * 16;
            uint32_t dst = smbase +
                (uint32_t)((((buf * 4 + plane) * 128 + row) * LDS + kp * 8) * 2);
            cp16(dst, src, v);
        }
        asm volatile("cp.async.commit_group;" ::: "memory");
    };

    float acc[4][4][4];
    #pragma unroll
    for (int a = 0; a < 4; a++)
        #pragma unroll
        for (int b = 0; b < 4; b++)
            #pragma unroll
            for (int d = 0; d < 4; d++) acc[a][b][d] = 0.0f;

    // B-fragment ldmatrix address lanes
    const int bg = lane >> 3;          // tile group 0..3
    const int br = lane & 7;           // row within tile
    const int b_nt_off = (bg >> 1);    // 0 or 1
    const int b_kh = (bg & 1) * 8;     // 0 or 8

    if (nch > 0) load_chunk(0, kt0);

    for (int i = 0; i < nch; i++) {
        const int buf = i & 1;
        // only pending group is the one for this buf: wait it, then one sync
        asm volatile("cp.async.wait_group 0;" ::: "memory");
        __syncthreads();
        // issue next chunk's loads into the other buffer (safe: all warps
        // finished reading it during iteration i-1 before this sync)
        if (i + 1 < nch) load_chunk(buf ^ 1, kt0 + i + 1);

        #pragma unroll
        for (int ks = 0; ks < 2; ks++) {
            // B fragments via ldmatrix.x4: 2 calls per plane
            uint32_t bfh[4][2], bfl[4][2];
            #pragma unroll
            for (int np = 0; np < 2; np++) {       // nt pairs (0,1) and (2,3)
                const int nr = wn + (np * 2 + b_nt_off) * 8 + br;
                const int kc = ks * 16 + b_kh;
                uint32_t ah = smbase +
                    (uint32_t)((((buf * 4 + 2) * 128 + nr) * LDS + kc) * 2);
                ldm_x4a(bfh[np*2][0], bfh[np*2][1], bfh[np*2+1][0], bfh[np*2+1][1], ah);
                uint32_t al = smbase +
                    (uint32_t)((((buf * 4 + 3) * 128 + nr) * LDS + kc) * 2);
                ldm_x4a(bfl[np*2][0], bfl[np*2][1], bfl[np*2+1][0], bfl[np*2+1][1], al);
            }
            // A fragments loaded per-mt, hi then lo reusing registers
            #pragma unroll
            for (int mt = 0; mt < 4; mt++) {
                const int r = wm + mt * 16 + (lane & 15);
                const int c = ks * 16 + (lane >> 4) * 8;
                uint32_t af[4];
                uint32_t ah = smbase +
                    (uint32_t)((((buf * 4 + 0) * 128 + r) * LDS + c) * 2);
                ldm_x4a(af[0], af[1], af[2], af[3], ah);
                #pragma unroll
                for (int nt = 0; nt < 4; nt++) {
                    mma_bf16(acc[mt][nt], af, bfh[nt]);
                    mma_bf16(acc[mt][nt], af, bfl[nt]);
                }
                uint32_t al = smbase +
                    (uint32_t)((((buf * 4 + 1) * 128 + r) * LDS + c) * 2);
                ldm_x4a(af[0], af[1], af[2], af[3], al);
                #pragma unroll
                for (int nt = 0; nt < 4; nt++)
                    mma_bf16(acc[mt][nt], af, bfh[nt]);
            }
        }
    }

    float* Cz = j.C + (size_t)blockIdx.z * j.strideCz;
    #pragma unroll
    for (int mt = 0; mt < 4; mt++) {
        int r0 = rowBase + wm + mt * 16 + (lane >> 2);
        #pragma unroll
        for (int nt = 0; nt < 4; nt++) {
            int c = colBase + wn + nt * 8 + (lane & 3) * 2;
            if (c < j.N) {
                if (r0 < j.M) {
                    Cz[(size_t)r0 * j.ldc + c]     = acc[mt][nt][0];
                    Cz[(size_t)r0 * j.ldc + c + 1] = acc[mt][nt][1];
                }
                if (r0 + 8 < j.M) {
                    Cz[(size_t)(r0 + 8) * j.ldc + c]     = acc[mt][nt][2];
                    Cz[(size_t)(r0 + 8) * j.ldc + c + 1] = acc[mt][nt][3];
                }
            }
        }
    }
}

// ---------------- conv front-end -------------------------------------------
__global__ void conv_kernel(const float* __restrict__ x,
                            const float* __restrict__ idd,
                            const float* __restrict__ cw, const float* __restrict__ cb,
                            const float* __restrict__ lw, const float* __restrict__ lb)
{
    __shared__ float xs[SNPX];
    __shared__ float pwi[200];
    __shared__ float pwl[200];
    const int n = blockIdx.x;
    const float* xr = x + (size_t)n * SNPX;
    for (int i = threadIdx.x; i < SNPX / 4; i += blockDim.x)
        ((float4*)xs)[i] = ((const float4*)xr)[i];
    if (threadIdx.x < 200) {
        int co = threadIdx.x / 25, off = threadIdx.x % 25;
        int widx = co * 25 + (off % 5) * 5 + (off / 5);
        pwi[threadIdx.x] = cw[widx];
        pwl[threadIdx.x] = lw[widx];
    }
    if (threadIdx.x >= 224) {
        int j = threadIdx.x - 224;
        split2(idd[(size_t)n * IDDIM + j],
               &g_fb_h[(size_t)n * FD + 3200 + j], &g_fb_l[(size_t)n * FD + 3200 + j]);
    }
    __syncthreads();

    const bool leaf = (n >= NINT);
    const int t = threadIdx.x;
    if (t < 200) {
        const float* xp = &xs[25 * t];
        #pragma unroll
        for (int co = 0; co < 8; co++) {
            float acc = cb[co];
            #pragma unroll
            for (int off = 0; off < 25; off++) acc += xp[off] * pwi[co * 25 + off];
            acc = fmaxf(acc, 0.0f);
            size_t o = (size_t)n * FD + co * 200 + t;
            split2(acc, &g_fb_h[o], &g_fb_l[o]);
        }
        if (leaf) {
            #pragma unroll
            for (int co = 0; co < 8; co++) {
                float acc = lb[co];
                #pragma unroll
                for (int off = 0; off < 25; off++) acc += xp[off] * pwl[co * 25 + off];
                acc = fmaxf(acc, 0.0f);
                g_h[(size_t)n * DD + co * 200 + t] = acc;
                size_t o = (size_t)n * FD + DD + co * 200 + t;
                split2(acc, &g_fb_h[o], &g_fb_l[o]);
            }
        }
    }
    if (leaf) {
        for (int j = threadIdx.x; j < DD; j += blockDim.x)
            g_c[(size_t)n * DD + j] = 0.0f;
    }
}

// ---------------- all LSTM weight splits in one kernel ---------------------
__global__ void split_weights(const float* __restrict__ Wi, const float* __restrict__ Wo,
                              const float* __restrict__ Wu, const float* __restrict__ Wf)
{
    const int WN = DD * KIN;
    int i = blockIdx.x * blockDim.x + threadIdx.x;
    if (i >= 4 * WN) return;
    int which = i / WN, r = i % WN;
    const float* src = (which == 0) ? Wi : (which == 1) ? Wo : (which == 2) ? Wu : Wf;
    float v = src[r];
    if (which < 3) split2(v, &g_wiou_h[(size_t)which * WN + r], &g_wiou_l[(size_t)which * WN + r]);
    else           split2(v, &g_wf_h[r], &g_wf_l[r]);
}

// ---------------- pack + split fc0 weight [192,3232] -----------------------
__global__ void pack_w012(const float* __restrict__ fc0_w)
{
    int idx = blockIdx.x * blockDim.x + threadIdx.x;
    if (idx >= YW * FD) return;
    int r = idx / FD, k = idx % FD;
    float v = fc0_w[(size_t)(r & 63) * (3 * FD) + (size_t)(r >> 6) * FD + k];
    split2(v, &g_w012h[idx], &g_w012l[idx]);
}

// ---------------- initial build (depth-11 parents, reads leaf h) -----------
__global__ void build_xin(int start, const float* __restrict__ idd)
{
    const int t = blockIdx.x;
    const int p = start + t;
    const int l = 2 * p + 1, r = 2 * p + 2;
    const float* hl = &g_h[(size_t)l * DD];
    const float* hr = &g_h[(size_t)r * DD];
    const size_t oiou = (size_t)t * KIN;
    const size_t ofl  = (size_t)(2 * t) * KIN;
    const size_t ofr  = (size_t)(2 * t + 1) * KIN;
    for (int j = threadIdx.x; j < IDDIM; j += blockDim.x) {
        float v = idd[(size_t)p * IDDIM + j];
        __nv_bfloat16 h, lo2;
        split2(v, &h, &lo2);
        g_xiou_h[oiou + j] = h; g_xiou_l[oiou + j] = lo2;
        g_xf_h[ofl + j] = h;    g_xf_l[ofl + j] = lo2;
        g_xf_h[ofr + j] = h;    g_xf_l[ofr + j] = lo2;
    }
    for (int j = threadIdx.x; j < DD; j += blockDim.x) {
        float a = hl[j], b = hr[j];
        split2(a + b, &g_xiou_h[oiou + IDDIM + j], &g_xiou_l[oiou + IDDIM + j]);
        split2(a, &g_xf_h[ofl + IDDIM + j], &g_xf_l[ofl + IDDIM + j]);
        split2(b, &g_xf_h[ofr + IDDIM + j], &g_xf_l[ofr + IDDIM + j]);
    }
}

// ---------------- fused combine: sibling pair + writes parent xin ----------
__global__ void lstm_combine2(int start, int m, int S, int writeNext,
                              const float* __restrict__ bi, const float* __restrict__ bf,
                              const float* __restrict__ bu, const float* __restrict__ bo,
                              const float* __restrict__ idd)
{
    const int t = blockIdx.x;
    const int two = (m >= 2);
    const int p0 = start + 2 * t;
    const int p1 = p0 + 1;
    const int q  = (p0 - 1) >> 1;                 // parent node
    const size_t oiou = (size_t)t * KIN;          // parent-local rows
    const size_t ofl  = (size_t)(2 * t) * KIN;
    const size_t ofr  = (size_t)(2 * t + 1) * KIN;

    if (writeNext) {
        for (int j = threadIdx.x; j < IDDIM; j += blockDim.x) {
            float v = idd[(size_t)q * IDDIM + j];
            __nv_bfloat16 h, lo2;
            split2(v, &h, &lo2);
            g_xiou_h[oiou + j] = h; g_xiou_l[oiou + j] = lo2;
            g_xf_h[ofl + j] = h;    g_xf_l[ofl + j] = lo2;
            g_xf_h[ofr + j] = h;    g_xf_l[ofr + j] = lo2;
        }
    }

    for (int j = threadIdx.x; j < DD; j += blockDim.x) {
        float h01[2];
        #pragma unroll
        for (int s = 0; s < 2; s++) {
            if (s == 1 && !two) { h01[1] = 0.f; break; }
            const int p = (s == 0) ? p0 : p1;
            const int loc = 2 * t + s;
            float si = 0.f, so = 0.f, su = 0.f, sfl = 0.f, sfr = 0.f;
            for (int z = 0; z < S; z++) {
                const float* piou = &g_pre_iou[((size_t)z * m + loc) * NIOU];
                si += piou[j];
                so += piou[DD + j];
                su += piou[2 * DD + j];
                const float* pf = &g_pre_f[(size_t)z * 2 * m * DD];
                sfl += pf[(size_t)(2 * loc) * DD + j];
                sfr += pf[(size_t)(2 * loc + 1) * DD + j];
            }
            const int l = 2 * p + 1, r = 2 * p + 2;
            float vi = sigmoidf(si + bi[j]);
            float vo = sigmoidf(so + bo[j]);
            float vu = tanhf  (su + bu[j]);
            float fl = sigmoidf(sfl + bf[j]);
            float fr = sigmoidf(sfr + bf[j]);
            float cn = vi * vu + fl * g_c[(size_t)l * DD + j] + fr * g_c[(size_t)r * DD + j];
            float hn = vo * tanhf(cn);
            g_c[(size_t)p * DD + j] = cn;
            size_t o = (size_t)p * FD + DD + j;
            split2(hn, &g_fb_h[o], &g_fb_l[o]);
            h01[s] = hn;
        }
        if (writeNext) {
            split2(h01[0] + h01[1], &g_xiou_h[oiou + IDDIM + j], &g_xiou_l[oiou + IDDIM + j]);
            split2(h01[0], &g_xf_h[ofl + IDDIM + j], &g_xf_l[ofl + IDDIM + j]);
            split2(h01[1], &g_xf_h[ofr + IDDIM + j], &g_xf_l[ofr + IDDIM + j]);
        }
    }
}

// ---------------- head: fusion combine + fc1 + fc2 -------------------------
__device__ __forceinline__ float ysum(int node, int col)
{
    float s = 0.f;
    #pragma unroll
    for (int z = 0; z < SFC0; z++)
        s += g_y[((size_t)z * NN + node) * YW + col];
    return s;
}

__global__ void head_kernel(const float* __restrict__ fc0_b,
                            const float* __restrict__ fc1_w, const float* __restrict__ fc1_b,
                            const float* __restrict__ fc2_w, const float* __restrict__ fc2_b,
                            float* __restrict__ out)
{
    __shared__ float z[64];
    __shared__ float z1[64];
    __shared__ float partial[2];
    const int n = blockIdx.x;
    const int j = threadIdx.x;

    float acc = fc0_b[j] + ysum(n, j);
    if (n > 0) acc += ysum((n - 1) >> 1, 64 + j);
    if (n < NINT)
        acc += 0.5f * (ysum(2 * n + 1, 128 + j) + ysum(2 * n + 2, 128 + j));
    z[j] = fmaxf(acc, 0.0f);
    __syncthreads();

    float a1 = fc1_b[j];
    #pragma unroll 8
    for (int k = 0; k < 64; k++) a1 += fc1_w[j * 64 + k] * z[k];
    z1[j] = fmaxf(a1, 0.0f);
    __syncthreads();

    float v = fc2_w[j] * z1[j];
    #pragma unroll
    for (int off = 16; off > 0; off >>= 1) v += __shfl_down_sync(0xffffffffu, v, off);
    if ((j & 31) == 0) partial[j >> 5] = v;
    __syncthreads();
    if (j == 0) out[n] = partial[0] + partial[1] + fc2_b[0];
}

// ---------------- launch ----------------------------------------------------
extern "C" void kernel_launch(void* const* d_in, const int* in_sizes, int n_in,
                              void* d_out, int out_size)
{
    const float* x      = (const float*)d_in[0];
    const float* idd    = (const float*)d_in[1];
    const float* conv_w  = (const float*)d_in[4];
    const float* conv_b  = (const float*)d_in[5];
    const float* convl_w = (const float*)d_in[6];
    const float* convl_b = (const float*)d_in[7];
    const float* Wi = (const float*)d_in[8];   const float* bi = (const float*)d_in[9];
    const float* Wf = (const float*)d_in[10];  const float* bf = (const float*)d_in[11];
    const float* Wu = (const float*)d_in[12];  const float* bu = (const float*)d_in[13];
    const float* Wo = (const float*)d_in[14];  const float* bo = (const float*)d_in[15];
    const float* fc0_w = (const float*)d_in[16]; const float* fc0_b = (const float*)d_in[17];
    const float* fc1_w = (const float*)d_in[18]; const float* fc1_b = (const float*)d_in[19];
    const float* fc2_w = (const float*)d_in[20]; const float* fc2_b = (const float*)d_in[21];
    float* out = (float*)d_out;

    float *p_pre_iou, *p_pre_f, *p_y;
    __nv_bfloat16 *p_xiou_h, *p_xiou_l, *p_xf_h, *p_xf_l;
    __nv_bfloat16 *p_wiou_h, *p_wiou_l, *p_wf_h, *p_wf_l;
    __nv_bfloat16 *p_fb_h, *p_fb_l, *p_w012h, *p_w012l;
    cudaGetSymbolAddress((void**)&p_pre_iou, g_pre_iou);
    cudaGetSymbolAddress((void**)&p_pre_f,   g_pre_f);
    cudaGetSymbolAddress((void**)&p_y,       g_y);
    cudaGetSymbolAddress((void**)&p_xiou_h,  g_xiou_h);
    cudaGetSymbolAddress((void**)&p_xiou_l,  g_xiou_l);
    cudaGetSymbolAddress((void**)&p_xf_h,    g_xf_h);
    cudaGetSymbolAddress((void**)&p_xf_l,    g_xf_l);
    cudaGetSymbolAddress((void**)&p_wiou_h,  g_wiou_h);
    cudaGetSymbolAddress((void**)&p_wiou_l,  g_wiou_l);
    cudaGetSymbolAddress((void**)&p_wf_h,    g_wf_h);
    cudaGetSymbolAddress((void**)&p_wf_l,    g_wf_l);
    cudaGetSymbolAddress((void**)&p_fb_h,    g_fb_h);
    cudaGetSymbolAddress((void**)&p_fb_l,    g_fb_l);
    cudaGetSymbolAddress((void**)&p_w012h,   g_w012h);
    cudaGetSymbolAddress((void**)&p_w012l,   g_w012l);

    cudaFuncSetAttribute(bmma2, cudaFuncAttributeMaxDynamicSharedMemorySize, BSM);

    // 0) split weights into bf16 hi/lo planes
    split_weights<<<(4 * DD * KIN + 255) / 256, 256>>>(Wi, Wo, Wu, Wf);
    pack_w012<<<(YW * FD + 255) / 256, 256>>>(fc0_w);

    // 1) conv front-end
    conv_kernel<<<NN, 256>>>(x, idd, conv_w, conv_b, convl_w, convl_b);

    // 2) initial xin build for depth-11 parents (reads leaf h)
    build_xin<<<2048, 256>>>(2047, idd);

    // 3) bottom-up tree LSTM: ONE dual-job GEMM launch + fused combine / level
    for (int depth = 11; depth >= 0; depth--) {
        int m = 1 << depth;
        int start = m - 1;
        // R8's proven split-K schedule
        int S = (m >= 2048) ? 1 : (m == 1024) ? 2 : (m == 512) ? 4 : (m == 256) ? 8 : 16;
        Job jiou = { p_xiou_h, p_xiou_l, p_wiou_h, p_wiou_l, p_pre_iou,
                     KIN, KIN, NIOU, (size_t)m * NIOU, m, NIOU, XT_IOU };
        Job jf   = { p_xf_h, p_xf_l, p_wf_h, p_wf_l, p_pre_f,
                     KIN, KIN, DD, (size_t)2 * m * DD, 2 * m, DD, XT_F };
        dim3 g(XT_IOU + XT_F, (2 * m + 127) / 128, S);
        bmma2<<<g, 256, BSM>>>(jiou, jf, KIN);
        int blocks = (m >= 2) ? m / 2 : 1;
        lstm_combine2<<<blocks, 256>>>(start, m, S, depth > 0 ? 1 : 0,
                                       bi, bf, bu, bo, idd);
    }

    // 4) fused fc0 with split-K: Y = feat @ [W0a;W0b;W0c]^T
    Job jfc0 = { p_fb_h, p_fb_l, p_w012h, p_w012l, p_y,
                 FD, FD, YW, (size_t)NN * YW, NN, YW, 2 };
    Job jnull = jfc0; jnull.xt = 0;
    dim3 g3(2, (NN + 127) / 128, SFC0);
    bmma2<<<g3, 256, BSM>>>(jfc0, jnull, FD);

    // 5) fusion combine + fc1 + fc2
    head_kernel<<<NN, 64>>>(fc0_b, fc1_w, fc1_b, fc2_w, fc2_b, out);
}

// round 11
// speedup vs baseline: 1.2159x; 1.1450x over previous
#include <cuda_runtime.h>
#include <cuda_bf16.h>
#include <math.h>
#include <stdint.h>

// ---------------- problem constants ----------------
#define NN     8191
#define NINT   4095
#define SNPX   5000
#define DD     1600
#define IDDIM  32
#define KIN    1632        // DD + IDDIM (mult of 32)
#define FD     3232        // 2*DD + IDDIM (mult of 32)
#define YW     192         // 3 * 64 fc0 pieces
#define NIOU   4800        // 3 * DD
#define SFC0   4
#define BK     32          // K per pipeline chunk
#define LDS    40          // smem row stride (bf16), 32 data + 8 pad
#define BSM    (2 * 4 * 128 * LDS * 2)   // dynamic smem for bmma2 (80KB)
#define XT_IOU 38          // ceil(4800/128)
#define XT_F   13          // ceil(1600/128)

// ---------------- scratch ----------------
__device__ float g_h[(size_t)NN * DD];           // only leaves consumed
__device__ float g_c[(size_t)NN * DD];
__device__ float g_pre_iou[(size_t)2048 * NIOU]; // S*m <= 2048 partial rows
__device__ float g_pre_f[(size_t)4096 * DD];     // S*2m <= 4096 partial rows
__device__ float g_y[(size_t)SFC0 * NN * YW];

__device__ __nv_bfloat16 g_fb_h[(size_t)NN * FD];
__device__ __nv_bfloat16 g_fb_l[(size_t)NN * FD];
__device__ __nv_bfloat16 g_xiou_h[(size_t)2048 * KIN];
__device__ __nv_bfloat16 g_xiou_l[(size_t)2048 * KIN];
__device__ __nv_bfloat16 g_xf_h[(size_t)4096 * KIN];
__device__ __nv_bfloat16 g_xf_l[(size_t)4096 * KIN];
__device__ __nv_bfloat16 g_wiou_h[(size_t)NIOU * KIN];
__device__ __nv_bfloat16 g_wiou_l[(size_t)NIOU * KIN];
__device__ __nv_bfloat16 g_wf_h[(size_t)DD * KIN];
__device__ __nv_bfloat16 g_wf_l[(size_t)DD * KIN];
__device__ __nv_bfloat16 g_w012h[(size_t)YW * FD];
__device__ __nv_bfloat16 g_w012l[(size_t)YW * FD];

struct Job {
    const __nv_bfloat16 *Ah, *Al, *Bh, *Bl;
    float* C;
    int lda, ldb, ldc;
    size_t strideCz;
    int M, N, xt;
};

__device__ __forceinline__ float sigmoidf(float x) { return 1.0f / (1.0f + expf(-x)); }

__device__ __forceinline__ void split2(float v, __nv_bfloat16* hi, __nv_bfloat16* lo)
{
    __nv_bfloat16 h = __float2bfloat16(v);
    *hi = h;
    *lo = __float2bfloat16(v - __bfloat162float(h));
}

// pack 4 consecutive hi/lo bf16 from 4 floats into two uint2-able halves
__device__ __forceinline__ void split4(const float4 v, uint2* hi, uint2* lo)
{
    __nv_bfloat16 h0, l0, h1, l1, h2, l2, h3, l3;
    split2(v.x, &h0, &l0); split2(v.y, &h1, &l1);
    split2(v.z, &h2, &l2); split2(v.w, &h3, &l3);
    __nv_bfloat162 a = {h0, h1}, b = {h2, h3};
    __nv_bfloat162 c = {l0, l1}, d = {l2, l3};
    hi->x = *(uint32_t*)&a; hi->y = *(uint32_t*)&b;
    lo->x = *(uint32_t*)&c; lo->y = *(uint32_t*)&d;
}

__device__ __forceinline__ uint32_t smem_u32(const void* p)
{
    uint32_t a;
    asm("{ .reg .u64 t; cvta.to.shared.u64 t, %1; cvt.u32.u64 %0, t; }"
        : "=r"(a) : "l"(p));
    return a;
}

__device__ __forceinline__ void cp16(uint32_t dst, const void* src, bool v)
{
    int sz = v ? 16 : 0;   // zfill when guard fails
    asm volatile("cp.async.cg.shared.global [%0], [%1], 16, %2;"
                 :: "r"(dst), "l"(src), "r"(sz) : "memory");
}

__device__ __forceinline__ void ldm_x4a(uint32_t& r0, uint32_t& r1, uint32_t& r2, uint32_t& r3,
                                        uint32_t addr)
{
    asm volatile("ldmatrix.sync.aligned.m8n8.x4.shared.b16 {%0,%1,%2,%3}, [%4];"
                 : "=r"(r0), "=r"(r1), "=r"(r2), "=r"(r3) : "r"(addr));
}

__device__ __forceinline__ void mma_bf16(float* c, const uint32_t* a, const uint32_t* b)
{
    asm volatile("mma.sync.aligned.m16n8k16.row.col.f32.bf16.bf16.f32 "
                 "{%0,%1,%2,%3}, {%4,%5,%6,%7}, {%8,%9}, {%0,%1,%2,%3};"
                 : "+f"(c[0]), "+f"(c[1]), "+f"(c[2]), "+f"(c[3])
                 : "r"(a[0]), "r"(a[1]), "r"(a[2]), "r"(a[3]), "r"(b[0]), "r"(b[1]));
}

// ---------------- dual-job pipelined tensor GEMM ----------------------------
// Cz[M,N] = A[M,Kz] @ B[N,Kz]^T per job; bf16 3-term split, fp32 acc,
// 128x128 tile, BK=32, 256 threads (2x4 warps, 64x32 warp tile),
// double-buffered cp.async with ONE __syncthreads per chunk,
// B fragments via ldmatrix; MMAs ordered in nt-passes (same-acc spacing 4).
__global__ void __launch_bounds__(256, 2)
bmma2(Job j0, Job j1, int K)
{
    extern __shared__ __align__(16) __nv_bfloat16 sm[];  // [2][4][128][LDS]
    const uint32_t smbase = smem_u32(sm);
    const int bx = blockIdx.x;
    const bool is0 = bx < j0.xt;
    const Job j = is0 ? j0 : j1;
    const int rowBase = blockIdx.y * 128;
    if (rowBase >= j.M) return;
    const int colBase = (is0 ? bx : bx - j0.xt) * 128;

    const int tid = threadIdx.x;
    const int warp = tid >> 5, lane = tid & 31;
    const int wm = (warp & 1) * 64;
    const int wn = (warp >> 1) * 32;

    const int ktiles = K / BK;
    const int S = gridDim.z;
    const int kt0 = (int)(((long long)blockIdx.z * ktiles) / S);
    const int kt1 = (int)(((long long)(blockIdx.z + 1) * ktiles) / S);
    const int nch = kt1 - kt0;

    auto load_chunk = [&](int buf, int kt) {
        const int k0 = kt * BK;
        #pragma unroll
        for (int it2 = 0; it2 < 8; it2++) {
            const int plane = it2 >> 1;
            const int rem = (it2 & 1) ? (256 + tid) : tid;   // 0..511
            const int row = rem >> 2;
            const int kp = rem & 3;
            const __nv_bfloat16* g = (plane == 0) ? j.Ah : (plane == 1) ? j.Al
                                    : (plane == 2) ? j.Bh : j.Bl;
            const int ld  = (plane < 2) ? j.lda : j.ldb;
            const int rb  = (plane < 2) ? rowBase : colBase;
            const int lim = (plane < 2) ? j.M : j.N;
            const int grow = rb + row;
            const bool v = grow < lim;
            const char* src = (const char*)(g + (size_t)(v ? grow : 0) * ld + k0)
                              + kp * 16;
            uint32_t dst = smbase +
                (uint32_t)((((buf * 4 + plane) * 128 + row) * LDS + kp * 8) * 2);
            cp16(dst, src, v);
        }
        asm volatile("cp.async.commit_group;" ::: "memory");
    };

    float acc[4][4][4];
    #pragma unroll
    for (int a = 0; a < 4; a++)
        #pragma unroll
        for (int b = 0; b < 4; b++)
            #pragma unroll
            for (int d = 0; d < 4; d++) acc[a][b][d] = 0.0f;

    // B-fragment ldmatrix address lanes
    const int bg = lane >> 3;          // tile group 0..3
    const int br = lane & 7;           // row within tile
    const int b_nt_off = (bg >> 1);    // 0 or 1
    const int b_kh = (bg & 1) * 8;     // 0 or 8

    if (nch > 0) load_chunk(0, kt0);

    for (int i = 0; i < nch; i++) {
        const int buf = i & 1;
        asm volatile("cp.async.wait_group 0;" ::: "memory");
        __syncthreads();
        if (i + 1 < nch) load_chunk(buf ^ 1, kt0 + i + 1);

        #pragma unroll
        for (int ks = 0; ks < 2; ks++) {
            uint32_t bfh[4][2], bfl[4][2];
            #pragma unroll
            for (int np = 0; np < 2; np++) {       // nt pairs (0,1) and (2,3)
                const int nr = wn + (np * 2 + b_nt_off) * 8 + br;
                const int kc = ks * 16 + b_kh;
                uint32_t ah = smbase +
                    (uint32_t)((((buf * 4 + 2) * 128 + nr) * LDS + kc) * 2);
                ldm_x4a(bfh[np*2][0], bfh[np*2][1], bfh[np*2+1][0], bfh[np*2+1][1], ah);
                uint32_t al = smbase +
                    (uint32_t)((((buf * 4 + 3) * 128 + nr) * LDS + kc) * 2);
                ldm_x4a(bfl[np*2][0], bfl[np*2][1], bfl[np*2+1][0], bfl[np*2+1][1], al);
            }
            #pragma unroll
            for (int mt = 0; mt < 4; mt++) {
                const int r = wm + mt * 16 + (lane & 15);
                const int c = ks * 16 + (lane >> 4) * 8;
                uint32_t af[4];
                uint32_t ah = smbase +
                    (uint32_t)((((buf * 4 + 0) * 128 + r) * LDS + c) * 2);
                ldm_x4a(af[0], af[1], af[2], af[3], ah);
                // pass 1: A-hi x B-hi (nt 0..3)
                #pragma unroll
                for (int nt = 0; nt < 4; nt++)
                    mma_bf16(acc[mt][nt], af, bfh[nt]);
                // pass 2: A-hi x B-lo (same acc, 4-MMA spacing)
                #pragma unroll
                for (int nt = 0; nt < 4; nt++)
                    mma_bf16(acc[mt][nt], af, bfl[nt]);
                uint32_t al = smbase +
                    (uint32_t)((((buf * 4 + 1) * 128 + r) * LDS + c) * 2);
                ldm_x4a(af[0], af[1], af[2], af[3], al);
                // pass 3: A-lo x B-hi
                #pragma unroll
                for (int nt = 0; nt < 4; nt++)
                    mma_bf16(acc[mt][nt], af, bfh[nt]);
            }
        }
    }

    float* Cz = j.C + (size_t)blockIdx.z * j.strideCz;
    #pragma unroll
    for (int mt = 0; mt < 4; mt++) {
        int r0 = rowBase + wm + mt * 16 + (lane >> 2);
        #pragma unroll
        for (int nt = 0; nt < 4; nt++) {
            int c = colBase + wn + nt * 8 + (lane & 3) * 2;
            if (c < j.N) {
                if (r0 < j.M) {
                    Cz[(size_t)r0 * j.ldc + c]     = acc[mt][nt][0];
                    Cz[(size_t)r0 * j.ldc + c + 1] = acc[mt][nt][1];
                }
                if (r0 + 8 < j.M) {
                    Cz[(size_t)(r0 + 8) * j.ldc + c]     = acc[mt][nt][2];
                    Cz[(size_t)(r0 + 8) * j.ldc + c + 1] = acc[mt][nt][3];
                }
            }
        }
    }
}

// ---------------- conv front-end -------------------------------------------
__global__ void conv_kernel(const float* __restrict__ x,
                            const float* __restrict__ idd,
                            const float* __restrict__ cw, const float* __restrict__ cb,
                            const float* __restrict__ lw, const float* __restrict__ lb)
{
    __shared__ float xs[SNPX];
    __shared__ float pwi[200];
    __shared__ float pwl[200];
    const int n = blockIdx.x;
    const float* xr = x + (size_t)n * SNPX;
    for (int i = threadIdx.x; i < SNPX / 4; i += blockDim.x)
        ((float4*)xs)[i] = ((const float4*)xr)[i];
    if (threadIdx.x < 200) {
        int co = threadIdx.x / 25, off = threadIdx.x % 25;
        int widx = co * 25 + (off % 5) * 5 + (off / 5);
        pwi[threadIdx.x] = cw[widx];
        pwl[threadIdx.x] = lw[widx];
    }
    if (threadIdx.x >= 224) {
        int j = threadIdx.x - 224;
        split2(idd[(size_t)n * IDDIM + j],
               &g_fb_h[(size_t)n * FD + 3200 + j], &g_fb_l[(size_t)n * FD + 3200 + j]);
    }
    __syncthreads();

    const bool leaf = (n >= NINT);
    const int t = threadIdx.x;
    if (t < 200) {
        const float* xp = &xs[25 * t];
        #pragma unroll
        for (int co = 0; co < 8; co++) {
            float acc = cb[co];
            #pragma unroll
            for (int off = 0; off < 25; off++) acc += xp[off] * pwi[co * 25 + off];
            acc = fmaxf(acc, 0.0f);
            size_t o = (size_t)n * FD + co * 200 + t;
            split2(acc, &g_fb_h[o], &g_fb_l[o]);
        }
        if (leaf) {
            #pragma unroll
            for (int co = 0; co < 8; co++) {
                float acc = lb[co];
                #pragma unroll
                for (int off = 0; off < 25; off++) acc += xp[off] * pwl[co * 25 + off];
                acc = fmaxf(acc, 0.0f);
                g_h[(size_t)n * DD + co * 200 + t] = acc;
                size_t o = (size_t)n * FD + DD + co * 200 + t;
                split2(acc, &g_fb_h[o], &g_fb_l[o]);
            }
        }
    }
    if (leaf) {
        for (int j = threadIdx.x; j < DD; j += blockDim.x)
            g_c[(size_t)n * DD + j] = 0.0f;
    }
}

// ---------------- all LSTM weight splits in one kernel ---------------------
__global__ void split_weights(const float* __restrict__ Wi, const float* __restrict__ Wo,
                              const float* __restrict__ Wu, const float* __restrict__ Wf)
{
    const int WN = DD * KIN;
    int i = blockIdx.x * blockDim.x + threadIdx.x;
    if (i >= 4 * WN) return;
    int which = i / WN, r = i % WN;
    const float* src = (which == 0) ? Wi : (which == 1) ? Wo : (which == 2) ? Wu : Wf;
    float v = src[r];
    if (which < 3) split2(v, &g_wiou_h[(size_t)which * WN + r], &g_wiou_l[(size_t)which * WN + r]);
    else           split2(v, &g_wf_h[r], &g_wf_l[r]);
}

// ---------------- pack + split fc0 weight [192,3232] -----------------------
__global__ void pack_w012(const float* __restrict__ fc0_w)
{
    int idx = blockIdx.x * blockDim.x + threadIdx.x;
    if (idx >= YW * FD) return;
    int r = idx / FD, k = idx % FD;
    float v = fc0_w[(size_t)(r & 63) * (3 * FD) + (size_t)(r >> 6) * FD + k];
    split2(v, &g_w012h[idx], &g_w012l[idx]);
}

// ---------------- initial build (depth-11 parents, reads leaf h) -----------
__global__ void build_xin(int start, const float* __restrict__ idd)
{
    const int t = blockIdx.x;
    const int p = start + t;
    const int l = 2 * p + 1, r = 2 * p + 2;
    const float4* hl4 = (const float4*)&g_h[(size_t)l * DD];
    const float4* hr4 = (const float4*)&g_h[(size_t)r * DD];
    const size_t oiou = (size_t)t * KIN;
    const size_t ofl  = (size_t)(2 * t) * KIN;
    const size_t ofr  = (size_t)(2 * t + 1) * KIN;
    for (int j = threadIdx.x; j < IDDIM; j += blockDim.x) {
        float v = idd[(size_t)p * IDDIM + j];
        __nv_bfloat16 h, lo2;
        split2(v, &h, &lo2);
        g_xiou_h[oiou + j] = h; g_xiou_l[oiou + j] = lo2;
        g_xf_h[ofl + j] = h;    g_xf_l[ofl + j] = lo2;
        g_xf_h[ofr + j] = h;    g_xf_l[ofr + j] = lo2;
    }
    for (int j4 = threadIdx.x; j4 < DD / 4; j4 += blockDim.x) {
        float4 a = hl4[j4], b = hr4[j4];
        float4 s = make_float4(a.x + b.x, a.y + b.y, a.z + b.z, a.w + b.w);
        uint2 hi, lo;
        split4(s, &hi, &lo);
        *(uint2*)&g_xiou_h[oiou + IDDIM + j4 * 4] = hi;
        *(uint2*)&g_xiou_l[oiou + IDDIM + j4 * 4] = lo;
        split4(a, &hi, &lo);
        *(uint2*)&g_xf_h[ofl + IDDIM + j4 * 4] = hi;
        *(uint2*)&g_xf_l[ofl + IDDIM + j4 * 4] = lo;
        split4(b, &hi, &lo);
        *(uint2*)&g_xf_h[ofr + IDDIM + j4 * 4] = hi;
        *(uint2*)&g_xf_l[ofr + IDDIM + j4 * 4] = lo;
    }
}

// ---------------- fused combine: sibling pair + writes parent xin ----------
// float4-vectorized over the DD dimension.
__global__ void lstm_combine2(int start, int m, int S, int writeNext,
                              const float* __restrict__ bi, const float* __restrict__ bf,
                              const float* __restrict__ bu, const float* __restrict__ bo,
                              const float* __restrict__ idd)
{
    const int t = blockIdx.x;
    const int two = (m >= 2);
    const int p0 = start + 2 * t;
    const int p1 = p0 + 1;
    const int q  = (p0 - 1) >> 1;                 // parent node
    const size_t oiou = (size_t)t * KIN;          // parent-local rows
    const size_t ofl  = (size_t)(2 * t) * KIN;
    const size_t ofr  = (size_t)(2 * t + 1) * KIN;

    if (writeNext) {
        for (int j = threadIdx.x; j < IDDIM; j += blockDim.x) {
            float v = idd[(size_t)q * IDDIM + j];
            __nv_bfloat16 h, lo2;
            split2(v, &h, &lo2);
            g_xiou_h[oiou + j] = h; g_xiou_l[oiou + j] = lo2;
            g_xf_h[ofl + j] = h;    g_xf_l[ofl + j] = lo2;
            g_xf_h[ofr + j] = h;    g_xf_l[ofr + j] = lo2;
        }
    }

    for (int j4 = threadIdx.x; j4 < DD / 4; j4 += blockDim.x) {
        const int j = j4 * 4;
        const float4 vbi = *(const float4*)&bi[j];
        const float4 vbf = *(const float4*)&bf[j];
        const float4 vbu = *(const float4*)&bu[j];
        const float4 vbo = *(const float4*)&bo[j];
        float4 h4[2];
        #pragma unroll
        for (int s = 0; s < 2; s++) {
            if (s == 1 && !two) { h4[1] = make_float4(0.f, 0.f, 0.f, 0.f); break; }
            const int p = (s == 0) ? p0 : p1;
            const int loc = 2 * t + s;
            float4 si = make_float4(0.f, 0.f, 0.f, 0.f), so = si, su = si,
                   sfl = si, sfr = si;
            for (int z = 0; z < S; z++) {
                const float* piou = &g_pre_iou[((size_t)z * m + loc) * NIOU];
                float4 a = *(const float4*)&piou[j];
                float4 b = *(const float4*)&piou[DD + j];
                float4 cc = *(const float4*)&piou[2 * DD + j];
                si.x += a.x; si.y += a.y; si.z += a.z; si.w += a.w;
                so.x += b.x; so.y += b.y; so.z += b.z; so.w += b.w;
                su.x += cc.x; su.y += cc.y; su.z += cc.z; su.w += cc.w;
                const float* pf = &g_pre_f[(size_t)z * 2 * m * DD];
                float4 d = *(const float4*)&pf[(size_t)(2 * loc) * DD + j];
                float4 e = *(const float4*)&pf[(size_t)(2 * loc + 1) * DD + j];
                sfl.x += d.x; sfl.y += d.y; sfl.z += d.z; sfl.w += d.w;
                sfr.x += e.x; sfr.y += e.y; sfr.z += e.z; sfr.w += e.w;
            }
            const int l = 2 * p + 1, r = 2 * p + 2;
            float4 cl = *(const float4*)&g_c[(size_t)l * DD + j];
            float4 cr = *(const float4*)&g_c[(size_t)r * DD + j];
            float4 cn, hn;
            {
                float vi, vo, vu, fl, fr;
                vi = sigmoidf(si.x + vbi.x); vo = sigmoidf(so.x + vbo.x);
                vu = tanhf(su.x + vbu.x);
                fl = sigmoidf(sfl.x + vbf.x); fr = sigmoidf(sfr.x + vbf.x);
                cn.x = vi * vu + fl * cl.x + fr * cr.x; hn.x = vo * tanhf(cn.x);
                vi = sigmoidf(si.y + vbi.y); vo = sigmoidf(so.y + vbo.y);
                vu = tanhf(su.y + vbu.y);
                fl = sigmoidf(sfl.y + vbf.y); fr = sigmoidf(sfr.y + vbf.y);
                cn.y = vi * vu + fl * cl.y + fr * cr.y; hn.y = vo * tanhf(cn.y);
                vi = sigmoidf(si.z + vbi.z); vo = sigmoidf(so.z + vbo.z);
                vu = tanhf(su.z + vbu.z);
                fl = sigmoidf(sfl.z + vbf.z); fr = sigmoidf(sfr.z + vbf.z);
                cn.z = vi * vu + fl * cl.z + fr * cr.z; hn.z = vo * tanhf(cn.z);
                vi = sigmoidf(si.w + vbi.w); vo = sigmoidf(so.w + vbo.w);
                vu = tanhf(su.w + vbu.w);
                fl = sigmoidf(sfl.w + vbf.w); fr = sigmoidf(sfr.w + vbf.w);
                cn.w = vi * vu + fl * cl.w + fr * cr.w; hn.w = vo * tanhf(cn.w);
            }
            *(float4*)&g_c[(size_t)p * DD + j] = cn;
            uint2 hi, lo;
            split4(hn, &hi, &lo);
            *(uint2*)&g_fb_h[(size_t)p * FD + DD + j] = hi;
            *(uint2*)&g_fb_l[(size_t)p * FD + DD + j] = lo;
            h4[s] = hn;
        }
        if (writeNext) {
            uint2 hi, lo;
            float4 sum = make_float4(h4[0].x + h4[1].x, h4[0].y + h4[1].y,
                                     h4[0].z + h4[1].z, h4[0].w + h4[1].w);
            split4(sum, &hi, &lo);
            *(uint2*)&g_xiou_h[oiou + IDDIM + j] = hi;
            *(uint2*)&g_xiou_l[oiou + IDDIM + j] = lo;
            split4(h4[0], &hi, &lo);
            *(uint2*)&g_xf_h[ofl + IDDIM + j] = hi;
            *(uint2*)&g_xf_l[ofl + IDDIM + j] = lo;
            split4(h4[1], &hi, &lo);
            *(uint2*)&g_xf_h[ofr + IDDIM + j] = hi;
            *(uint2*)&g_xf_l[ofr + IDDIM + j] = lo;
        }
    }
}

// ---------------- head: fusion combine + fc1 + fc2 -------------------------
__device__ __forceinline__ float ysum(int node, int col)
{
    float s = 0.f;
    #pragma unroll
    for (int z = 0; z < SFC0; z++)
        s += g_y[((size_t)z * NN + node) * YW + col];
    return s;
}

__global__ void head_kernel(const float* __restrict__ fc0_b,
                            const float* __restrict__ fc1_w, const float* __restrict__ fc1_b,
                            const float* __restrict__ fc2_w, const float* __restrict__ fc2_b,
                            float* __restrict__ out)
{
    __shared__ float z[64];
    __shared__ float z1[64];
    __shared__ float partial[2];
    const int n = blockIdx.x;
    const int j = threadIdx.x;

    float acc = fc0_b[j] + ysum(n, j);
    if (n > 0) acc += ysum((n - 1) >> 1, 64 + j);
    if (n < NINT)
        acc += 0.5f * (ysum(2 * n + 1, 128 + j) + ysum(2 * n + 2, 128 + j));
    z[j] = fmaxf(acc, 0.0f);
    __syncthreads();

    float a1 = fc1_b[j];
    #pragma unroll 8
    for (int k = 0; k < 64; k++) a1 += fc1_w[j * 64 + k] * z[k];
    z1[j] = fmaxf(a1, 0.0f);
    __syncthreads();

    float v = fc2_w[j] * z1[j];
    #pragma unroll
    for (int off = 16; off > 0; off >>= 1) v += __shfl_down_sync(0xffffffffu, v, off);
    if ((j & 31) == 0) partial[j >> 5] = v;
    __syncthreads();
    if (j == 0) out[n] = partial[0] + partial[1] + fc2_b[0];
}

// ---------------- launch ----------------------------------------------------
extern "C" void kernel_launch(void* const* d_in, const int* in_sizes, int n_in,
                              void* d_out, int out_size)
{
    const float* x      = (const float*)d_in[0];
    const float* idd    = (const float*)d_in[1];
    const float* conv_w  = (const float*)d_in[4];
    const float* conv_b  = (const float*)d_in[5];
    const float* convl_w = (const float*)d_in[6];
    const float* convl_b = (const float*)d_in[7];
    const float* Wi = (const float*)d_in[8];   const float* bi = (const float*)d_in[9];
    const float* Wf = (const float*)d_in[10];  const float* bf = (const float*)d_in[11];
    const float* Wu = (const float*)d_in[12];  const float* bu = (const float*)d_in[13];
    const float* Wo = (const float*)d_in[14];  const float* bo = (const float*)d_in[15];
    const float* fc0_w = (const float*)d_in[16]; const float* fc0_b = (const float*)d_in[17];
    const float* fc1_w = (const float*)d_in[18]; const float* fc1_b = (const float*)d_in[19];
    const float* fc2_w = (const float*)d_in[20]; const float* fc2_b = (const float*)d_in[21];
    float* out = (float*)d_out;

    float *p_pre_iou, *p_pre_f, *p_y;
    __nv_bfloat16 *p_xiou_h, *p_xiou_l, *p_xf_h, *p_xf_l;
    __nv_bfloat16 *p_wiou_h, *p_wiou_l, *p_wf_h, *p_wf_l;
    __nv_bfloat16 *p_fb_h, *p_fb_l, *p_w012h, *p_w012l;
    cudaGetSymbolAddress((void**)&p_pre_iou, g_pre_iou);
    cudaGetSymbolAddress((void**)&p_pre_f,   g_pre_f);
    cudaGetSymbolAddress((void**)&p_y,       g_y);
    cudaGetSymbolAddress((void**)&p_xiou_h,  g_xiou_h);
    cudaGetSymbolAddress((void**)&p_xiou_l,  g_xiou_l);
    cudaGetSymbolAddress((void**)&p_xf_h,    g_xf_h);
    cudaGetSymbolAddress((void**)&p_xf_l,    g_xf_l);
    cudaGetSymbolAddress((void**)&p_wiou_h,  g_wiou_h);
    cudaGetSymbolAddress((void**)&p_wiou_l,  g_wiou_l);
    cudaGetSymbolAddress((void**)&p_wf_h,    g_wf_h);
    cudaGetSymbolAddress((void**)&p_wf_l,    g_wf_l);
    cudaGetSymbolAddress((void**)&p_fb_h,    g_fb_h);
    cudaGetSymbolAddress((void**)&p_fb_l,    g_fb_l);
    cudaGetSymbolAddress((void**)&p_w012h,   g_w012h);
    cudaGetSymbolAddress((void**)&p_w012l,   g_w012l);

    cudaFuncSetAttribute(bmma2, cudaFuncAttributeMaxDynamicSharedMemorySize, BSM);

    // 0) split weights into bf16 hi/lo planes
    split_weights<<<(4 * DD * KIN + 255) / 256, 256>>>(Wi, Wo, Wu, Wf);
    pack_w012<<<(YW * FD + 255) / 256, 256>>>(fc0_w);

    // 1) conv front-end
    conv_kernel<<<NN, 256>>>(x, idd, conv_w, conv_b, convl_w, convl_b);

    // 2) initial xin build for depth-11 parents (reads leaf h)
    build_xin<<<2048, 256>>>(2047, idd);

    // 3) bottom-up tree LSTM: ONE dual-job GEMM launch + fused combine / level
    for (int depth = 11; depth >= 0; depth--) {
        int m = 1 << depth;
        int start = m - 1;
        int S = (m >= 2048) ? 1 : (m == 1024) ? 2 : (m == 512) ? 4 : (m == 256) ? 8 : 16;
        Job jiou = { p_xiou_h, p_xiou_l, p_wiou_h, p_wiou_l, p_pre_iou,
                     KIN, KIN, NIOU, (size_t)m * NIOU, m, NIOU, XT_IOU };
        Job jf   = { p_xf_h, p_xf_l, p_wf_h, p_wf_l, p_pre_f,
                     KIN, KIN, DD, (size_t)2 * m * DD, 2 * m, DD, XT_F };
        dim3 g(XT_IOU + XT_F, (2 * m + 127) / 128, S);
        bmma2<<<g, 256, BSM>>>(jiou, jf, KIN);
        int blocks = (m >= 2) ? m / 2 : 1;
        lstm_combine2<<<blocks, 256>>>(start, m, S, depth > 0 ? 1 : 0,
                                       bi, bf, bu, bo, idd);
    }

    // 4) fused fc0 with split-K: Y = feat @ [W0a;W0b;W0c]^T
    Job jfc0 = { p_fb_h, p_fb_l, p_w012h, p_w012l, p_y,
                 FD, FD, YW, (size_t)NN * YW, NN, YW, 2 };
    Job jnull = jfc0; jnull.xt = 0;
    dim3 g3(2, (NN + 127) / 128, SFC0);
    bmma2<<<g3, 256, BSM>>>(jfc0, jnull, FD);

    // 5) fusion combine + fc1 + fc2
    head_kernel<<<NN, 64>>>(fc0_b, fc1_w, fc1_b, fc2_w, fc2_b, out);
}

// round 12
// speedup vs baseline: 1.2205x; 1.0037x over previous
#include <cuda_runtime.h>
#include <cuda_bf16.h>
#include <math.h>
#include <stdint.h>

// ---------------- problem constants ----------------
#define NN     8191
#define NINT   4095
#define SNPX   5000
#define DD     1600
#define IDDIM  32
#define KIN    1632        // DD + IDDIM (mult of 32)
#define FD     3232        // 2*DD + IDDIM (mult of 32)
#define YW     192         // 3 * 64 fc0 pieces
#define NIOU   4800        // 3 * DD
#define SFC0   4
#define BK     32          // K per pipeline chunk
#define LDS    40          // smem row stride (bf16), 32 data + 8 pad
#define BSM    (2 * 4 * 128 * LDS * 2)   // dynamic smem for bmma2 (80KB)
#define XT_IOU 38          // ceil(4800/128)
#define XT_F   13          // ceil(1600/128)

// ---------------- scratch ----------------
__device__ float g_h[(size_t)NN * DD];           // only leaves consumed
__device__ float g_c[(size_t)NN * DD];
__device__ float g_pre_iou[(size_t)2048 * NIOU]; // S*m <= 2048 partial rows
__device__ float g_pre_f[(size_t)4096 * DD];     // S*2m <= 4096 partial rows
__device__ float g_y[(size_t)SFC0 * NN * YW];

__device__ __nv_bfloat16 g_fb_h[(size_t)NN * FD];
__device__ __nv_bfloat16 g_fb_l[(size_t)NN * FD];
__device__ __nv_bfloat16 g_xiou_h[(size_t)2048 * KIN];
__device__ __nv_bfloat16 g_xiou_l[(size_t)2048 * KIN];
__device__ __nv_bfloat16 g_xf_h[(size_t)4096 * KIN];
__device__ __nv_bfloat16 g_xf_l[(size_t)4096 * KIN];
__device__ __nv_bfloat16 g_wiou_h[(size_t)NIOU * KIN];
__device__ __nv_bfloat16 g_wiou_l[(size_t)NIOU * KIN];
__device__ __nv_bfloat16 g_wf_h[(size_t)DD * KIN];
__device__ __nv_bfloat16 g_wf_l[(size_t)DD * KIN];
__device__ __nv_bfloat16 g_w012h[(size_t)YW * FD];
__device__ __nv_bfloat16 g_w012l[(size_t)YW * FD];

struct Job {
    const __nv_bfloat16 *Ah, *Al, *Bh, *Bl;
    float* C;
    int lda, ldb, ldc;
    size_t strideCz;
    int M, N, xt;
};

__device__ __forceinline__ float sigmoidf(float x) { return 1.0f / (1.0f + expf(-x)); }

__device__ __forceinline__ void split2(float v, __nv_bfloat16* hi, __nv_bfloat16* lo)
{
    __nv_bfloat16 h = __float2bfloat16(v);
    *hi = h;
    *lo = __float2bfloat16(v - __bfloat162float(h));
}

// pack 4 consecutive hi/lo bf16 from 4 floats into two uint2-able halves
__device__ __forceinline__ void split4(const float4 v, uint2* hi, uint2* lo)
{
    __nv_bfloat16 h0, l0, h1, l1, h2, l2, h3, l3;
    split2(v.x, &h0, &l0); split2(v.y, &h1, &l1);
    split2(v.z, &h2, &l2); split2(v.w, &h3, &l3);
    __nv_bfloat162 a = {h0, h1}, b = {h2, h3};
    __nv_bfloat162 c = {l0, l1}, d = {l2, l3};
    hi->x = *(uint32_t*)&a; hi->y = *(uint32_t*)&b;
    lo->x = *(uint32_t*)&c; lo->y = *(uint32_t*)&d;
}

__device__ __forceinline__ uint32_t smem_u32(const void* p)
{
    uint32_t a;
    asm("{ .reg .u64 t; cvta.to.shared.u64 t, %1; cvt.u32.u64 %0, t; }"
        : "=r"(a) : "l"(p));
    return a;
}

__device__ __forceinline__ void cp16(uint32_t dst, const void* src, bool v)
{
    int sz = v ? 16 : 0;   // zfill when guard fails
    asm volatile("cp.async.cg.shared.global [%0], [%1], 16, %2;"
                 :: "r"(dst), "l"(src), "r"(sz) : "memory");
}

__device__ __forceinline__ void ldm_x4a(uint32_t& r0, uint32_t& r1, uint32_t& r2, uint32_t& r3,
                                        uint32_t addr)
{
    asm volatile("ldmatrix.sync.aligned.m8n8.x4.shared.b16 {%0,%1,%2,%3}, [%4];"
                 : "=r"(r0), "=r"(r1), "=r"(r2), "=r"(r3) : "r"(addr));
}

__device__ __forceinline__ void mma_bf16(float* c, const uint32_t* a, const uint32_t* b)
{
    asm volatile("mma.sync.aligned.m16n8k16.row.col.f32.bf16.bf16.f32 "
                 "{%0,%1,%2,%3}, {%4,%5,%6,%7}, {%8,%9}, {%0,%1,%2,%3};"
                 : "+f"(c[0]), "+f"(c[1]), "+f"(c[2]), "+f"(c[3])
                 : "r"(a[0]), "r"(a[1]), "r"(a[2]), "r"(a[3]), "r"(b[0]), "r"(b[1]));
}

// ---------------- dual-job pipelined tensor GEMM ----------------------------
// Cz[M,N] = A[M,Kz] @ B[N,Kz]^T per job; bf16 3-term split, fp32 acc,
// 128x128 tile, BK=32, 256 threads (2x4 warps, 64x32 warp tile),
// double-buffered cp.async with ONE __syncthreads per chunk,
// B fragments via ldmatrix; MMAs in full warp-tile passes (same-acc spacing 16).
__global__ void __launch_bounds__(256, 2)
bmma2(Job j0, Job j1, int K)
{
    extern __shared__ __align__(16) __nv_bfloat16 sm[];  // [2][4][128][LDS]
    const uint32_t smbase = smem_u32(sm);
    const int bx = blockIdx.x;
    const bool is0 = bx < j0.xt;
    const Job j = is0 ? j0 : j1;
    const int rowBase = blockIdx.y * 128;
    if (rowBase >= j.M) return;
    const int colBase = (is0 ? bx : bx - j0.xt) * 128;

    const int tid = threadIdx.x;
    const int warp = tid >> 5, lane = tid & 31;
    const int wm = (warp & 1) * 64;
    const int wn = (warp >> 1) * 32;

    const int ktiles = K / BK;
    const int S = gridDim.z;
    const int kt0 = (int)(((long long)blockIdx.z * ktiles) / S);
    const int kt1 = (int)(((long long)(blockIdx.z + 1) * ktiles) / S);
    const int nch = kt1 - kt0;

    auto load_chunk = [&](int buf, int kt) {
        const int k0 = kt * BK;
        #pragma unroll
        for (int it2 = 0; it2 < 8; it2++) {
            const int plane = it2 >> 1;
            const int rem = (it2 & 1) ? (256 + tid) : tid;   // 0..511
            const int row = rem >> 2;
            const int kp = rem & 3;
            const __nv_bfloat16* g = (plane == 0) ? j.Ah : (plane == 1) ? j.Al
                                    : (plane == 2) ? j.Bh : j.Bl;
            const int ld  = (plane < 2) ? j.lda : j.ldb;
            const int rb  = (plane < 2) ? rowBase : colBase;
            const int lim = (plane < 2) ? j.M : j.N;
            const int grow = rb + row;
            const bool v = grow < lim;
            const char* src = (const char*)(g + (size_t)(v ? grow : 0) * ld + k0)
                              + kp * 16;
            uint32_t dst = smbase +
                (uint32_t)((((buf * 4 + plane) * 128 + row) * LDS + kp * 8) * 2);
            cp16(dst, src, v);
        }
        asm volatile("cp.async.commit_group;" ::: "memory");
    };

    float acc[4][4][4];
    #pragma unroll
    for (int a = 0; a < 4; a++)
        #pragma unroll
        for (int b = 0; b < 4; b++)
            #pragma unroll
            for (int d = 0; d < 4; d++) acc[a][b][d] = 0.0f;

    // B-fragment ldmatrix address lanes
    const int bg = lane >> 3;          // tile group 0..3
    const int br = lane & 7;           // row within tile
    const int b_nt_off = (bg >> 1);    // 0 or 1
    const int b_kh = (bg & 1) * 8;     // 0 or 8

    if (nch > 0) load_chunk(0, kt0);

    for (int i = 0; i < nch; i++) {
        const int buf = i & 1;
        asm volatile("cp.async.wait_group 0;" ::: "memory");
        __syncthreads();
        if (i + 1 < nch) load_chunk(buf ^ 1, kt0 + i + 1);

        #pragma unroll
        for (int ks = 0; ks < 2; ks++) {
            uint32_t bfh[4][2], bfl[4][2];
            #pragma unroll
            for (int np = 0; np < 2; np++) {       // nt pairs (0,1) and (2,3)
                const int nr = wn + (np * 2 + b_nt_off) * 8 + br;
                const int kc = ks * 16 + b_kh;
                uint32_t ah = smbase +
                    (uint32_t)((((buf * 4 + 2) * 128 + nr) * LDS + kc) * 2);
                ldm_x4a(bfh[np*2][0], bfh[np*2][1], bfh[np*2+1][0], bfh[np*2+1][1], ah);
                uint32_t al = smbase +
                    (uint32_t)((((buf * 4 + 3) * 128 + nr) * LDS + kc) * 2);
                ldm_x4a(bfl[np*2][0], bfl[np*2][1], bfl[np*2+1][0], bfl[np*2+1][1], al);
            }
            const int ar = wm + (lane & 15);
            const int ac = ks * 16 + (lane >> 4) * 8;
            uint32_t af[4][4];
            // load ALL A-hi fragments (4 ldmatrix), then full passes
            #pragma unroll
            for (int mt = 0; mt < 4; mt++) {
                uint32_t ah = smbase +
                    (uint32_t)((((buf * 4 + 0) * 128 + ar + mt * 16) * LDS + ac) * 2);
                ldm_x4a(af[mt][0], af[mt][1], af[mt][2], af[mt][3], ah);
            }
            // pass 1: A-hi x B-hi (16 MMAs, same-acc spacing 16)
            #pragma unroll
            for (int mt = 0; mt < 4; mt++)
                #pragma unroll
                for (int nt = 0; nt < 4; nt++)
                    mma_bf16(acc[mt][nt], af[mt], bfh[nt]);
            // pass 2: A-hi x B-lo
            #pragma unroll
            for (int mt = 0; mt < 4; mt++)
                #pragma unroll
                for (int nt = 0; nt < 4; nt++)
                    mma_bf16(acc[mt][nt], af[mt], bfl[nt]);
            // reload A-lo into the same registers
            #pragma unroll
            for (int mt = 0; mt < 4; mt++) {
                uint32_t al = smbase +
                    (uint32_t)((((buf * 4 + 1) * 128 + ar + mt * 16) * LDS + ac) * 2);
                ldm_x4a(af[mt][0], af[mt][1], af[mt][2], af[mt][3], al);
            }
            // pass 3: A-lo x B-hi
            #pragma unroll
            for (int mt = 0; mt < 4; mt++)
                #pragma unroll
                for (int nt = 0; nt < 4; nt++)
                    mma_bf16(acc[mt][nt], af[mt], bfh[nt]);
        }
    }

    float* Cz = j.C + (size_t)blockIdx.z * j.strideCz;
    #pragma unroll
    for (int mt = 0; mt < 4; mt++) {
        int r0 = rowBase + wm + mt * 16 + (lane >> 2);
        #pragma unroll
        for (int nt = 0; nt < 4; nt++) {
            int c = colBase + wn + nt * 8 + (lane & 3) * 2;
            if (c < j.N) {
                if (r0 < j.M) {
                    Cz[(size_t)r0 * j.ldc + c]     = acc[mt][nt][0];
                    Cz[(size_t)r0 * j.ldc + c + 1] = acc[mt][nt][1];
                }
                if (r0 + 8 < j.M) {
                    Cz[(size_t)(r0 + 8) * j.ldc + c]     = acc[mt][nt][2];
                    Cz[(size_t)(r0 + 8) * j.ldc + c + 1] = acc[mt][nt][3];
                }
            }
        }
    }
}

// ---------------- conv front-end -------------------------------------------
__global__ void conv_kernel(const float* __restrict__ x,
                            const float* __restrict__ idd,
                            const float* __restrict__ cw, const float* __restrict__ cb,
                            const float* __restrict__ lw, const float* __restrict__ lb)
{
    __shared__ float xs[SNPX];
    __shared__ float pwi[200];
    __shared__ float pwl[200];
    const int n = blockIdx.x;
    const float* xr = x + (size_t)n * SNPX;
    for (int i = threadIdx.x; i < SNPX / 4; i += blockDim.x)
        ((float4*)xs)[i] = ((const float4*)xr)[i];
    if (threadIdx.x < 200) {
        int co = threadIdx.x / 25, off = threadIdx.x % 25;
        int widx = co * 25 + (off % 5) * 5 + (off / 5);
        pwi[threadIdx.x] = cw[widx];
        pwl[threadIdx.x] = lw[widx];
    }
    if (threadIdx.x >= 224) {
        int j = threadIdx.x - 224;
        split2(idd[(size_t)n * IDDIM + j],
               &g_fb_h[(size_t)n * FD + 3200 + j], &g_fb_l[(size_t)n * FD + 3200 + j]);
    }
    __syncthreads();

    const bool leaf = (n >= NINT);
    const int t = threadIdx.x;
    if (t < 200) {
        const float* xp = &xs[25 * t];
        #pragma unroll
        for (int co = 0; co < 8; co++) {
            float acc = cb[co];
            #pragma unroll
            for (int off = 0; off < 25; off++) acc += xp[off] * pwi[co * 25 + off];
            acc = fmaxf(acc, 0.0f);
            size_t o = (size_t)n * FD + co * 200 + t;
            split2(acc, &g_fb_h[o], &g_fb_l[o]);
        }
        if (leaf) {
            #pragma unroll
            for (int co = 0; co < 8; co++) {
                float acc = lb[co];
                #pragma unroll
                for (int off = 0; off < 25; off++) acc += xp[off] * pwl[co * 25 + off];
                acc = fmaxf(acc, 0.0f);
                g_h[(size_t)n * DD + co * 200 + t] = acc;
                size_t o = (size_t)n * FD + DD + co * 200 + t;
                split2(acc, &g_fb_h[o], &g_fb_l[o]);
            }
        }
    }
    if (leaf) {
        for (int j = threadIdx.x; j < DD; j += blockDim.x)
            g_c[(size_t)n * DD + j] = 0.0f;
    }
}

// ---------------- all LSTM weight splits in one kernel ---------------------
__global__ void split_weights(const float* __restrict__ Wi, const float* __restrict__ Wo,
                              const float* __restrict__ Wu, const float* __restrict__ Wf)
{
    const int WN = DD * KIN;
    int i = blockIdx.x * blockDim.x + threadIdx.x;
    if (i >= 4 * WN) return;
    int which = i / WN, r = i % WN;
    const float* src = (which == 0) ? Wi : (which == 1) ? Wo : (which == 2) ? Wu : Wf;
    float v = src[r];
    if (which < 3) split2(v, &g_wiou_h[(size_t)which * WN + r], &g_wiou_l[(size_t)which * WN + r]);
    else           split2(v, &g_wf_h[r], &g_wf_l[r]);
}

// ---------------- pack + split fc0 weight [192,3232] -----------------------
__global__ void pack_w012(const float* __restrict__ fc0_w)
{
    int idx = blockIdx.x * blockDim.x + threadIdx.x;
    if (idx >= YW * FD) return;
    int r = idx / FD, k = idx % FD;
    float v = fc0_w[(size_t)(r & 63) * (3 * FD) + (size_t)(r >> 6) * FD + k];
    split2(v, &g_w012h[idx], &g_w012l[idx]);
}

// ---------------- initial build (depth-11 parents, reads leaf h) -----------
__global__ void build_xin(int start, const float* __restrict__ idd)
{
    const int t = blockIdx.x;
    const int p = start + t;
    const int l = 2 * p + 1, r = 2 * p + 2;
    const float4* hl4 = (const float4*)&g_h[(size_t)l * DD];
    const float4* hr4 = (const float4*)&g_h[(size_t)r * DD];
    const size_t oiou = (size_t)t * KIN;
    const size_t ofl  = (size_t)(2 * t) * KIN;
    const size_t ofr  = (size_t)(2 * t + 1) * KIN;
    for (int j = threadIdx.x; j < IDDIM; j += blockDim.x) {
        float v = idd[(size_t)p * IDDIM + j];
        __nv_bfloat16 h, lo2;
        split2(v, &h, &lo2);
        g_xiou_h[oiou + j] = h; g_xiou_l[oiou + j] = lo2;
        g_xf_h[ofl + j] = h;    g_xf_l[ofl + j] = lo2;
        g_xf_h[ofr + j] = h;    g_xf_l[ofr + j] = lo2;
    }
    for (int j4 = threadIdx.x; j4 < DD / 4; j4 += blockDim.x) {
        float4 a = hl4[j4], b = hr4[j4];
        float4 s = make_float4(a.x + b.x, a.y + b.y, a.z + b.z, a.w + b.w);
        uint2 hi, lo;
        split4(s, &hi, &lo);
        *(uint2*)&g_xiou_h[oiou + IDDIM + j4 * 4] = hi;
        *(uint2*)&g_xiou_l[oiou + IDDIM + j4 * 4] = lo;
        split4(a, &hi, &lo);
        *(uint2*)&g_xf_h[ofl + IDDIM + j4 * 4] = hi;
        *(uint2*)&g_xf_l[ofl + IDDIM + j4 * 4] = lo;
        split4(b, &hi, &lo);
        *(uint2*)&g_xf_h[ofr + IDDIM + j4 * 4] = hi;
        *(uint2*)&g_xf_l[ofr + IDDIM + j4 * 4] = lo;
    }
}

// ---------------- fused combine: sibling pair + writes parent xin ----------
// float4-vectorized over the DD dimension.
__global__ void lstm_combine2(int start, int m, int S, int writeNext,
                              const float* __restrict__ bi, const float* __restrict__ bf,
                              const float* __restrict__ bu, const float* __restrict__ bo,
                              const float* __restrict__ idd)
{
    const int t = blockIdx.x;
    const int two = (m >= 2);
    const int p0 = start + 2 * t;
    const int p1 = p0 + 1;
    const int q  = (p0 - 1) >> 1;                 // parent node
    const size_t oiou = (size_t)t * KIN;          // parent-local rows
    const size_t ofl  = (size_t)(2 * t) * KIN;
    const size_t ofr  = (size_t)(2 * t + 1) * KIN;

    if (writeNext) {
        for (int j = threadIdx.x; j < IDDIM; j += blockDim.x) {
            float v = idd[(size_t)q * IDDIM + j];
            __nv_bfloat16 h, lo2;
            split2(v, &h, &lo2);
            g_xiou_h[oiou + j] = h; g_xiou_l[oiou + j] = lo2;
            g_xf_h[ofl + j] = h;    g_xf_l[ofl + j] = lo2;
            g_xf_h[ofr + j] = h;    g_xf_l[ofr + j] = lo2;
        }
    }

    for (int j4 = threadIdx.x; j4 < DD / 4; j4 += blockDim.x) {
        const int j = j4 * 4;
        const float4 vbi = *(const float4*)&bi[j];
        const float4 vbf = *(const float4*)&bf[j];
        const float4 vbu = *(const float4*)&bu[j];
        const float4 vbo = *(const float4*)&bo[j];
        float4 h4[2];
        #pragma unroll
        for (int s = 0; s < 2; s++) {
            if (s == 1 && !two) { h4[1] = make_float4(0.f, 0.f, 0.f, 0.f); break; }
            const int p = (s == 0) ? p0 : p1;
            const int loc = 2 * t + s;
            float4 si = make_float4(0.f, 0.f, 0.f, 0.f), so = si, su = si,
                   sfl = si, sfr = si;
            for (int z = 0; z < S; z++) {
                const float* piou = &g_pre_iou[((size_t)z * m + loc) * NIOU];
                float4 a = *(const float4*)&piou[j];
                float4 b = *(const float4*)&piou[DD + j];
                float4 cc = *(const float4*)&piou[2 * DD + j];
                si.x += a.x; si.y += a.y; si.z += a.z; si.w += a.w;
                so.x += b.x; so.y += b.y; so.z += b.z; so.w += b.w;
                su.x += cc.x; su.y += cc.y; su.z += cc.z; su.w += cc.w;
                const float* pf = &g_pre_f[(size_t)z * 2 * m * DD];
                float4 d = *(const float4*)&pf[(size_t)(2 * loc) * DD + j];
                float4 e = *(const float4*)&pf[(size_t)(2 * loc + 1) * DD + j];
                sfl.x += d.x; sfl.y += d.y; sfl.z += d.z; sfl.w += d.w;
                sfr.x += e.x; sfr.y += e.y; sfr.z += e.z; sfr.w += e.w;
            }
            const int l = 2 * p + 1, r = 2 * p + 2;
            float4 cl = *(const float4*)&g_c[(size_t)l * DD + j];
            float4 cr = *(const float4*)&g_c[(size_t)r * DD + j];
            float4 cn, hn;
            {
                float vi, vo, vu, fl, fr;
                vi = sigmoidf(si.x + vbi.x); vo = sigmoidf(so.x + vbo.x);
                vu = tanhf(su.x + vbu.x);
                fl = sigmoidf(sfl.x + vbf.x); fr = sigmoidf(sfr.x + vbf.x);
                cn.x = vi * vu + fl * cl.x + fr * cr.x; hn.x = vo * tanhf(cn.x);
                vi = sigmoidf(si.y + vbi.y); vo = sigmoidf(so.y + vbo.y);
                vu = tanhf(su.y + vbu.y);
                fl = sigmoidf(sfl.y + vbf.y); fr = sigmoidf(sfr.y + vbf.y);
                cn.y = vi * vu + fl * cl.y + fr * cr.y; hn.y = vo * tanhf(cn.y);
                vi = sigmoidf(si.z + vbi.z); vo = sigmoidf(so.z + vbo.z);
                vu = tanhf(su.z + vbu.z);
                fl = sigmoidf(sfl.z + vbf.z); fr = sigmoidf(sfr.z + vbf.z);
                cn.z = vi * vu + fl * cl.z + fr * cr.z; hn.z = vo * tanhf(cn.z);
                vi = sigmoidf(si.w + vbi.w); vo = sigmoidf(so.w + vbo.w);
                vu = tanhf(su.w + vbu.w);
                fl = sigmoidf(sfl.w + vbf.w); fr = sigmoidf(sfr.w + vbf.w);
                cn.w = vi * vu + fl * cl.w + fr * cr.w; hn.w = vo * tanhf(cn.w);
            }
            *(float4*)&g_c[(size_t)p * DD + j] = cn;
            uint2 hi, lo;
            split4(hn, &hi, &lo);
            *(uint2*)&g_fb_h[(size_t)p * FD + DD + j] = hi;
            *(uint2*)&g_fb_l[(size_t)p * FD + DD + j] = lo;
            h4[s] = hn;
        }
        if (writeNext) {
            uint2 hi, lo;
            float4 sum = make_float4(h4[0].x + h4[1].x, h4[0].y + h4[1].y,
                                     h4[0].z + h4[1].z, h4[0].w + h4[1].w);
            split4(sum, &hi, &lo);
            *(uint2*)&g_xiou_h[oiou + IDDIM + j] = hi;
            *(uint2*)&g_xiou_l[oiou + IDDIM + j] = lo;
            split4(h4[0], &hi, &lo);
            *(uint2*)&g_xf_h[ofl + IDDIM + j] = hi;
            *(uint2*)&g_xf_l[ofl + IDDIM + j] = lo;
            split4(h4[1], &hi, &lo);
            *(uint2*)&g_xf_h[ofr + IDDIM + j] = hi;
            *(uint2*)&g_xf_l[ofr + IDDIM + j] = lo;
        }
    }
}

// ---------------- head: fusion combine + fc1 + fc2 -------------------------
__device__ __forceinline__ float ysum(int node, int col)
{
    float s = 0.f;
    #pragma unroll
    for (int z = 0; z < SFC0; z++)
        s += g_y[((size_t)z * NN + node) * YW + col];
    return s;
}

__global__ void head_kernel(const float* __restrict__ fc0_b,
                            const float* __restrict__ fc1_w, const float* __restrict__ fc1_b,
                            const float* __restrict__ fc2_w, const float* __restrict__ fc2_b,
                            float* __restrict__ out)
{
    __shared__ float z[64];
    __shared__ float z1[64];
    __shared__ float partial[2];
    const int n = blockIdx.x;
    const int j = threadIdx.x;

    float acc = fc0_b[j] + ysum(n, j);
    if (n > 0) acc += ysum((n - 1) >> 1, 64 + j);
    if (n < NINT)
        acc += 0.5f * (ysum(2 * n + 1, 128 + j) + ysum(2 * n + 2, 128 + j));
    z[j] = fmaxf(acc, 0.0f);
    __syncthreads();

    float a1 = fc1_b[j];
    #pragma unroll 8
    for (int k = 0; k < 64; k++) a1 += fc1_w[j * 64 + k] * z[k];
    z1[j] = fmaxf(a1, 0.0f);
    __syncthreads();

    float v = fc2_w[j] * z1[j];
    #pragma unroll
    for (int off = 16; off > 0; off >>= 1) v += __shfl_down_sync(0xffffffffu, v, off);
    if ((j & 31) == 0) partial[j >> 5] = v;
    __syncthreads();
    if (j == 0) out[n] = partial[0] + partial[1] + fc2_b[0];
}

// ---------------- launch ----------------------------------------------------
extern "C" void kernel_launch(void* const* d_in, const int* in_sizes, int n_in,
                              void* d_out, int out_size)
{
    const float* x      = (const float*)d_in[0];
    const float* idd    = (const float*)d_in[1];
    const float* conv_w  = (const float*)d_in[4];
    const float* conv_b  = (const float*)d_in[5];
    const float* convl_w = (const float*)d_in[6];
    const float* convl_b = (const float*)d_in[7];
    const float* Wi = (const float*)d_in[8];   const float* bi = (const float*)d_in[9];
    const float* Wf = (const float*)d_in[10];  const float* bf = (const float*)d_in[11];
    const float* Wu = (const float*)d_in[12];  const float* bu = (const float*)d_in[13];
    const float* Wo = (const float*)d_in[14];  const float* bo = (const float*)d_in[15];
    const float* fc0_w = (const float*)d_in[16]; const float* fc0_b = (const float*)d_in[17];
    const float* fc1_w = (const float*)d_in[18]; const float* fc1_b = (const float*)d_in[19];
    const float* fc2_w = (const float*)d_in[20]; const float* fc2_b = (const float*)d_in[21];
    float* out = (float*)d_out;

    float *p_pre_iou, *p_pre_f, *p_y;
    __nv_bfloat16 *p_xiou_h, *p_xiou_l, *p_xf_h, *p_xf_l;
    __nv_bfloat16 *p_wiou_h, *p_wiou_l, *p_wf_h, *p_wf_l;
    __nv_bfloat16 *p_fb_h, *p_fb_l, *p_w012h, *p_w012l;
    cudaGetSymbolAddress((void**)&p_pre_iou, g_pre_iou);
    cudaGetSymbolAddress((void**)&p_pre_f,   g_pre_f);
    cudaGetSymbolAddress((void**)&p_y,       g_y);
    cudaGetSymbolAddress((void**)&p_xiou_h,  g_xiou_h);
    cudaGetSymbolAddress((void**)&p_xiou_l,  g_xiou_l);
    cudaGetSymbolAddress((void**)&p_xf_h,    g_xf_h);
    cudaGetSymbolAddress((void**)&p_xf_l,    g_xf_l);
    cudaGetSymbolAddress((void**)&p_wiou_h,  g_wiou_h);
    cudaGetSymbolAddress((void**)&p_wiou_l,  g_wiou_l);
    cudaGetSymbolAddress((void**)&p_wf_h,    g_wf_h);
    cudaGetSymbolAddress((void**)&p_wf_l,    g_wf_l);
    cudaGetSymbolAddress((void**)&p_fb_h,    g_fb_h);
    cudaGetSymbolAddress((void**)&p_fb_l,    g_fb_l);
    cudaGetSymbolAddress((void**)&p_w012h,   g_w012h);
    cudaGetSymbolAddress((void**)&p_w012l,   g_w012l);

    cudaFuncSetAttribute(bmma2, cudaFuncAttributeMaxDynamicSharedMemorySize, BSM);

    // 0) split weights into bf16 hi/lo planes
    split_weights<<<(4 * DD * KIN + 255) / 256, 256>>>(Wi, Wo, Wu, Wf);
    pack_w012<<<(YW * FD + 255) / 256, 256>>>(fc0_w);

    // 1) conv front-end
    conv_kernel<<<NN, 256>>>(x, idd, conv_w, conv_b, convl_w, convl_b);

    // 2) initial xin build for depth-11 parents (reads leaf h)
    build_xin<<<2048, 256>>>(2047, idd);

    // 3) bottom-up tree LSTM: ONE dual-job GEMM launch + fused combine / level
    for (int depth = 11; depth >= 0; depth--) {
        int m = 1 << depth;
        int start = m - 1;
        int S = (m >= 2048) ? 1 : (m == 1024) ? 2 : (m == 512) ? 4 : (m == 256) ? 8 : 16;
        Job jiou = { p_xiou_h, p_xiou_l, p_wiou_h, p_wiou_l, p_pre_iou,
                     KIN, KIN, NIOU, (size_t)m * NIOU, m, NIOU, XT_IOU };
        Job jf   = { p_xf_h, p_xf_l, p_wf_h, p_wf_l, p_pre_f,
                     KIN, KIN, DD, (size_t)2 * m * DD, 2 * m, DD, XT_F };
        dim3 g(XT_IOU + XT_F, (2 * m + 127) / 128, S);
        bmma2<<<g, 256, BSM>>>(jiou, jf, KIN);
        int blocks = (m >= 2) ? m / 2 : 1;
        lstm_combine2<<<blocks, 256>>>(start, m, S, depth > 0 ? 1 : 0,
                                       bi, bf, bu, bo, idd);
    }

    // 4) fused fc0 with split-K: Y = feat @ [W0a;W0b;W0c]^T
    Job jfc0 = { p_fb_h, p_fb_l, p_w012h, p_w012l, p_y,
                 FD, FD, YW, (size_t)NN * YW, NN, YW, 2 };
    Job jnull = jfc0; jnull.xt = 0;
    dim3 g3(2, (NN + 127) / 128, SFC0);
    bmma2<<<g3, 256, BSM>>>(jfc0, jnull, FD);

    // 5) fusion combine + fc1 + fc2
    head_kernel<<<NN, 64>>>(fc0_b, fc1_w, fc1_b, fc2_w, fc2_b, out);
}

// round 13
// speedup vs baseline: 1.3250x; 1.0857x over previous
#include <cuda_runtime.h>
#include <cuda_bf16.h>
#include <math.h>
#include <stdint.h>

// ---------------- problem constants ----------------
#define NN     8191
#define NINT   4095
#define SNPX   5000
#define DD     1600
#define IDDIM  32
#define KIN    1632        // DD + IDDIM (mult of 32)
#define FD     3232        // 2*DD + IDDIM (mult of 32)
#define YW     192         // 3 * 64 fc0 pieces
#define NIOU   4800        // 3 * DD
#define SFC0   4
#define BK     32          // K per pipeline chunk
#define LDS    40          // smem row stride (bf16), 32 data + 8 pad
#define BSM    (2 * 4 * 128 * LDS * 2)   // dynamic smem for bmma2 (80KB)
#define XT_IOU 38          // ceil(4800/128)
#define XT_F   13          // ceil(1600/128)

// ---------------- scratch ----------------
__device__ float g_h[(size_t)NN * DD];           // only leaves consumed
__device__ float g_c[(size_t)NN * DD];           // leaves never touched (zero by math)
__device__ float g_pre_iou[(size_t)2048 * NIOU]; // S*m <= 2048 partial rows
__device__ float g_pre_f[(size_t)4096 * DD];     // S*2m <= 4096 partial rows
__device__ float g_y[(size_t)SFC0 * NN * YW];

__device__ __nv_bfloat16 g_fb_h[(size_t)NN * FD];
__device__ __nv_bfloat16 g_fb_l[(size_t)NN * FD];
__device__ __nv_bfloat16 g_xiou_h[(size_t)2048 * KIN];
__device__ __nv_bfloat16 g_xiou_l[(size_t)2048 * KIN];
__device__ __nv_bfloat16 g_xf_h[(size_t)4096 * KIN];
__device__ __nv_bfloat16 g_xf_l[(size_t)4096 * KIN];
__device__ __nv_bfloat16 g_wiou_h[(size_t)NIOU * KIN];
__device__ __nv_bfloat16 g_wiou_l[(size_t)NIOU * KIN];
__device__ __nv_bfloat16 g_wf_h[(size_t)DD * KIN];
__device__ __nv_bfloat16 g_wf_l[(size_t)DD * KIN];
__device__ __nv_bfloat16 g_w012h[(size_t)YW * FD];
__device__ __nv_bfloat16 g_w012l[(size_t)YW * FD];

struct Job {
    const __nv_bfloat16 *Ah, *Al, *Bh, *Bl;
    float* C;
    int lda, ldb, ldc;
    size_t strideCz;
    int M, N, xt;
};

__device__ __forceinline__ float sigmoidf(float x) { return 1.0f / (1.0f + expf(-x)); }

__device__ __forceinline__ void split2(float v, __nv_bfloat16* hi, __nv_bfloat16* lo)
{
    __nv_bfloat16 h = __float2bfloat16(v);
    *hi = h;
    *lo = __float2bfloat16(v - __bfloat162float(h));
}

// pack 4 consecutive hi/lo bf16 from 4 floats into two uint2-able halves
__device__ __forceinline__ void split4(const float4 v, uint2* hi, uint2* lo)
{
    __nv_bfloat16 h0, l0, h1, l1, h2, l2, h3, l3;
    split2(v.x, &h0, &l0); split2(v.y, &h1, &l1);
    split2(v.z, &h2, &l2); split2(v.w, &h3, &l3);
    __nv_bfloat162 a = {h0, h1}, b = {h2, h3};
    __nv_bfloat162 c = {l0, l1}, d = {l2, l3};
    hi->x = *(uint32_t*)&a; hi->y = *(uint32_t*)&b;
    lo->x = *(uint32_t*)&c; lo->y = *(uint32_t*)&d;
}

__device__ __forceinline__ uint32_t smem_u32(const void* p)
{
    uint32_t a;
    asm("{ .reg .u64 t; cvta.to.shared.u64 t, %1; cvt.u32.u64 %0, t; }"
        : "=r"(a) : "l"(p));
    return a;
}

__device__ __forceinline__ void cp16(uint32_t dst, const void* src, bool v)
{
    int sz = v ? 16 : 0;   // zfill when guard fails
    asm volatile("cp.async.cg.shared.global [%0], [%1], 16, %2;"
                 :: "r"(dst), "l"(src), "r"(sz) : "memory");
}

__device__ __forceinline__ void ldm_x4a(uint32_t& r0, uint32_t& r1, uint32_t& r2, uint32_t& r3,
                                        uint32_t addr)
{
    asm volatile("ldmatrix.sync.aligned.m8n8.x4.shared.b16 {%0,%1,%2,%3}, [%4];"
                 : "=r"(r0), "=r"(r1), "=r"(r2), "=r"(r3) : "r"(addr));
}

__device__ __forceinline__ void mma_bf16(float* c, const uint32_t* a, const uint32_t* b)
{
    asm volatile("mma.sync.aligned.m16n8k16.row.col.f32.bf16.bf16.f32 "
                 "{%0,%1,%2,%3}, {%4,%5,%6,%7}, {%8,%9}, {%0,%1,%2,%3};"
                 : "+f"(c[0]), "+f"(c[1]), "+f"(c[2]), "+f"(c[3])
                 : "r"(a[0]), "r"(a[1]), "r"(a[2]), "r"(a[3]), "r"(b[0]), "r"(b[1]));
}

// ---------------- dual-job pipelined tensor GEMM ----------------------------
// Cz[M,N] = A[M,Kz] @ B[N,Kz]^T per job; bf16 3-term split, fp32 acc,
// 128x128 tile, BK=32, 256 threads (2x4 warps, 64x32 warp tile),
// double-buffered cp.async with ONE __syncthreads per chunk,
// B fragments via ldmatrix; MMAs in full warp-tile passes.
__global__ void __launch_bounds__(256, 2)
bmma2(Job j0, Job j1, int K)
{
    extern __shared__ __align__(16) __nv_bfloat16 sm[];  // [2][4][128][LDS]
    const uint32_t smbase = smem_u32(sm);
    const int bx = blockIdx.x;
    const bool is0 = bx < j0.xt;
    const Job j = is0 ? j0 : j1;
    const int rowBase = blockIdx.y * 128;
    if (rowBase >= j.M) return;
    const int colBase = (is0 ? bx : bx - j0.xt) * 128;

    const int tid = threadIdx.x;
    const int warp = tid >> 5, lane = tid & 31;
    const int wm = (warp & 1) * 64;
    const int wn = (warp >> 1) * 32;

    const int ktiles = K / BK;
    const int S = gridDim.z;
    const int kt0 = (int)(((long long)blockIdx.z * ktiles) / S);
    const int kt1 = (int)(((long long)(blockIdx.z + 1) * ktiles) / S);
    const int nch = kt1 - kt0;

    auto load_chunk = [&](int buf, int kt) {
        const int k0 = kt * BK;
        #pragma unroll
        for (int it2 = 0; it2 < 8; it2++) {
            const int plane = it2 >> 1;
            const int rem = (it2 & 1) ? (256 + tid) : tid;   // 0..511
            const int row = rem >> 2;
            const int kp = rem & 3;
            const __nv_bfloat16* g = (plane == 0) ? j.Ah : (plane == 1) ? j.Al
                                    : (plane == 2) ? j.Bh : j.Bl;
            const int ld  = (plane < 2) ? j.lda : j.ldb;
            const int rb  = (plane < 2) ? rowBase : colBase;
            const int lim = (plane < 2) ? j.M : j.N;
            const int grow = rb + row;
            const bool v = grow < lim;
            const char* src = (const char*)(g + (size_t)(v ? grow : 0) * ld + k0)
                              + kp * 16;
            uint32_t dst = smbase +
                (uint32_t)((((buf * 4 + plane) * 128 + row) * LDS + kp * 8) * 2);
            cp16(dst, src, v);
        }
        asm volatile("cp.async.commit_group;" ::: "memory");
    };

    float acc[4][4][4];
    #pragma unroll
    for (int a = 0; a < 4; a++)
        #pragma unroll
        for (int b = 0; b < 4; b++)
            #pragma unroll
            for (int d = 0; d < 4; d++) acc[a][b][d] = 0.0f;

    // B-fragment ldmatrix address lanes
    const int bg = lane >> 3;          // tile group 0..3
    const int br = lane & 7;           // row within tile
    const int b_nt_off = (bg >> 1);    // 0 or 1
    const int b_kh = (bg & 1) * 8;     // 0 or 8

    if (nch > 0) load_chunk(0, kt0);

    for (int i = 0; i < nch; i++) {
        const int buf = i & 1;
        asm volatile("cp.async.wait_group 0;" ::: "memory");
        __syncthreads();
        if (i + 1 < nch) load_chunk(buf ^ 1, kt0 + i + 1);

        #pragma unroll
        for (int ks = 0; ks < 2; ks++) {
            uint32_t bfh[4][2], bfl[4][2];
            #pragma unroll
            for (int np = 0; np < 2; np++) {       // nt pairs (0,1) and (2,3)
                const int nr = wn + (np * 2 + b_nt_off) * 8 + br;
                const int kc = ks * 16 + b_kh;
                uint32_t ah = smbase +
                    (uint32_t)((((buf * 4 + 2) * 128 + nr) * LDS + kc) * 2);
                ldm_x4a(bfh[np*2][0], bfh[np*2][1], bfh[np*2+1][0], bfh[np*2+1][1], ah);
                uint32_t al = smbase +
                    (uint32_t)((((buf * 4 + 3) * 128 + nr) * LDS + kc) * 2);
                ldm_x4a(bfl[np*2][0], bfl[np*2][1], bfl[np*2+1][0], bfl[np*2+1][1], al);
            }
            const int ar = wm + (lane & 15);
            const int ac = ks * 16 + (lane >> 4) * 8;
            uint32_t af[4][4];
            #pragma unroll
            for (int mt = 0; mt < 4; mt++) {
                uint32_t ah = smbase +
                    (uint32_t)((((buf * 4 + 0) * 128 + ar + mt * 16) * LDS + ac) * 2);
                ldm_x4a(af[mt][0], af[mt][1], af[mt][2], af[mt][3], ah);
            }
            #pragma unroll
            for (int mt = 0; mt < 4; mt++)
                #pragma unroll
                for (int nt = 0; nt < 4; nt++)
                    mma_bf16(acc[mt][nt], af[mt], bfh[nt]);
            #pragma unroll
            for (int mt = 0; mt < 4; mt++)
                #pragma unroll
                for (int nt = 0; nt < 4; nt++)
                    mma_bf16(acc[mt][nt], af[mt], bfl[nt]);
            #pragma unroll
            for (int mt = 0; mt < 4; mt++) {
                uint32_t al = smbase +
                    (uint32_t)((((buf * 4 + 1) * 128 + ar + mt * 16) * LDS + ac) * 2);
                ldm_x4a(af[mt][0], af[mt][1], af[mt][2], af[mt][3], al);
            }
            #pragma unroll
            for (int mt = 0; mt < 4; mt++)
                #pragma unroll
                for (int nt = 0; nt < 4; nt++)
                    mma_bf16(acc[mt][nt], af[mt], bfh[nt]);
        }
    }

    float* Cz = j.C + (size_t)blockIdx.z * j.strideCz;
    #pragma unroll
    for (int mt = 0; mt < 4; mt++) {
        int r0 = rowBase + wm + mt * 16 + (lane >> 2);
        #pragma unroll
        for (int nt = 0; nt < 4; nt++) {
            int c = colBase + wn + nt * 8 + (lane & 3) * 2;
            if (c < j.N) {
                if (r0 < j.M) {
                    Cz[(size_t)r0 * j.ldc + c]     = acc[mt][nt][0];
                    Cz[(size_t)r0 * j.ldc + c + 1] = acc[mt][nt][1];
                }
                if (r0 + 8 < j.M) {
                    Cz[(size_t)(r0 + 8) * j.ldc + c]     = acc[mt][nt][2];
                    Cz[(size_t)(r0 + 8) * j.ldc + c + 1] = acc[mt][nt][3];
                }
            }
        }
    }
}

// ---------------- conv front-end (no leaf-c zeroing: leaf c never read) ----
__global__ void conv_kernel(const float* __restrict__ x,
                            const float* __restrict__ idd,
                            const float* __restrict__ cw, const float* __restrict__ cb,
                            const float* __restrict__ lw, const float* __restrict__ lb)
{
    __shared__ float xs[SNPX];
    __shared__ float pwi[200];
    __shared__ float pwl[200];
    const int n = blockIdx.x;
    const float* xr = x + (size_t)n * SNPX;
    for (int i = threadIdx.x; i < SNPX / 4; i += blockDim.x)
        ((float4*)xs)[i] = ((const float4*)xr)[i];
    if (threadIdx.x < 200) {
        int co = threadIdx.x / 25, off = threadIdx.x % 25;
        int widx = co * 25 + (off % 5) * 5 + (off / 5);
        pwi[threadIdx.x] = cw[widx];
        pwl[threadIdx.x] = lw[widx];
    }
    if (threadIdx.x >= 224) {
        int j = threadIdx.x - 224;
        split2(idd[(size_t)n * IDDIM + j],
               &g_fb_h[(size_t)n * FD + 3200 + j], &g_fb_l[(size_t)n * FD + 3200 + j]);
    }
    __syncthreads();

    const bool leaf = (n >= NINT);
    const int t = threadIdx.x;
    if (t < 200) {
        const float* xp = &xs[25 * t];
        #pragma unroll
        for (int co = 0; co < 8; co++) {
            float acc = cb[co];
            #pragma unroll
            for (int off = 0; off < 25; off++) acc += xp[off] * pwi[co * 25 + off];
            acc = fmaxf(acc, 0.0f);
            size_t o = (size_t)n * FD + co * 200 + t;
            split2(acc, &g_fb_h[o], &g_fb_l[o]);
        }
        if (leaf) {
            #pragma unroll
            for (int co = 0; co < 8; co++) {
                float acc = lb[co];
                #pragma unroll
                for (int off = 0; off < 25; off++) acc += xp[off] * pwl[co * 25 + off];
                acc = fmaxf(acc, 0.0f);
                g_h[(size_t)n * DD + co * 200 + t] = acc;
                size_t o = (size_t)n * FD + DD + co * 200 + t;
                split2(acc, &g_fb_h[o], &g_fb_l[o]);
            }
        }
    }
}

// ---------------- all LSTM weight splits in one kernel ---------------------
__global__ void split_weights(const float* __restrict__ Wi, const float* __restrict__ Wo,
                              const float* __restrict__ Wu, const float* __restrict__ Wf)
{
    const int WN = DD * KIN;
    int i = blockIdx.x * blockDim.x + threadIdx.x;
    if (i >= 4 * WN) return;
    int which = i / WN, r = i % WN;
    const float* src = (which == 0) ? Wi : (which == 1) ? Wo : (which == 2) ? Wu : Wf;
    float v = src[r];
    if (which < 3) split2(v, &g_wiou_h[(size_t)which * WN + r], &g_wiou_l[(size_t)which * WN + r]);
    else           split2(v, &g_wf_h[r], &g_wf_l[r]);
}

// ---------------- pack + split fc0 weight [192,3232] -----------------------
__global__ void pack_w012(const float* __restrict__ fc0_w)
{
    int idx = blockIdx.x * blockDim.x + threadIdx.x;
    if (idx >= YW * FD) return;
    int r = idx / FD, k = idx % FD;
    float v = fc0_w[(size_t)(r & 63) * (3 * FD) + (size_t)(r >> 6) * FD + k];
    split2(v, &g_w012h[idx], &g_w012l[idx]);
}

// ---------------- initial build (depth-11 parents): xiou ONLY --------------
// (f-gates at depth 11 multiply zero leaf cells — xf rows not needed)
__global__ void build_xin(int start, const float* __restrict__ idd)
{
    const int t = blockIdx.x;
    const int p = start + t;
    const int l = 2 * p + 1, r = 2 * p + 2;
    const float4* hl4 = (const float4*)&g_h[(size_t)l * DD];
    const float4* hr4 = (const float4*)&g_h[(size_t)r * DD];
    const size_t oiou = (size_t)t * KIN;
    for (int j = threadIdx.x; j < IDDIM; j += blockDim.x) {
        float v = idd[(size_t)p * IDDIM + j];
        __nv_bfloat16 h, lo2;
        split2(v, &h, &lo2);
        g_xiou_h[oiou + j] = h; g_xiou_l[oiou + j] = lo2;
    }
    for (int j4 = threadIdx.x; j4 < DD / 4; j4 += blockDim.x) {
        float4 a = hl4[j4], b = hr4[j4];
        float4 s = make_float4(a.x + b.x, a.y + b.y, a.z + b.z, a.w + b.w);
        uint2 hi, lo;
        split4(s, &hi, &lo);
        *(uint2*)&g_xiou_h[oiou + IDDIM + j4 * 4] = hi;
        *(uint2*)&g_xiou_l[oiou + IDDIM + j4 * 4] = lo;
    }
}

// ---------------- fused combine: sibling pair + writes parent xin ----------
// float4-vectorized. noF: skip f-gates & child-c (children are leaves, c=0).
__global__ void lstm_combine2(int start, int m, int S, int writeNext, int noF,
                              const float* __restrict__ bi, const float* __restrict__ bf,
                              const float* __restrict__ bu, const float* __restrict__ bo,
                              const float* __restrict__ idd)
{
    const int t = blockIdx.x;
    const int two = (m >= 2);
    const int p0 = start + 2 * t;
    const int p1 = p0 + 1;
    const int q  = (p0 - 1) >> 1;                 // parent node
    const size_t oiou = (size_t)t * KIN;          // parent-local rows
    const size_t ofl  = (size_t)(2 * t) * KIN;
    const size_t ofr  = (size_t)(2 * t + 1) * KIN;

    if (writeNext) {
        for (int j = threadIdx.x; j < IDDIM; j += blockDim.x) {
            float v = idd[(size_t)q * IDDIM + j];
            __nv_bfloat16 h, lo2;
            split2(v, &h, &lo2);
            g_xiou_h[oiou + j] = h; g_xiou_l[oiou + j] = lo2;
            g_xf_h[ofl + j] = h;    g_xf_l[ofl + j] = lo2;
            g_xf_h[ofr + j] = h;    g_xf_l[ofr + j] = lo2;
        }
    }

    for (int j4 = threadIdx.x; j4 < DD / 4; j4 += blockDim.x) {
        const int j = j4 * 4;
        const float4 vbi = *(const float4*)&bi[j];
        const float4 vbf = *(const float4*)&bf[j];
        const float4 vbu = *(const float4*)&bu[j];
        const float4 vbo = *(const float4*)&bo[j];
        float4 h4[2];
        #pragma unroll
        for (int s = 0; s < 2; s++) {
            if (s == 1 && !two) { h4[1] = make_float4(0.f, 0.f, 0.f, 0.f); break; }
            const int p = (s == 0) ? p0 : p1;
            const int loc = 2 * t + s;
            float4 si = make_float4(0.f, 0.f, 0.f, 0.f), so = si, su = si,
                   sfl = si, sfr = si;
            for (int z = 0; z < S; z++) {
                const float* piou = &g_pre_iou[((size_t)z * m + loc) * NIOU];
                float4 a = *(const float4*)&piou[j];
                float4 b = *(const float4*)&piou[DD + j];
                float4 cc = *(const float4*)&piou[2 * DD + j];
                si.x += a.x; si.y += a.y; si.z += a.z; si.w += a.w;
                so.x += b.x; so.y += b.y; so.z += b.z; so.w += b.w;
                su.x += cc.x; su.y += cc.y; su.z += cc.z; su.w += cc.w;
                if (!noF) {
                    const float* pf = &g_pre_f[(size_t)z * 2 * m * DD];
                    float4 d = *(const float4*)&pf[(size_t)(2 * loc) * DD + j];
                    float4 e = *(const float4*)&pf[(size_t)(2 * loc + 1) * DD + j];
                    sfl.x += d.x; sfl.y += d.y; sfl.z += d.z; sfl.w += d.w;
                    sfr.x += e.x; sfr.y += e.y; sfr.z += e.z; sfr.w += e.w;
                }
            }
            float4 cl = make_float4(0.f, 0.f, 0.f, 0.f), cr = cl;
            if (!noF) {
                const int l = 2 * p + 1, r = 2 * p + 2;
                cl = *(const float4*)&g_c[(size_t)l * DD + j];
                cr = *(const float4*)&g_c[(size_t)r * DD + j];
            }
            float4 cn, hn;
            {
                float vi, vo, vu, fl, fr;
                vi = sigmoidf(si.x + vbi.x); vo = sigmoidf(so.x + vbo.x);
                vu = tanhf(su.x + vbu.x);
                fl = noF ? 0.f : sigmoidf(sfl.x + vbf.x);
                fr = noF ? 0.f : sigmoidf(sfr.x + vbf.x);
                cn.x = vi * vu + fl * cl.x + fr * cr.x; hn.x = vo * tanhf(cn.x);
                vi = sigmoidf(si.y + vbi.y); vo = sigmoidf(so.y + vbo.y);
                vu = tanhf(su.y + vbu.y);
                fl = noF ? 0.f : sigmoidf(sfl.y + vbf.y);
                fr = noF ? 0.f : sigmoidf(sfr.y + vbf.y);
                cn.y = vi * vu + fl * cl.y + fr * cr.y; hn.y = vo * tanhf(cn.y);
                vi = sigmoidf(si.z + vbi.z); vo = sigmoidf(so.z + vbo.z);
                vu = tanhf(su.z + vbu.z);
                fl = noF ? 0.f : sigmoidf(sfl.z + vbf.z);
                fr = noF ? 0.f : sigmoidf(sfr.z + vbf.z);
                cn.z = vi * vu + fl * cl.z + fr * cr.z; hn.z = vo * tanhf(cn.z);
                vi = sigmoidf(si.w + vbi.w); vo = sigmoidf(so.w + vbo.w);
                vu = tanhf(su.w + vbu.w);
                fl = noF ? 0.f : sigmoidf(sfl.w + vbf.w);
                fr = noF ? 0.f : sigmoidf(sfr.w + vbf.w);
                cn.w = vi * vu + fl * cl.w + fr * cr.w; hn.w = vo * tanhf(cn.w);
            }
            *(float4*)&g_c[(size_t)p * DD + j] = cn;
            uint2 hi, lo;
            split4(hn, &hi, &lo);
            *(uint2*)&g_fb_h[(size_t)p * FD + DD + j] = hi;
            *(uint2*)&g_fb_l[(size_t)p * FD + DD + j] = lo;
            h4[s] = hn;
        }
        if (writeNext) {
            uint2 hi, lo;
            float4 sum = make_float4(h4[0].x + h4[1].x, h4[0].y + h4[1].y,
                                     h4[0].z + h4[1].z, h4[0].w + h4[1].w);
            split4(sum, &hi, &lo);
            *(uint2*)&g_xiou_h[oiou + IDDIM + j] = hi;
            *(uint2*)&g_xiou_l[oiou + IDDIM + j] = lo;
            split4(h4[0], &hi, &lo);
            *(uint2*)&g_xf_h[ofl + IDDIM + j] = hi;
            *(uint2*)&g_xf_l[ofl + IDDIM + j] = lo;
            split4(h4[1], &hi, &lo);
            *(uint2*)&g_xf_h[ofr + IDDIM + j] = hi;
            *(uint2*)&g_xf_l[ofr + IDDIM + j] = lo;
        }
    }
}

// ---------------- head: fusion combine + fc1 + fc2 -------------------------
__device__ __forceinline__ float ysum(int node, int col)
{
    float s = 0.f;
    #pragma unroll
    for (int z = 0; z < SFC0; z++)
        s += g_y[((size_t)z * NN + node) * YW + col];
    return s;
}

__global__ void head_kernel(const float* __restrict__ fc0_b,
                            const float* __restrict__ fc1_w, const float* __restrict__ fc1_b,
                            const float* __restrict__ fc2_w, const float* __restrict__ fc2_b,
                            float* __restrict__ out)
{
    __shared__ float z[64];
    __shared__ float z1[64];
    __shared__ float partial[2];
    const int n = blockIdx.x;
    const int j = threadIdx.x;

    float acc = fc0_b[j] + ysum(n, j);
    if (n > 0) acc += ysum((n - 1) >> 1, 64 + j);
    if (n < NINT)
        acc += 0.5f * (ysum(2 * n + 1, 128 + j) + ysum(2 * n + 2, 128 + j));
    z[j] = fmaxf(acc, 0.0f);
    __syncthreads();

    float a1 = fc1_b[j];
    #pragma unroll 8
    for (int k = 0; k < 64; k++) a1 += fc1_w[j * 64 + k] * z[k];
    z1[j] = fmaxf(a1, 0.0f);
    __syncthreads();

    float v = fc2_w[j] * z1[j];
    #pragma unroll
    for (int off = 16; off > 0; off >>= 1) v += __shfl_down_sync(0xffffffffu, v, off);
    if ((j & 31) == 0) partial[j >> 5] = v;
    __syncthreads();
    if (j == 0) out[n] = partial[0] + partial[1] + fc2_b[0];
}

// ---------------- launch ----------------------------------------------------
extern "C" void kernel_launch(void* const* d_in, const int* in_sizes, int n_in,
                              void* d_out, int out_size)
{
    const float* x      = (const float*)d_in[0];
    const float* idd    = (const float*)d_in[1];
    const float* conv_w  = (const float*)d_in[4];
    const float* conv_b  = (const float*)d_in[5];
    const float* convl_w = (const float*)d_in[6];
    const float* convl_b = (const float*)d_in[7];
    const float* Wi = (const float*)d_in[8];   const float* bi = (const float*)d_in[9];
    const float* Wf = (const float*)d_in[10];  const float* bf = (const float*)d_in[11];
    const float* Wu = (const float*)d_in[12];  const float* bu = (const float*)d_in[13];
    const float* Wo = (const float*)d_in[14];  const float* bo = (const float*)d_in[15];
    const float* fc0_w = (const float*)d_in[16]; const float* fc0_b = (const float*)d_in[17];
    const float* fc1_w = (const float*)d_in[18]; const float* fc1_b = (const float*)d_in[19];
    const float* fc2_w = (const float*)d_in[20]; const float* fc2_b = (const float*)d_in[21];
    float* out = (float*)d_out;

    float *p_pre_iou, *p_pre_f, *p_y;
    __nv_bfloat16 *p_xiou_h, *p_xiou_l, *p_xf_h, *p_xf_l;
    __nv_bfloat16 *p_wiou_h, *p_wiou_l, *p_wf_h, *p_wf_l;
    __nv_bfloat16 *p_fb_h, *p_fb_l, *p_w012h, *p_w012l;
    cudaGetSymbolAddress((void**)&p_pre_iou, g_pre_iou);
    cudaGetSymbolAddress((void**)&p_pre_f,   g_pre_f);
    cudaGetSymbolAddress((void**)&p_y,       g_y);
    cudaGetSymbolAddress((void**)&p_xiou_h,  g_xiou_h);
    cudaGetSymbolAddress((void**)&p_xiou_l,  g_xiou_l);
    cudaGetSymbolAddress((void**)&p_xf_h,    g_xf_h);
    cudaGetSymbolAddress((void**)&p_xf_l,    g_xf_l);
    cudaGetSymbolAddress((void**)&p_wiou_h,  g_wiou_h);
    cudaGetSymbolAddress((void**)&p_wiou_l,  g_wiou_l);
    cudaGetSymbolAddress((void**)&p_wf_h,    g_wf_h);
    cudaGetSymbolAddress((void**)&p_wf_l,    g_wf_l);
    cudaGetSymbolAddress((void**)&p_fb_h,    g_fb_h);
    cudaGetSymbolAddress((void**)&p_fb_l,    g_fb_l);
    cudaGetSymbolAddress((void**)&p_w012h,   g_w012h);
    cudaGetSymbolAddress((void**)&p_w012l,   g_w012l);

    cudaFuncSetAttribute(bmma2, cudaFuncAttributeMaxDynamicSharedMemorySize, BSM);

    // 0) split weights into bf16 hi/lo planes
    split_weights<<<(4 * DD * KIN + 255) / 256, 256>>>(Wi, Wo, Wu, Wf);
    pack_w012<<<(YW * FD + 255) / 256, 256>>>(fc0_w);

    // 1) conv front-end
    conv_kernel<<<NN, 256>>>(x, idd, conv_w, conv_b, convl_w, convl_b);

    // 2) initial xiou build for depth-11 parents (reads leaf h; no xf needed)
    build_xin<<<2048, 256>>>(2047, idd);

    // 3) bottom-up tree LSTM
    for (int depth = 11; depth >= 0; depth--) {
        int m = 1 << depth;
        int start = m - 1;
        int S = (m >= 2048) ? 1 : (m == 1024) ? 2 : (m == 512) ? 4 : (m == 256) ? 8 : 16;
        Job jiou = { p_xiou_h, p_xiou_l, p_wiou_h, p_wiou_l, p_pre_iou,
                     KIN, KIN, NIOU, (size_t)m * NIOU, m, NIOU, XT_IOU };
        if (depth == 11) {
            // leaf children: f-gates multiply zero cells — iou GEMM only
            Job jnull = jiou; jnull.xt = 0;
            dim3 g(XT_IOU, (m + 127) / 128, S);
            bmma2<<<g, 256, BSM>>>(jiou, jnull, KIN);
        } else {
            Job jf = { p_xf_h, p_xf_l, p_wf_h, p_wf_l, p_pre_f,
                       KIN, KIN, DD, (size_t)2 * m * DD, 2 * m, DD, XT_F };
            dim3 g(XT_IOU + XT_F, (2 * m + 127) / 128, S);
            bmma2<<<g, 256, BSM>>>(jiou, jf, KIN);
        }
        int blocks = (m >= 2) ? m / 2 : 1;
        lstm_combine2<<<blocks, 256>>>(start, m, S, depth > 0 ? 1 : 0,
                                       depth == 11 ? 1 : 0,
                                       bi, bf, bu, bo, idd);
    }

    // 4) fused fc0 with split-K: Y = feat @ [W0a;W0b;W0c]^T
    Job jfc0 = { p_fb_h, p_fb_l, p_w012h, p_w012l, p_y,
                 FD, FD, YW, (size_t)NN * YW, NN, YW, 2 };
    Job jnull = jfc0; jnull.xt = 0;
    dim3 g3(2, (NN + 127) / 128, SFC0);
    bmma2<<<g3, 256, BSM>>>(jfc0, jnull, FD);

    // 5) fusion combine + fc1 + fc2
    head_kernel<<<NN, 64>>>(fc0_b, fc1_w, fc1_b, fc2_w, fc2_b, out);
}

// round 14
// speedup vs baseline: 1.3356x; 1.0079x over previous
#include <cuda_runtime.h>
#include <cuda_bf16.h>
#include <math.h>
#include <stdint.h>

// ---------------- problem constants ----------------
#define NN     8191
#define NINT   4095
#define SNPX   5000
#define DD     1600
#define IDDIM  32
#define KIN    1632        // DD + IDDIM (mult of 32)
#define FD     3232        // 2*DD + IDDIM (mult of 32)
#define YW     192         // 3 * 64 fc0 pieces
#define NIOU   4800        // 3 * DD
#define SFC0   2
#define BK     32          // K per pipeline chunk
#define LDS    40          // smem row stride (bf16), 32 data + 8 pad
#define BSM    (2 * 4 * 128 * LDS * 2)   // dynamic smem for bmma2 (80KB)
#define XT_IOU 38          // ceil(4800/128)
#define XT_F   13          // ceil(1600/128)

// ---------------- scratch ----------------
__device__ float g_h[(size_t)NN * DD];           // only leaves consumed
__device__ float g_c[(size_t)NN * DD];           // leaves never touched (zero by math)
__device__ float g_pre_iou[(size_t)4096 * NIOU]; // S*m <= 4096 partial rows
__device__ float g_pre_f[(size_t)4096 * DD];     // S*2m <= 4096 partial rows
__device__ float g_y[(size_t)SFC0 * NN * YW];

__device__ __nv_bfloat16 g_fb_h[(size_t)NN * FD];
__device__ __nv_bfloat16 g_fb_l[(size_t)NN * FD];
__device__ __nv_bfloat16 g_xiou_h[(size_t)2048 * KIN];
__device__ __nv_bfloat16 g_xiou_l[(size_t)2048 * KIN];
__device__ __nv_bfloat16 g_xf_h[(size_t)4096 * KIN];
__device__ __nv_bfloat16 g_xf_l[(size_t)4096 * KIN];
__device__ __nv_bfloat16 g_wiou_h[(size_t)NIOU * KIN];
__device__ __nv_bfloat16 g_wiou_l[(size_t)NIOU * KIN];
__device__ __nv_bfloat16 g_wf_h[(size_t)DD * KIN];
__device__ __nv_bfloat16 g_wf_l[(size_t)DD * KIN];
__device__ __nv_bfloat16 g_w012h[(size_t)YW * FD];
__device__ __nv_bfloat16 g_w012l[(size_t)YW * FD];

struct Job {
    const __nv_bfloat16 *Ah, *Al, *Bh, *Bl;
    float* C;
    int lda, ldb, ldc;
    size_t strideCz;
    int M, N, xt;
};

__device__ __forceinline__ float sigmoidf(float x) { return 1.0f / (1.0f + expf(-x)); }

__device__ __forceinline__ void split2(float v, __nv_bfloat16* hi, __nv_bfloat16* lo)
{
    __nv_bfloat16 h = __float2bfloat16(v);
    *hi = h;
    *lo = __float2bfloat16(v - __bfloat162float(h));
}

// pack 4 consecutive hi/lo bf16 from 4 floats into two uint2-able halves
__device__ __forceinline__ void split4(const float4 v, uint2* hi, uint2* lo)
{
    __nv_bfloat16 h0, l0, h1, l1, h2, l2, h3, l3;
    split2(v.x, &h0, &l0); split2(v.y, &h1, &l1);
    split2(v.z, &h2, &l2); split2(v.w, &h3, &l3);
    __nv_bfloat162 a = {h0, h1}, b = {h2, h3};
    __nv_bfloat162 c = {l0, l1}, d = {l2, l3};
    hi->x = *(uint32_t*)&a; hi->y = *(uint32_t*)&b;
    lo->x = *(uint32_t*)&c; lo->y = *(uint32_t*)&d;
}

__device__ __forceinline__ uint32_t smem_u32(const void* p)
{
    uint32_t a;
    asm("{ .reg .u64 t; cvta.to.shared.u64 t, %1; cvt.u32.u64 %0, t; }"
        : "=r"(a) : "l"(p));
    return a;
}

__device__ __forceinline__ void cp16(uint32_t dst, const void* src, bool v)
{
    int sz = v ? 16 : 0;   // zfill when guard fails
    asm volatile("cp.async.cg.shared.global [%0], [%1], 16, %2;"
                 :: "r"(dst), "l"(src), "r"(sz) : "memory");
}

__device__ __forceinline__ void ldm_x4a(uint32_t& r0, uint32_t& r1, uint32_t& r2, uint32_t& r3,
                                        uint32_t addr)
{
    asm volatile("ldmatrix.sync.aligned.m8n8.x4.shared.b16 {%0,%1,%2,%3}, [%4];"
                 : "=r"(r0), "=r"(r1), "=r"(r2), "=r"(r3) : "r"(addr));
}

__device__ __forceinline__ void mma_bf16(float* c, const uint32_t* a, const uint32_t* b)
{
    asm volatile("mma.sync.aligned.m16n8k16.row.col.f32.bf16.bf16.f32 "
                 "{%0,%1,%2,%3}, {%4,%5,%6,%7}, {%8,%9}, {%0,%1,%2,%3};"
                 : "+f"(c[0]), "+f"(c[1]), "+f"(c[2]), "+f"(c[3])
                 : "r"(a[0]), "r"(a[1]), "r"(a[2]), "r"(a[3]), "r"(b[0]), "r"(b[1]));
}

// ---------------- dual-job pipelined tensor GEMM ----------------------------
__global__ void __launch_bounds__(256, 2)
bmma2(Job j0, Job j1, int K)
{
    extern __shared__ __align__(16) __nv_bfloat16 sm[];  // [2][4][128][LDS]
    const uint32_t smbase = smem_u32(sm);
    const int bx = blockIdx.x;
    const bool is0 = bx < j0.xt;
    const Job j = is0 ? j0 : j1;
    const int rowBase = blockIdx.y * 128;
    if (rowBase >= j.M) return;
    const int colBase = (is0 ? bx : bx - j0.xt) * 128;

    const int tid = threadIdx.x;
    const int warp = tid >> 5, lane = tid & 31;
    const int wm = (warp & 1) * 64;
    const int wn = (warp >> 1) * 32;

    const int ktiles = K / BK;
    const int S = gridDim.z;
    const int kt0 = (int)(((long long)blockIdx.z * ktiles) / S);
    const int kt1 = (int)(((long long)(blockIdx.z + 1) * ktiles) / S);
    const int nch = kt1 - kt0;

    auto load_chunk = [&](int buf, int kt) {
        const int k0 = kt * BK;
        #pragma unroll
        for (int it2 = 0; it2 < 8; it2++) {
            const int plane = it2 >> 1;
            const int rem = (it2 & 1) ? (256 + tid) : tid;   // 0..511
            const int row = rem >> 2;
            const int kp = rem & 3;
            const __nv_bfloat16* g = (plane == 0) ? j.Ah : (plane == 1) ? j.Al
                                    : (plane == 2) ? j.Bh : j.Bl;
            const int ld  = (plane < 2) ? j.lda : j.ldb;
            const int rb  = (plane < 2) ? rowBase : colBase;
            const int lim = (plane < 2) ? j.M : j.N;
            const int grow = rb + row;
            const bool v = grow < lim;
            const char* src = (const char*)(g + (size_t)(v ? grow : 0) * ld + k0)
                              + kp * 16;
            uint32_t dst = smbase +
                (uint32_t)((((buf * 4 + plane) * 128 + row) * LDS + kp * 8) * 2);
            cp16(dst, src, v);
        }
        asm volatile("cp.async.commit_group;" ::: "memory");
    };

    float acc[4][4][4];
    #pragma unroll
    for (int a = 0; a < 4; a++)
        #pragma unroll
        for (int b = 0; b < 4; b++)
            #pragma unroll
            for (int d = 0; d < 4; d++) acc[a][b][d] = 0.0f;

    const int bg = lane >> 3;
    const int br = lane & 7;
    const int b_nt_off = (bg >> 1);
    const int b_kh = (bg & 1) * 8;

    if (nch > 0) load_chunk(0, kt0);

    for (int i = 0; i < nch; i++) {
        const int buf = i & 1;
        asm volatile("cp.async.wait_group 0;" ::: "memory");
        __syncthreads();
        if (i + 1 < nch) load_chunk(buf ^ 1, kt0 + i + 1);

        #pragma unroll
        for (int ks = 0; ks < 2; ks++) {
            uint32_t bfh[4][2], bfl[4][2];
            #pragma unroll
            for (int np = 0; np < 2; np++) {
                const int nr = wn + (np * 2 + b_nt_off) * 8 + br;
                const int kc = ks * 16 + b_kh;
                uint32_t ah = smbase +
                    (uint32_t)((((buf * 4 + 2) * 128 + nr) * LDS + kc) * 2);
                ldm_x4a(bfh[np*2][0], bfh[np*2][1], bfh[np*2+1][0], bfh[np*2+1][1], ah);
                uint32_t al = smbase +
                    (uint32_t)((((buf * 4 + 3) * 128 + nr) * LDS + kc) * 2);
                ldm_x4a(bfl[np*2][0], bfl[np*2][1], bfl[np*2+1][0], bfl[np*2+1][1], al);
            }
            const int ar = wm + (lane & 15);
            const int ac = ks * 16 + (lane >> 4) * 8;
            uint32_t af[4][4];
            #pragma unroll
            for (int mt = 0; mt < 4; mt++) {
                uint32_t ah = smbase +
                    (uint32_t)((((buf * 4 + 0) * 128 + ar + mt * 16) * LDS + ac) * 2);
                ldm_x4a(af[mt][0], af[mt][1], af[mt][2], af[mt][3], ah);
            }
            #pragma unroll
            for (int mt = 0; mt < 4; mt++)
                #pragma unroll
                for (int nt = 0; nt < 4; nt++)
                    mma_bf16(acc[mt][nt], af[mt], bfh[nt]);
            #pragma unroll
            for (int mt = 0; mt < 4; mt++)
                #pragma unroll
                for (int nt = 0; nt < 4; nt++)
                    mma_bf16(acc[mt][nt], af[mt], bfl[nt]);
            #pragma unroll
            for (int mt = 0; mt < 4; mt++) {
                uint32_t al = smbase +
                    (uint32_t)((((buf * 4 + 1) * 128 + ar + mt * 16) * LDS + ac) * 2);
                ldm_x4a(af[mt][0], af[mt][1], af[mt][2], af[mt][3], al);
            }
            #pragma unroll
            for (int mt = 0; mt < 4; mt++)
                #pragma unroll
                for (int nt = 0; nt < 4; nt++)
                    mma_bf16(acc[mt][nt], af[mt], bfh[nt]);
        }
    }

    float* Cz = j.C + (size_t)blockIdx.z * j.strideCz;
    #pragma unroll
    for (int mt = 0; mt < 4; mt++) {
        int r0 = rowBase + wm + mt * 16 + (lane >> 2);
        #pragma unroll
        for (int nt = 0; nt < 4; nt++) {
            int c = colBase + wn + nt * 8 + (lane & 3) * 2;
            if (c < j.N) {
                if (r0 < j.M) {
                    Cz[(size_t)r0 * j.ldc + c]     = acc[mt][nt][0];
                    Cz[(size_t)r0 * j.ldc + c + 1] = acc[mt][nt][1];
                }
                if (r0 + 8 < j.M) {
                    Cz[(size_t)(r0 + 8) * j.ldc + c]     = acc[mt][nt][2];
                    Cz[(size_t)(r0 + 8) * j.ldc + c + 1] = acc[mt][nt][3];
                }
            }
        }
    }
}

// ---------------- conv front-end --------------------------------------------
__global__ void conv_kernel(const float* __restrict__ x,
                            const float* __restrict__ idd,
                            const float* __restrict__ cw, const float* __restrict__ cb,
                            const float* __restrict__ lw, const float* __restrict__ lb)
{
    __shared__ float xs[SNPX];
    __shared__ float pwi[200];
    __shared__ float pwl[200];
    const int n = blockIdx.x;
    const float* xr = x + (size_t)n * SNPX;
    for (int i = threadIdx.x; i < SNPX / 4; i += blockDim.x)
        ((float4*)xs)[i] = ((const float4*)xr)[i];
    if (threadIdx.x < 200) {
        int co = threadIdx.x / 25, off = threadIdx.x % 25;
        int widx = co * 25 + (off % 5) * 5 + (off / 5);
        pwi[threadIdx.x] = cw[widx];
        pwl[threadIdx.x] = lw[widx];
    }
    if (threadIdx.x >= 224) {
        int j = threadIdx.x - 224;
        split2(idd[(size_t)n * IDDIM + j],
               &g_fb_h[(size_t)n * FD + 3200 + j], &g_fb_l[(size_t)n * FD + 3200 + j]);
    }
    __syncthreads();

    const bool leaf = (n >= NINT);
    const int t = threadIdx.x;
    if (t < 200) {
        const float* xp = &xs[25 * t];
        #pragma unroll
        for (int co = 0; co < 8; co++) {
            float acc = cb[co];
            #pragma unroll
            for (int off = 0; off < 25; off++) acc += xp[off] * pwi[co * 25 + off];
            acc = fmaxf(acc, 0.0f);
            size_t o = (size_t)n * FD + co * 200 + t;
            split2(acc, &g_fb_h[o], &g_fb_l[o]);
        }
        if (leaf) {
            #pragma unroll
            for (int co = 0; co < 8; co++) {
                float acc = lb[co];
                #pragma unroll
                for (int off = 0; off < 25; off++) acc += xp[off] * pwl[co * 25 + off];
                acc = fmaxf(acc, 0.0f);
                g_h[(size_t)n * DD + co * 200 + t] = acc;
                size_t o = (size_t)n * FD + DD + co * 200 + t;
                split2(acc, &g_fb_h[o], &g_fb_l[o]);
            }
        }
    }
}

// ---------------- all weight prep in ONE kernel -----------------------------
__global__ void prep_weights(const float* __restrict__ Wi, const float* __restrict__ Wo,
                             const float* __restrict__ Wu, const float* __restrict__ Wf,
                             const float* __restrict__ fc0_w)
{
    const int WN = DD * KIN;
    int i = blockIdx.x * blockDim.x + threadIdx.x;
    if (i < 4 * WN) {
        int which = i / WN, r = i % WN;
        const float* src = (which == 0) ? Wi : (which == 1) ? Wo : (which == 2) ? Wu : Wf;
        float v = src[r];
        if (which < 3)
            split2(v, &g_wiou_h[(size_t)which * WN + r], &g_wiou_l[(size_t)which * WN + r]);
        else
            split2(v, &g_wf_h[r], &g_wf_l[r]);
    } else {
        int idx = i - 4 * WN;
        if (idx >= YW * FD) return;
        int r = idx / FD, k = idx % FD;
        float v = fc0_w[(size_t)(r & 63) * (3 * FD) + (size_t)(r >> 6) * FD + k];
        split2(v, &g_w012h[idx], &g_w012l[idx]);
    }
}

// ---------------- initial build (depth-11 parents): xiou ONLY ---------------
__global__ void build_xin(int start, const float* __restrict__ idd)
{
    const int t = blockIdx.x;
    const int p = start + t;
    const int l = 2 * p + 1, r = 2 * p + 2;
    const float4* hl4 = (const float4*)&g_h[(size_t)l * DD];
    const float4* hr4 = (const float4*)&g_h[(size_t)r * DD];
    const size_t oiou = (size_t)t * KIN;
    for (int j = threadIdx.x; j < IDDIM; j += blockDim.x) {
        float v = idd[(size_t)p * IDDIM + j];
        __nv_bfloat16 h, lo2;
        split2(v, &h, &lo2);
        g_xiou_h[oiou + j] = h; g_xiou_l[oiou + j] = lo2;
    }
    for (int j4 = threadIdx.x; j4 < DD / 4; j4 += blockDim.x) {
        float4 a = hl4[j4], b = hr4[j4];
        float4 s = make_float4(a.x + b.x, a.y + b.y, a.z + b.z, a.w + b.w);
        uint2 hi, lo;
        split4(s, &hi, &lo);
        *(uint2*)&g_xiou_h[oiou + IDDIM + j4 * 4] = hi;
        *(uint2*)&g_xiou_l[oiou + IDDIM + j4 * 4] = lo;
    }
}

// ---------------- fused combine: sibling pair + writes parent xin -----------
__global__ void lstm_combine2(int start, int m, int S, int writeNext, int noF,
                              const float* __restrict__ bi, const float* __restrict__ bf,
                              const float* __restrict__ bu, const float* __restrict__ bo,
                              const float* __restrict__ idd)
{
    const int t = blockIdx.x;
    const int two = (m >= 2);
    const int p0 = start + 2 * t;
    const int p1 = p0 + 1;
    const int q  = (p0 - 1) >> 1;
    const size_t oiou = (size_t)t * KIN;
    const size_t ofl  = (size_t)(2 * t) * KIN;
    const size_t ofr  = (size_t)(2 * t + 1) * KIN;

    if (writeNext) {
        for (int j = threadIdx.x; j < IDDIM; j += blockDim.x) {
            float v = idd[(size_t)q * IDDIM + j];
            __nv_bfloat16 h, lo2;
            split2(v, &h, &lo2);
            g_xiou_h[oiou + j] = h; g_xiou_l[oiou + j] = lo2;
            g_xf_h[ofl + j] = h;    g_xf_l[ofl + j] = lo2;
            g_xf_h[ofr + j] = h;    g_xf_l[ofr + j] = lo2;
        }
    }

    for (int j4 = threadIdx.x; j4 < DD / 4; j4 += blockDim.x) {
        const int j = j4 * 4;
        const float4 vbi = *(const float4*)&bi[j];
        const float4 vbf = *(const float4*)&bf[j];
        const float4 vbu = *(const float4*)&bu[j];
        const float4 vbo = *(const float4*)&bo[j];
        float4 h4[2];
        #pragma unroll
        for (int s = 0; s < 2; s++) {
            if (s == 1 && !two) { h4[1] = make_float4(0.f, 0.f, 0.f, 0.f); break; }
            const int p = (s == 0) ? p0 : p1;
            const int loc = 2 * t + s;
            float4 si = make_float4(0.f, 0.f, 0.f, 0.f), so = si, su = si,
                   sfl = si, sfr = si;
            for (int z = 0; z < S; z++) {
                const float* piou = &g_pre_iou[((size_t)z * m + loc) * NIOU];
                float4 a = *(const float4*)&piou[j];
                float4 b = *(const float4*)&piou[DD + j];
                float4 cc = *(const float4*)&piou[2 * DD + j];
                si.x += a.x; si.y += a.y; si.z += a.z; si.w += a.w;
                so.x += b.x; so.y += b.y; so.z += b.z; so.w += b.w;
                su.x += cc.x; su.y += cc.y; su.z += cc.z; su.w += cc.w;
                if (!noF) {
                    const float* pf = &g_pre_f[(size_t)z * 2 * m * DD];
                    float4 d = *(const float4*)&pf[(size_t)(2 * loc) * DD + j];
                    float4 e = *(const float4*)&pf[(size_t)(2 * loc + 1) * DD + j];
                    sfl.x += d.x; sfl.y += d.y; sfl.z += d.z; sfl.w += d.w;
                    sfr.x += e.x; sfr.y += e.y; sfr.z += e.z; sfr.w += e.w;
                }
            }
            float4 cl = make_float4(0.f, 0.f, 0.f, 0.f), cr = cl;
            if (!noF) {
                const int l = 2 * p + 1, r = 2 * p + 2;
                cl = *(const float4*)&g_c[(size_t)l * DD + j];
                cr = *(const float4*)&g_c[(size_t)r * DD + j];
            }
            float4 cn, hn;
            {
                float vi, vo, vu, fl, fr;
                vi = sigmoidf(si.x + vbi.x); vo = sigmoidf(so.x + vbo.x);
                vu = tanhf(su.x + vbu.x);
                fl = noF ? 0.f : sigmoidf(sfl.x + vbf.x);
                fr = noF ? 0.f : sigmoidf(sfr.x + vbf.x);
                cn.x = vi * vu + fl * cl.x + fr * cr.x; hn.x = vo * tanhf(cn.x);
                vi = sigmoidf(si.y + vbi.y); vo = sigmoidf(so.y + vbo.y);
                vu = tanhf(su.y + vbu.y);
                fl = noF ? 0.f : sigmoidf(sfl.y + vbf.y);
                fr = noF ? 0.f : sigmoidf(sfr.y + vbf.y);
                cn.y = vi * vu + fl * cl.y + fr * cr.y; hn.y = vo * tanhf(cn.y);
                vi = sigmoidf(si.z + vbi.z); vo = sigmoidf(so.z + vbo.z);
                vu = tanhf(su.z + vbu.z);
                fl = noF ? 0.f : sigmoidf(sfl.z + vbf.z);
                fr = noF ? 0.f : sigmoidf(sfr.z + vbf.z);
                cn.z = vi * vu + fl * cl.z + fr * cr.z; hn.z = vo * tanhf(cn.z);
                vi = sigmoidf(si.w + vbi.w); vo = sigmoidf(so.w + vbo.w);
                vu = tanhf(su.w + vbu.w);
                fl = noF ? 0.f : sigmoidf(sfl.w + vbf.w);
                fr = noF ? 0.f : sigmoidf(sfr.w + vbf.w);
                cn.w = vi * vu + fl * cl.w + fr * cr.w; hn.w = vo * tanhf(cn.w);
            }
            *(float4*)&g_c[(size_t)p * DD + j] = cn;
            uint2 hi, lo;
            split4(hn, &hi, &lo);
            *(uint2*)&g_fb_h[(size_t)p * FD + DD + j] = hi;
            *(uint2*)&g_fb_l[(size_t)p * FD + DD + j] = lo;
            h4[s] = hn;
        }
        if (writeNext) {
            uint2 hi, lo;
            float4 sum = make_float4(h4[0].x + h4[1].x, h4[0].y + h4[1].y,
                                     h4[0].z + h4[1].z, h4[0].w + h4[1].w);
            split4(sum, &hi, &lo);
            *(uint2*)&g_xiou_h[oiou + IDDIM + j] = hi;
            *(uint2*)&g_xiou_l[oiou + IDDIM + j] = lo;
            split4(h4[0], &hi, &lo);
            *(uint2*)&g_xf_h[ofl + IDDIM + j] = hi;
            *(uint2*)&g_xf_l[ofl + IDDIM + j] = lo;
            split4(h4[1], &hi, &lo);
            *(uint2*)&g_xf_h[ofr + IDDIM + j] = hi;
            *(uint2*)&g_xf_l[ofr + IDDIM + j] = lo;
        }
    }
}

// ---------------- head: 4 nodes per 256-thread block ------------------------
__device__ __forceinline__ float ysum(int node, int col)
{
    float s = 0.f;
    #pragma unroll
    for (int z = 0; z < SFC0; z++)
        s += g_y[((size_t)z * NN + node) * YW + col];
    return s;
}

__global__ void head_kernel(const float* __restrict__ fc0_b,
                            const float* __restrict__ fc1_w, const float* __restrict__ fc1_b,
                            const float* __restrict__ fc2_w, const float* __restrict__ fc2_b,
                            float* __restrict__ out)
{
    __shared__ float z[4][64];
    __shared__ float partial[4][2];
    const int sub = threadIdx.x >> 6;     // 0..3
    const int j = threadIdx.x & 63;
    const int n = blockIdx.x * 4 + sub;
    const bool valid = (n < NN);

    float acc = 0.0f;
    if (valid) {
        acc = fc0_b[j] + ysum(n, j);
        if (n > 0) acc += ysum((n - 1) >> 1, 64 + j);
        if (n < NINT)
            acc += 0.5f * (ysum(2 * n + 1, 128 + j) + ysum(2 * n + 2, 128 + j));
    }
    z[sub][j] = fmaxf(acc, 0.0f);
    __syncthreads();

    float a1 = fc1_b[j];
    #pragma unroll 8
    for (int k = 0; k < 64; k++) a1 += fc1_w[j * 64 + k] * z[sub][k];
    float z1 = fmaxf(a1, 0.0f);

    float v = fc2_w[j] * z1;
    #pragma unroll
    for (int off = 16; off > 0; off >>= 1) v += __shfl_down_sync(0xffffffffu, v, off);
    if ((j & 31) == 0) partial[sub][j >> 5] = v;
    __syncthreads();
    if (j == 0 && valid) out[n] = partial[sub][0] + partial[sub][1] + fc2_b[0];
}

// ---------------- launch ----------------------------------------------------
extern "C" void kernel_launch(void* const* d_in, const int* in_sizes, int n_in,
                              void* d_out, int out_size)
{
    const float* x      = (const float*)d_in[0];
    const float* idd    = (const float*)d_in[1];
    const float* conv_w  = (const float*)d_in[4];
    const float* conv_b  = (const float*)d_in[5];
    const float* convl_w = (const float*)d_in[6];
    const float* convl_b = (const float*)d_in[7];
    const float* Wi = (const float*)d_in[8];   const float* bi = (const float*)d_in[9];
    const float* Wf = (const float*)d_in[10];  const float* bf = (const float*)d_in[11];
    const float* Wu = (const float*)d_in[12];  const float* bu = (const float*)d_in[13];
    const float* Wo = (const float*)d_in[14];  const float* bo = (const float*)d_in[15];
    const float* fc0_w = (const float*)d_in[16]; const float* fc0_b = (const float*)d_in[17];
    const float* fc1_w = (const float*)d_in[18]; const float* fc1_b = (const float*)d_in[19];
    const float* fc2_w = (const float*)d_in[20]; const float* fc2_b = (const float*)d_in[21];
    float* out = (float*)d_out;

    float *p_pre_iou, *p_pre_f, *p_y;
    __nv_bfloat16 *p_xiou_h, *p_xiou_l, *p_xf_h, *p_xf_l;
    __nv_bfloat16 *p_wiou_h, *p_wiou_l, *p_wf_h, *p_wf_l;
    __nv_bfloat16 *p_fb_h, *p_fb_l, *p_w012h, *p_w012l;
    cudaGetSymbolAddress((void**)&p_pre_iou, g_pre_iou);
    cudaGetSymbolAddress((void**)&p_pre_f,   g_pre_f);
    cudaGetSymbolAddress((void**)&p_y,       g_y);
    cudaGetSymbolAddress((void**)&p_xiou_h,  g_xiou_h);
    cudaGetSymbolAddress((void**)&p_xiou_l,  g_xiou_l);
    cudaGetSymbolAddress((void**)&p_xf_h,    g_xf_h);
    cudaGetSymbolAddress((void**)&p_xf_l,    g_xf_l);
    cudaGetSymbolAddress((void**)&p_wiou_h,  g_wiou_h);
    cudaGetSymbolAddress((void**)&p_wiou_l,  g_wiou_l);
    cudaGetSymbolAddress((void**)&p_wf_h,    g_wf_h);
    cudaGetSymbolAddress((void**)&p_wf_l,    g_wf_l);
    cudaGetSymbolAddress((void**)&p_fb_h,    g_fb_h);
    cudaGetSymbolAddress((void**)&p_fb_l,    g_fb_l);
    cudaGetSymbolAddress((void**)&p_w012h,   g_w012h);
    cudaGetSymbolAddress((void**)&p_w012l,   g_w012l);

    cudaFuncSetAttribute(bmma2, cudaFuncAttributeMaxDynamicSharedMemorySize, BSM);

    // 0) split + pack all weights (one launch)
    const int prepN = 4 * DD * KIN + YW * FD;
    prep_weights<<<(prepN + 255) / 256, 256>>>(Wi, Wo, Wu, Wf, fc0_w);

    // 1) conv front-end
    conv_kernel<<<NN, 256>>>(x, idd, conv_w, conv_b, convl_w, convl_b);

    // 2) initial xiou build for depth-11 parents
    build_xin<<<2048, 256>>>(2047, idd);

    // 3) bottom-up tree LSTM
    for (int depth = 11; depth >= 0; depth--) {
        int m = 1 << depth;
        int start = m - 1;
        int S = (m >= 2048) ? 2 : (m == 1024) ? 2 : (m == 512) ? 4 : (m == 256) ? 8 : 16;
        Job jiou = { p_xiou_h, p_xiou_l, p_wiou_h, p_wiou_l, p_pre_iou,
                     KIN, KIN, NIOU, (size_t)m * NIOU, m, NIOU, XT_IOU };
        if (depth == 11) {
            Job jnull = jiou; jnull.xt = 0;
            dim3 g(XT_IOU, (m + 127) / 128, S);
            bmma2<<<g, 256, BSM>>>(jiou, jnull, KIN);
        } else {
            Job jf = { p_xf_h, p_xf_l, p_wf_h, p_wf_l, p_pre_f,
                       KIN, KIN, DD, (size_t)2 * m * DD, 2 * m, DD, XT_F };
            dim3 g(XT_IOU + XT_F, (2 * m + 127) / 128, S);
            bmma2<<<g, 256, BSM>>>(jiou, jf, KIN);
        }
        int blocks = (m >= 2) ? m / 2 : 1;
        lstm_combine2<<<blocks, 256>>>(start, m, S, depth > 0 ? 1 : 0,
                                       depth == 11 ? 1 : 0,
                                       bi, bf, bu, bo, idd);
    }

    // 4) fused fc0 with split-K=2 (256 blocks = exactly one wave)
    Job jfc0 = { p_fb_h, p_fb_l, p_w012h, p_w012l, p_y,
                 FD, FD, YW, (size_t)NN * YW, NN, YW, 2 };
    Job jnull = jfc0; jnull.xt = 0;
    dim3 g3(2, (NN + 127) / 128, SFC0);
    bmma2<<<g3, 256, BSM>>>(jfc0, jnull, FD);

    // 5) fusion combine + fc1 + fc2 (4 nodes per block)
    head_kernel<<<(NN + 3) / 4, 256>>>(fc0_b, fc1_w, fc1_b, fc2_w, fc2_b, out);
}

// round 15
// speedup vs baseline: 1.3631x; 1.0206x over previous
#include <cuda_runtime.h>
#include <cuda_bf16.h>
#include <math.h>
#include <stdint.h>

// ---------------- problem constants ----------------
#define NN     8191
#define NINT   4095
#define SNPX   5000
#define DD     1600
#define IDDIM  32
#define KIN    1632        // DD + IDDIM (mult of 32)
#define FD     3232        // 2*DD + IDDIM (mult of 32)
#define YW     192         // 3 * 64 fc0 pieces
#define NIOU   4800        // 3 * DD
#define SFC0   2
#define BK     32          // K per pipeline chunk
#define LDS    40          // smem row stride (bf16), 32 data + 8 pad
#define BSM    (2 * 4 * 128 * LDS * 2)   // dynamic smem for bmma2 (80KB)
#define XT_IOU 38          // ceil(4800/128)
#define XT_F   13          // ceil(1600/128)

// ---------------- scratch ----------------
__device__ float g_h[(size_t)NN * DD];           // only leaves consumed
__device__ float g_c[(size_t)NN * DD];           // leaves never touched (zero by math)
__device__ float g_pre_iou[(size_t)4096 * NIOU]; // S*m <= 4096 partial rows
__device__ float g_pre_f[(size_t)4096 * DD];     // S*2m <= 4096 partial rows
__device__ float g_y[(size_t)SFC0 * NN * YW];

__device__ __nv_bfloat16 g_fb_h[(size_t)NN * FD];
__device__ __nv_bfloat16 g_fb_l[(size_t)NN * FD];
__device__ __nv_bfloat16 g_xiou_h[(size_t)2048 * KIN];
__device__ __nv_bfloat16 g_xiou_l[(size_t)2048 * KIN];
__device__ __nv_bfloat16 g_xf_h[(size_t)4096 * KIN];
__device__ __nv_bfloat16 g_xf_l[(size_t)4096 * KIN];
__device__ __nv_bfloat16 g_wiou_h[(size_t)NIOU * KIN];
__device__ __nv_bfloat16 g_wiou_l[(size_t)NIOU * KIN];
__device__ __nv_bfloat16 g_wf_h[(size_t)DD * KIN];
__device__ __nv_bfloat16 g_wf_l[(size_t)DD * KIN];
__device__ __nv_bfloat16 g_w012h[(size_t)YW * FD];
__device__ __nv_bfloat16 g_w012l[(size_t)YW * FD];

struct Job {
    const __nv_bfloat16 *Ah, *Al, *Bh, *Bl;
    float* C;
    int lda, ldb, ldc;
    size_t strideCz;
    int M, N, xt;
};

__device__ __forceinline__ float sigmoidf(float x) { return 1.0f / (1.0f + expf(-x)); }

__device__ __forceinline__ void split2(float v, __nv_bfloat16* hi, __nv_bfloat16* lo)
{
    __nv_bfloat16 h = __float2bfloat16(v);
    *hi = h;
    *lo = __float2bfloat16(v - __bfloat162float(h));
}

// pack 4 consecutive hi/lo bf16 from 4 floats into two uint2-able halves
__device__ __forceinline__ void split4(const float4 v, uint2* hi, uint2* lo)
{
    __nv_bfloat16 h0, l0, h1, l1, h2, l2, h3, l3;
    split2(v.x, &h0, &l0); split2(v.y, &h1, &l1);
    split2(v.z, &h2, &l2); split2(v.w, &h3, &l3);
    __nv_bfloat162 a = {h0, h1}, b = {h2, h3};
    __nv_bfloat162 c = {l0, l1}, d = {l2, l3};
    hi->x = *(uint32_t*)&a; hi->y = *(uint32_t*)&b;
    lo->x = *(uint32_t*)&c; lo->y = *(uint32_t*)&d;
}

__device__ __forceinline__ uint32_t smem_u32(const void* p)
{
    uint32_t a;
    asm("{ .reg .u64 t; cvta.to.shared.u64 t, %1; cvt.u32.u64 %0, t; }"
        : "=r"(a) : "l"(p));
    return a;
}

__device__ __forceinline__ void cp16(uint32_t dst, const void* src, bool v)
{
    int sz = v ? 16 : 0;   // zfill when guard fails
    asm volatile("cp.async.cg.shared.global [%0], [%1], 16, %2;"
                 :: "r"(dst), "l"(src), "r"(sz) : "memory");
}

__device__ __forceinline__ void ldm_x4a(uint32_t& r0, uint32_t& r1, uint32_t& r2, uint32_t& r3,
                                        uint32_t addr)
{
    asm volatile("ldmatrix.sync.aligned.m8n8.x4.shared.b16 {%0,%1,%2,%3}, [%4];"
                 : "=r"(r0), "=r"(r1), "=r"(r2), "=r"(r3) : "r"(addr));
}

__device__ __forceinline__ void mma_bf16(float* c, const uint32_t* a, const uint32_t* b)
{
    asm volatile("mma.sync.aligned.m16n8k16.row.col.f32.bf16.bf16.f32 "
                 "{%0,%1,%2,%3}, {%4,%5,%6,%7}, {%8,%9}, {%0,%1,%2,%3};"
                 : "+f"(c[0]), "+f"(c[1]), "+f"(c[2]), "+f"(c[3])
                 : "r"(a[0]), "r"(a[1]), "r"(a[2]), "r"(a[3]), "r"(b[0]), "r"(b[1]));
}

// ---------------- dual-job pipelined tensor GEMM ----------------------------
__global__ void __launch_bounds__(256, 2)
bmma2(Job j0, Job j1, int K)
{
    extern __shared__ __align__(16) __nv_bfloat16 sm[];  // [2][4][128][LDS]
    const uint32_t smbase = smem_u32(sm);
    const int bx = blockIdx.x;
    const bool is0 = bx < j0.xt;
    const Job j = is0 ? j0 : j1;
    const int rowBase = blockIdx.y * 128;
    if (rowBase >= j.M) return;
    const int colBase = (is0 ? bx : bx - j0.xt) * 128;

    const int tid = threadIdx.x;
    const int warp = tid >> 5, lane = tid & 31;
    const int wm = (warp & 1) * 64;
    const int wn = (warp >> 1) * 32;

    const int ktiles = K / BK;
    const int S = gridDim.z;
    const int kt0 = (int)(((long long)blockIdx.z * ktiles) / S);
    const int kt1 = (int)(((long long)(blockIdx.z + 1) * ktiles) / S);
    const int nch = kt1 - kt0;

    auto load_chunk = [&](int buf, int kt) {
        const int k0 = kt * BK;
        #pragma unroll
        for (int it2 = 0; it2 < 8; it2++) {
            const int plane = it2 >> 1;
            const int rem = (it2 & 1) ? (256 + tid) : tid;   // 0..511
            const int row = rem >> 2;
            const int kp = rem & 3;
            const __nv_bfloat16* g = (plane == 0) ? j.Ah : (plane == 1) ? j.Al
                                    : (plane == 2) ? j.Bh : j.Bl;
            const int ld  = (plane < 2) ? j.lda : j.ldb;
            const int rb  = (plane < 2) ? rowBase : colBase;
            const int lim = (plane < 2) ? j.M : j.N;
            const int grow = rb + row;
            const bool v = grow < lim;
            const char* src = (const char*)(g + (size_t)(v ? grow : 0) * ld + k0)
                              + kp * 16;
            uint32_t dst = smbase +
                (uint32_t)((((buf * 4 + plane) * 128 + row) * LDS + kp * 8) * 2);
            cp16(dst, src, v);
        }
        asm volatile("cp.async.commit_group;" ::: "memory");
    };

    float acc[4][4][4];
    #pragma unroll
    for (int a = 0; a < 4; a++)
        #pragma unroll
        for (int b = 0; b < 4; b++)
            #pragma unroll
            for (int d = 0; d < 4; d++) acc[a][b][d] = 0.0f;

    const int bg = lane >> 3;
    const int br = lane & 7;
    const int b_nt_off = (bg >> 1);
    const int b_kh = (bg & 1) * 8;

    if (nch > 0) load_chunk(0, kt0);

    for (int i = 0; i < nch; i++) {
        const int buf = i & 1;
        asm volatile("cp.async.wait_group 0;" ::: "memory");
        __syncthreads();
        if (i + 1 < nch) load_chunk(buf ^ 1, kt0 + i + 1);

        #pragma unroll
        for (int ks = 0; ks < 2; ks++) {
            uint32_t bfh[4][2], bfl[4][2];
            #pragma unroll
            for (int np = 0; np < 2; np++) {
                const int nr = wn + (np * 2 + b_nt_off) * 8 + br;
                const int kc = ks * 16 + b_kh;
                uint32_t ah = smbase +
                    (uint32_t)((((buf * 4 + 2) * 128 + nr) * LDS + kc) * 2);
                ldm_x4a(bfh[np*2][0], bfh[np*2][1], bfh[np*2+1][0], bfh[np*2+1][1], ah);
                uint32_t al = smbase +
                    (uint32_t)((((buf * 4 + 3) * 128 + nr) * LDS + kc) * 2);
                ldm_x4a(bfl[np*2][0], bfl[np*2][1], bfl[np*2+1][0], bfl[np*2+1][1], al);
            }
            const int ar = wm + (lane & 15);
            const int ac = ks * 16 + (lane >> 4) * 8;
            uint32_t af[4][4];
            #pragma unroll
            for (int mt = 0; mt < 4; mt++) {
                uint32_t ah = smbase +
                    (uint32_t)((((buf * 4 + 0) * 128 + ar + mt * 16) * LDS + ac) * 2);
                ldm_x4a(af[mt][0], af[mt][1], af[mt][2], af[mt][3], ah);
            }
            #pragma unroll
            for (int mt = 0; mt < 4; mt++)
                #pragma unroll
                for (int nt = 0; nt < 4; nt++)
                    mma_bf16(acc[mt][nt], af[mt], bfh[nt]);
            #pragma unroll
            for (int mt = 0; mt < 4; mt++)
                #pragma unroll
                for (int nt = 0; nt < 4; nt++)
                    mma_bf16(acc[mt][nt], af[mt], bfl[nt]);
            #pragma unroll
            for (int mt = 0; mt < 4; mt++) {
                uint32_t al = smbase +
                    (uint32_t)((((buf * 4 + 1) * 128 + ar + mt * 16) * LDS + ac) * 2);
                ldm_x4a(af[mt][0], af[mt][1], af[mt][2], af[mt][3], al);
            }
            #pragma unroll
            for (int mt = 0; mt < 4; mt++)
                #pragma unroll
                for (int nt = 0; nt < 4; nt++)
                    mma_bf16(acc[mt][nt], af[mt], bfh[nt]);
        }
    }

    float* Cz = j.C + (size_t)blockIdx.z * j.strideCz;
    #pragma unroll
    for (int mt = 0; mt < 4; mt++) {
        int r0 = rowBase + wm + mt * 16 + (lane >> 2);
        #pragma unroll
        for (int nt = 0; nt < 4; nt++) {
            int c = colBase + wn + nt * 8 + (lane & 3) * 2;
            if (c < j.N) {
                if (r0 < j.M) {
                    Cz[(size_t)r0 * j.ldc + c]     = acc[mt][nt][0];
                    Cz[(size_t)r0 * j.ldc + c + 1] = acc[mt][nt][1];
                }
                if (r0 + 8 < j.M) {
                    Cz[(size_t)(r0 + 8) * j.ldc + c]     = acc[mt][nt][2];
                    Cz[(size_t)(r0 + 8) * j.ldc + c + 1] = acc[mt][nt][3];
                }
            }
        }
    }
}

// ---------------- conv front-end --------------------------------------------
__global__ void conv_kernel(const float* __restrict__ x,
                            const float* __restrict__ idd,
                            const float* __restrict__ cw, const float* __restrict__ cb,
                            const float* __restrict__ lw, const float* __restrict__ lb)
{
    __shared__ float xs[SNPX];
    __shared__ float pwi[200];
    __shared__ float pwl[200];
    const int n = blockIdx.x;
    const float* xr = x + (size_t)n * SNPX;
    for (int i = threadIdx.x; i < SNPX / 4; i += blockDim.x)
        ((float4*)xs)[i] = ((const float4*)xr)[i];
    if (threadIdx.x < 200) {
        int co = threadIdx.x / 25, off = threadIdx.x % 25;
        int widx = co * 25 + (off % 5) * 5 + (off / 5);
        pwi[threadIdx.x] = cw[widx];
        pwl[threadIdx.x] = lw[widx];
    }
    if (threadIdx.x >= 224) {
        int j = threadIdx.x - 224;
        split2(idd[(size_t)n * IDDIM + j],
               &g_fb_h[(size_t)n * FD + 3200 + j], &g_fb_l[(size_t)n * FD + 3200 + j]);
    }
    __syncthreads();

    const bool leaf = (n >= NINT);
    const int t = threadIdx.x;
    if (t < 200) {
        const float* xp = &xs[25 * t];
        #pragma unroll
        for (int co = 0; co < 8; co++) {
            float acc = cb[co];
            #pragma unroll
            for (int off = 0; off < 25; off++) acc += xp[off] * pwi[co * 25 + off];
            acc = fmaxf(acc, 0.0f);
            size_t o = (size_t)n * FD + co * 200 + t;
            split2(acc, &g_fb_h[o], &g_fb_l[o]);
        }
        if (leaf) {
            #pragma unroll
            for (int co = 0; co < 8; co++) {
                float acc = lb[co];
                #pragma unroll
                for (int off = 0; off < 25; off++) acc += xp[off] * pwl[co * 25 + off];
                acc = fmaxf(acc, 0.0f);
                g_h[(size_t)n * DD + co * 200 + t] = acc;
                size_t o = (size_t)n * FD + DD + co * 200 + t;
                split2(acc, &g_fb_h[o], &g_fb_l[o]);
            }
        }
    }
}

// ---------------- all weight prep in ONE kernel -----------------------------
__global__ void prep_weights(const float* __restrict__ Wi, const float* __restrict__ Wo,
                             const float* __restrict__ Wu, const float* __restrict__ Wf,
                             const float* __restrict__ fc0_w)
{
    const int WN = DD * KIN;
    int i = blockIdx.x * blockDim.x + threadIdx.x;
    if (i < 4 * WN) {
        int which = i / WN, r = i % WN;
        const float* src = (which == 0) ? Wi : (which == 1) ? Wo : (which == 2) ? Wu : Wf;
        float v = src[r];
        if (which < 3)
            split2(v, &g_wiou_h[(size_t)which * WN + r], &g_wiou_l[(size_t)which * WN + r]);
        else
            split2(v, &g_wf_h[r], &g_wf_l[r]);
    } else {
        int idx = i - 4 * WN;
        if (idx >= YW * FD) return;
        int r = idx / FD, k = idx % FD;
        float v = fc0_w[(size_t)(r & 63) * (3 * FD) + (size_t)(r >> 6) * FD + k];
        split2(v, &g_w012h[idx], &g_w012l[idx]);
    }
}

// ---------------- initial build (depth-11 parents): xiou ONLY ---------------
__global__ void build_xin(int start, const float* __restrict__ idd)
{
    const int t = blockIdx.x;
    const int p = start + t;
    const int l = 2 * p + 1, r = 2 * p + 2;
    const float4* hl4 = (const float4*)&g_h[(size_t)l * DD];
    const float4* hr4 = (const float4*)&g_h[(size_t)r * DD];
    const size_t oiou = (size_t)t * KIN;
    for (int j = threadIdx.x; j < IDDIM; j += blockDim.x) {
        float v = idd[(size_t)p * IDDIM + j];
        __nv_bfloat16 h, lo2;
        split2(v, &h, &lo2);
        g_xiou_h[oiou + j] = h; g_xiou_l[oiou + j] = lo2;
    }
    for (int j4 = threadIdx.x; j4 < DD / 4; j4 += blockDim.x) {
        float4 a = hl4[j4], b = hr4[j4];
        float4 s = make_float4(a.x + b.x, a.y + b.y, a.z + b.z, a.w + b.w);
        uint2 hi, lo;
        split4(s, &hi, &lo);
        *(uint2*)&g_xiou_h[oiou + IDDIM + j4 * 4] = hi;
        *(uint2*)&g_xiou_l[oiou + IDDIM + j4 * 4] = lo;
    }
}

// ---------------- fused combine: sibling pair + writes parent xin -----------
__global__ void lstm_combine2(int start, int m, int S, int writeNext, int noF,
                              const float* __restrict__ bi, const float* __restrict__ bf,
                              const float* __restrict__ bu, const float* __restrict__ bo,
                              const float* __restrict__ idd)
{
    const int t = blockIdx.x;
    const int two = (m >= 2);
    const int p0 = start + 2 * t;
    const int p1 = p0 + 1;
    const int q  = (p0 - 1) >> 1;
    const size_t oiou = (size_t)t * KIN;
    const size_t ofl  = (size_t)(2 * t) * KIN;
    const size_t ofr  = (size_t)(2 * t + 1) * KIN;

    if (writeNext) {
        for (int j = threadIdx.x; j < IDDIM; j += blockDim.x) {
            float v = idd[(size_t)q * IDDIM + j];
            __nv_bfloat16 h, lo2;
            split2(v, &h, &lo2);
            g_xiou_h[oiou + j] = h; g_xiou_l[oiou + j] = lo2;
            g_xf_h[ofl + j] = h;    g_xf_l[ofl + j] = lo2;
            g_xf_h[ofr + j] = h;    g_xf_l[ofr + j] = lo2;
        }
    }

    for (int j4 = threadIdx.x; j4 < DD / 4; j4 += blockDim.x) {
        const int j = j4 * 4;
        const float4 vbi = *(const float4*)&bi[j];
        const float4 vbf = *(const float4*)&bf[j];
        const float4 vbu = *(const float4*)&bu[j];
        const float4 vbo = *(const float4*)&bo[j];
        float4 h4[2];
        #pragma unroll
        for (int s = 0; s < 2; s++) {
            if (s == 1 && !two) { h4[1] = make_float4(0.f, 0.f, 0.f, 0.f); break; }
            const int p = (s == 0) ? p0 : p1;
            const int loc = 2 * t + s;
            float4 si = make_float4(0.f, 0.f, 0.f, 0.f), so = si, su = si,
                   sfl = si, sfr = si;
            for (int z = 0; z < S; z++) {
                const float* piou = &g_pre_iou[((size_t)z * m + loc) * NIOU];
                float4 a = *(const float4*)&piou[j];
                float4 b = *(const float4*)&piou[DD + j];
                float4 cc = *(const float4*)&piou[2 * DD + j];
                si.x += a.x; si.y += a.y; si.z += a.z; si.w += a.w;
                so.x += b.x; so.y += b.y; so.z += b.z; so.w += b.w;
                su.x += cc.x; su.y += cc.y; su.z += cc.z; su.w += cc.w;
                if (!noF) {
                    const float* pf = &g_pre_f[(size_t)z * 2 * m * DD];
                    float4 d = *(const float4*)&pf[(size_t)(2 * loc) * DD + j];
                    float4 e = *(const float4*)&pf[(size_t)(2 * loc + 1) * DD + j];
                    sfl.x += d.x; sfl.y += d.y; sfl.z += d.z; sfl.w += d.w;
                    sfr.x += e.x; sfr.y += e.y; sfr.z += e.z; sfr.w += e.w;
                }
            }
            float4 cl = make_float4(0.f, 0.f, 0.f, 0.f), cr = cl;
            if (!noF) {
                const int l = 2 * p + 1, r = 2 * p + 2;
                cl = *(const float4*)&g_c[(size_t)l * DD + j];
                cr = *(const float4*)&g_c[(size_t)r * DD + j];
            }
            float4 cn, hn;
            {
                float vi, vo, vu, fl, fr;
                vi = sigmoidf(si.x + vbi.x); vo = sigmoidf(so.x + vbo.x);
                vu = tanhf(su.x + vbu.x);
                fl = noF ? 0.f : sigmoidf(sfl.x + vbf.x);
                fr = noF ? 0.f : sigmoidf(sfr.x + vbf.x);
                cn.x = vi * vu + fl * cl.x + fr * cr.x; hn.x = vo * tanhf(cn.x);
                vi = sigmoidf(si.y + vbi.y); vo = sigmoidf(so.y + vbo.y);
                vu = tanhf(su.y + vbu.y);
                fl = noF ? 0.f : sigmoidf(sfl.y + vbf.y);
                fr = noF ? 0.f : sigmoidf(sfr.y + vbf.y);
                cn.y = vi * vu + fl * cl.y + fr * cr.y; hn.y = vo * tanhf(cn.y);
                vi = sigmoidf(si.z + vbi.z); vo = sigmoidf(so.z + vbo.z);
                vu = tanhf(su.z + vbu.z);
                fl = noF ? 0.f : sigmoidf(sfl.z + vbf.z);
                fr = noF ? 0.f : sigmoidf(sfr.z + vbf.z);
                cn.z = vi * vu + fl * cl.z + fr * cr.z; hn.z = vo * tanhf(cn.z);
                vi = sigmoidf(si.w + vbi.w); vo = sigmoidf(so.w + vbo.w);
                vu = tanhf(su.w + vbu.w);
                fl = noF ? 0.f : sigmoidf(sfl.w + vbf.w);
                fr = noF ? 0.f : sigmoidf(sfr.w + vbf.w);
                cn.w = vi * vu + fl * cl.w + fr * cr.w; hn.w = vo * tanhf(cn.w);
            }
            *(float4*)&g_c[(size_t)p * DD + j] = cn;
            uint2 hi, lo;
            split4(hn, &hi, &lo);
            *(uint2*)&g_fb_h[(size_t)p * FD + DD + j] = hi;
            *(uint2*)&g_fb_l[(size_t)p * FD + DD + j] = lo;
            h4[s] = hn;
        }
        if (writeNext) {
            uint2 hi, lo;
            float4 sum = make_float4(h4[0].x + h4[1].x, h4[0].y + h4[1].y,
                                     h4[0].z + h4[1].z, h4[0].w + h4[1].w);
            split4(sum, &hi, &lo);
            *(uint2*)&g_xiou_h[oiou + IDDIM + j] = hi;
            *(uint2*)&g_xiou_l[oiou + IDDIM + j] = lo;
            split4(h4[0], &hi, &lo);
            *(uint2*)&g_xf_h[ofl + IDDIM + j] = hi;
            *(uint2*)&g_xf_l[ofl + IDDIM + j] = lo;
            split4(h4[1], &hi, &lo);
            *(uint2*)&g_xf_h[ofr + IDDIM + j] = hi;
            *(uint2*)&g_xf_l[ofr + IDDIM + j] = lo;
        }
    }
}

// ---------------- head: 4 nodes per 256-thread block ------------------------
__device__ __forceinline__ float ysum(int node, int col)
{
    float s = 0.f;
    #pragma unroll
    for (int z = 0; z < SFC0; z++)
        s += g_y[((size_t)z * NN + node) * YW + col];
    return s;
}

__global__ void head_kernel(const float* __restrict__ fc0_b,
                            const float* __restrict__ fc1_w, const float* __restrict__ fc1_b,
                            const float* __restrict__ fc2_w, const float* __restrict__ fc2_b,
                            float* __restrict__ out)
{
    __shared__ float z[4][64];
    __shared__ float partial[4][2];
    const int sub = threadIdx.x >> 6;
    const int j = threadIdx.x & 63;
    const int n = blockIdx.x * 4 + sub;
    const bool valid = (n < NN);

    float acc = 0.0f;
    if (valid) {
        acc = fc0_b[j] + ysum(n, j);
        if (n > 0) acc += ysum((n - 1) >> 1, 64 + j);
        if (n < NINT)
            acc += 0.5f * (ysum(2 * n + 1, 128 + j) + ysum(2 * n + 2, 128 + j));
    }
    z[sub][j] = fmaxf(acc, 0.0f);
    __syncthreads();

    float a1 = fc1_b[j];
    #pragma unroll 8
    for (int k = 0; k < 64; k++) a1 += fc1_w[j * 64 + k] * z[sub][k];
    float z1 = fmaxf(a1, 0.0f);

    float v = fc2_w[j] * z1;
    #pragma unroll
    for (int off = 16; off > 0; off >>= 1) v += __shfl_down_sync(0xffffffffu, v, off);
    if ((j & 31) == 0) partial[sub][j >> 5] = v;
    __syncthreads();
    if (j == 0 && valid) out[n] = partial[sub][0] + partial[sub][1] + fc2_b[0];
}

// ---------------- launch ----------------------------------------------------
extern "C" void kernel_launch(void* const* d_in, const int* in_sizes, int n_in,
                              void* d_out, int out_size)
{
    const float* x      = (const float*)d_in[0];
    const float* idd    = (const float*)d_in[1];
    const float* conv_w  = (const float*)d_in[4];
    const float* conv_b  = (const float*)d_in[5];
    const float* convl_w = (const float*)d_in[6];
    const float* convl_b = (const float*)d_in[7];
    const float* Wi = (const float*)d_in[8];   const float* bi = (const float*)d_in[9];
    const float* Wf = (const float*)d_in[10];  const float* bf = (const float*)d_in[11];
    const float* Wu = (const float*)d_in[12];  const float* bu = (const float*)d_in[13];
    const float* Wo = (const float*)d_in[14];  const float* bo = (const float*)d_in[15];
    const float* fc0_w = (const float*)d_in[16]; const float* fc0_b = (const float*)d_in[17];
    const float* fc1_w = (const float*)d_in[18]; const float* fc1_b = (const float*)d_in[19];
    const float* fc2_w = (const float*)d_in[20]; const float* fc2_b = (const float*)d_in[21];
    float* out = (float*)d_out;

    float *p_pre_iou, *p_pre_f, *p_y;
    __nv_bfloat16 *p_xiou_h, *p_xiou_l, *p_xf_h, *p_xf_l;
    __nv_bfloat16 *p_wiou_h, *p_wiou_l, *p_wf_h, *p_wf_l;
    __nv_bfloat16 *p_fb_h, *p_fb_l, *p_w012h, *p_w012l;
    cudaGetSymbolAddress((void**)&p_pre_iou, g_pre_iou);
    cudaGetSymbolAddress((void**)&p_pre_f,   g_pre_f);
    cudaGetSymbolAddress((void**)&p_y,       g_y);
    cudaGetSymbolAddress((void**)&p_xiou_h,  g_xiou_h);
    cudaGetSymbolAddress((void**)&p_xiou_l,  g_xiou_l);
    cudaGetSymbolAddress((void**)&p_xf_h,    g_xf_h);
    cudaGetSymbolAddress((void**)&p_xf_l,    g_xf_l);
    cudaGetSymbolAddress((void**)&p_wiou_h,  g_wiou_h);
    cudaGetSymbolAddress((void**)&p_wiou_l,  g_wiou_l);
    cudaGetSymbolAddress((void**)&p_wf_h,    g_wf_h);
    cudaGetSymbolAddress((void**)&p_wf_l,    g_wf_l);
    cudaGetSymbolAddress((void**)&p_fb_h,    g_fb_h);
    cudaGetSymbolAddress((void**)&p_fb_l,    g_fb_l);
    cudaGetSymbolAddress((void**)&p_w012h,   g_w012h);
    cudaGetSymbolAddress((void**)&p_w012l,   g_w012l);

    cudaFuncSetAttribute(bmma2, cudaFuncAttributeMaxDynamicSharedMemorySize, BSM);

    // 0) split + pack all weights (one launch)
    const int prepN = 4 * DD * KIN + YW * FD;
    prep_weights<<<(prepN + 255) / 256, 256>>>(Wi, Wo, Wu, Wf, fc0_w);

    // 1) conv front-end
    conv_kernel<<<NN, 256>>>(x, idd, conv_w, conv_b, convl_w, convl_b);

    // 2) initial xiou build for depth-11 parents
    build_xin<<<2048, 256>>>(2047, idd);

    // 3) bottom-up tree LSTM
    // split-K schedule chosen by wave-fill: blocks/(296*ceil(blocks/296))
    // at minimum S per level (halves partial traffic vs R14 where possible).
    for (int depth = 11; depth >= 0; depth--) {
        int m = 1 << depth;
        int start = m - 1;
        int S;
        if (m >= 2048)      S = 2;   // iou-only: 1216 blocks, 82% fill
        else if (m == 1024) S = 1;   // 816 blocks, 92% fill
        else if (m == 512)  S = 2;   // 816 blocks, 92% fill
        else if (m == 256)  S = 4;   // 816 blocks, 92% fill
        else if (m == 128)  S = 8;   // 816 blocks, 92% fill
        else                S = 16;  // latency-bound small levels
        Job jiou = { p_xiou_h, p_xiou_l, p_wiou_h, p_wiou_l, p_pre_iou,
                     KIN, KIN, NIOU, (size_t)m * NIOU, m, NIOU, XT_IOU };
        if (depth == 11) {
            Job jnull = jiou; jnull.xt = 0;
            dim3 g(XT_IOU, (m + 127) / 128, S);
            bmma2<<<g, 256, BSM>>>(jiou, jnull, KIN);
        } else {
            Job jf = { p_xf_h, p_xf_l, p_wf_h, p_wf_l, p_pre_f,
                       KIN, KIN, DD, (size_t)2 * m * DD, 2 * m, DD, XT_F };
            dim3 g(XT_IOU + XT_F, (2 * m + 127) / 128, S);
            bmma2<<<g, 256, BSM>>>(jiou, jf, KIN);
        }
        int blocks = (m >= 2) ? m / 2 : 1;
        lstm_combine2<<<blocks, 256>>>(start, m, S, depth > 0 ? 1 : 0,
                                       depth == 11 ? 1 : 0,
                                       bi, bf, bu, bo, idd);
    }

    // 4) fused fc0 with split-K=2 (256 blocks, 86% single-wave fill)
    Job jfc0 = { p_fb_h, p_fb_l, p_w012h, p_w012l, p_y,
                 FD, FD, YW, (size_t)NN * YW, NN, YW, 2 };
    Job jnull = jfc0; jnull.xt = 0;
    dim3 g3(2, (NN + 127) / 128, SFC0);
    bmma2<<<g3, 256, BSM>>>(jfc0, jnull, FD);

    // 5) fusion combine + fc1 + fc2 (4 nodes per block)
    head_kernel<<<(NN + 3) / 4, 256>>>(fc0_b, fc1_w, fc1_b, fc2_w, fc2_b, out);
}